// round 3
// baseline (speedup 1.0000x reference)
#include <cuda_runtime.h>
#include <math.h>

#define BB 2
#define TT 4096
#define DD 128
#define KK 256
#define BT (BB * TT)

// ---------------- scratch ----------------
__device__ float g_kh[BT * DD];
__device__ float g_mf[BT * DD];
__device__ float g_qh[BT * DD];
__device__ float g_a0[BT * DD];
__device__ float g_a1[BT * DD];
__device__ float g_a2[BT * DD];
__device__ float g_a3[BT * DD];
__device__ float g_zc[BT * DD];
__device__ float g_va[BT * DD];

// ---------------- packed f32x2 helpers ----------------
typedef unsigned long long ull;
__device__ __forceinline__ ull dup2(float x) {
    ull r; asm("mov.b64 %0, {%1, %1};" : "=l"(r) : "f"(x)); return r;
}
__device__ __forceinline__ void fma2(ull& d, ull a, ull b) {
    asm("fma.rn.f32x2 %0, %1, %2, %0;" : "+l"(d) : "l"(a), "l"(b));
}
__device__ __forceinline__ float2 unpk(ull v) {
    float2 r; asm("mov.b64 {%0, %1}, %2;" : "=f"(r.x), "=f"(r.y) : "l"(v)); return r;
}

// ---------------- depthwise causal conv ----------------
__global__ __launch_bounds__(512) void conv_kernel(const float* __restrict__ z,
                                                   const float* __restrict__ w,
                                                   const float* __restrict__ bias,
                                                   float* __restrict__ mf) {
    int d = threadIdx.x;
    int t = blockIdx.x * 4 + threadIdx.y;
    int b = blockIdx.y;
    float acc = bias[d];
    int kstart = (KK - 1) - t;
    if (kstart < 0) kstart = 0;
    const float* zp = z + ((long long)b * TT + t - (KK - 1)) * DD + d;
    const float* wp = w + d;
#pragma unroll 4
    for (int k = kstart; k < KK; k++)
        acc = fmaf(zp[(long long)k * DD], wp[(long long)k * DD], acc);
    mf[((long long)b * TT + t) * DD + d] = acc;
}

// ---------------- block reduce of 4 values (128 threads) ----------------
__device__ __forceinline__ void block_reduce4(float v[4], float* red) {
#pragma unroll
    for (int k = 0; k < 4; k++) {
        float x = v[k];
#pragma unroll
        for (int o = 16; o; o >>= 1) x += __shfl_xor_sync(0xffffffffu, x, o);
        if ((threadIdx.x & 31) == 0) red[((threadIdx.x >> 5) << 2) + k] = x;
    }
    __syncthreads();
#pragma unroll
    for (int k = 0; k < 4; k++) v[k] = red[k] + red[4 + k] + red[8 + k] + red[12 + k];
    __syncthreads();
}

// ---------------- Y = sphere_norm(X @ W + bias) ----------------
__global__ __launch_bounds__(128) void gemm_norm_kernel(const float* __restrict__ X,
                                                        const float* __restrict__ W,
                                                        const float* __restrict__ bias,
                                                        float* __restrict__ Y) {
    extern __shared__ float sm[];
    float* Ws  = sm;           // 128*128
    float* xs  = sm + 16384;   // 4*128
    float* red = sm + 16896;   // 16
    int d = threadIdx.x;
    for (int idx = d; idx < 16384; idx += 128) Ws[idx] = W[idx];
    float bv = bias[d];
    __syncthreads();
    long long row0 = (long long)blockIdx.x * 16;
    for (int g = 0; g < 16; g += 4) {
#pragma unroll
        for (int k = 0; k < 4; k++) xs[k * 128 + d] = X[(row0 + g + k) * DD + d];
        __syncthreads();
        float a0 = bv, a1 = bv, a2 = bv, a3 = bv;
#pragma unroll 4
        for (int j = 0; j < 128; j++) {
            float wv = Ws[j * 128 + d];
            a0 = fmaf(xs[j], wv, a0);
            a1 = fmaf(xs[128 + j], wv, a1);
            a2 = fmaf(xs[256 + j], wv, a2);
            a3 = fmaf(xs[384 + j], wv, a3);
        }
        float acc[4] = {a0, a1, a2, a3};
        float v[4] = {a0 * a0, a1 * a1, a2 * a2, a3 * a3};
        block_reduce4(v, red);
#pragma unroll
        for (int k = 0; k < 4; k++) {
            float norm = fmaxf(sqrtf(v[k]), 1e-8f);
            Y[(row0 + g + k) * DD + d] = __fdividef(acc[k], norm);
        }
        __syncthreads();
    }
}

// ---------------- fused epilogue + next-stage q projection ----------------
__global__ __launch_bounds__(128) void epilogue_kernel(
    const float* __restrict__ A0, const float* __restrict__ A1,
    const float* __restrict__ A2, const float* __restrict__ A3,
    const float* __restrict__ Wo, const float* __restrict__ bo,
    const float* __restrict__ Wq, const float* __restrict__ bq,
    const float* __restrict__ mf, const float* __restrict__ zin,
    const float* __restrict__ zbase, float* __restrict__ vacc,
    float* __restrict__ zc, float* __restrict__ qh,
    float sw, float rc, int first, int has_next) {
    extern __shared__ float sm[];
    float* Wos = sm;            // 16384
    float* Wqs = sm + 16384;    // 16384
    float* xs  = sm + 32768;    // 512
    float* red = sm + 33280;    // 16
    int d = threadIdx.x;
    for (int idx = d; idx < 16384; idx += 128) { Wos[idx] = Wo[idx]; Wqs[idx] = Wq[idx]; }
    float bov = bo[d], bqv = bq[d];
    __syncthreads();
    long long row0 = (long long)blockIdx.x * 16;
    for (int g = 0; g < 16; g += 4) {
#pragma unroll
        for (int k = 0; k < 4; k++) {
            long long off = (row0 + g + k) * DD + d;
            xs[k * 128 + d] = A0[off] + A1[off] + A2[off] + A3[off];
        }
        __syncthreads();
        float a0 = bov, a1 = bov, a2 = bov, a3 = bov;
#pragma unroll 4
        for (int j = 0; j < 128; j++) {
            float wv = Wos[j * 128 + d];
            a0 = fmaf(xs[j], wv, a0);
            a1 = fmaf(xs[128 + j], wv, a1);
            a2 = fmaf(xs[256 + j], wv, a2);
            a3 = fmaf(xs[384 + j], wv, a3);
        }
        float acc[4] = {a0, a1, a2, a3};
        float tot[4], zcd[4], v[4];
#pragma unroll
        for (int k = 0; k < 4; k++) {
            long long off = (row0 + g + k) * DD + d;
            tot[k] = acc[k] + mf[off];
            zcd[k] = zin[off];
            v[k]   = tot[k] * zcd[k];
        }
        block_reduce4(v, red);
        float proj[4];
#pragma unroll
        for (int k = 0; k < 4; k++) {
            proj[k] = tot[k] - v[k] * zcd[k];
            long long off = (row0 + g + k) * DD + d;
            float vp = first ? 0.f : vacc[off];
            vacc[off] = vp + sw * proj[k];
        }
        if (has_next) {
            float zn[4], u[4];
#pragma unroll
            for (int k = 0; k < 4; k++) {
                long long off = (row0 + g + k) * DD + d;
                zn[k] = zbase[off] + rc * proj[k];
                u[k]  = zn[k] * zn[k];
            }
            block_reduce4(u, red);
#pragma unroll
            for (int k = 0; k < 4; k++) {
                long long off = (row0 + g + k) * DD + d;
                float znv = __fdividef(zn[k], fmaxf(sqrtf(u[k]), 1e-8f));
                zc[off] = znv;
                xs[k * 128 + d] = znv;
            }
            __syncthreads();
            float q0 = bqv, q1 = bqv, q2 = bqv, q3 = bqv;
#pragma unroll 4
            for (int j = 0; j < 128; j++) {
                float wv = Wqs[j * 128 + d];
                q0 = fmaf(xs[j], wv, q0);
                q1 = fmaf(xs[128 + j], wv, q1);
                q2 = fmaf(xs[256 + j], wv, q2);
                q3 = fmaf(xs[384 + j], wv, q3);
            }
            float qa[4] = {q0, q1, q2, q3};
            float w2[4] = {q0 * q0, q1 * q1, q2 * q2, q3 * q3};
            block_reduce4(w2, red);
#pragma unroll
            for (int k = 0; k < 4; k++) {
                long long off = (row0 + g + k) * DD + d;
                qh[off] = __fdividef(qa[k], fmaxf(sqrtf(w2[k]), 1e-8f));
            }
        }
        __syncthreads();
    }
}

// ---------------- causal sin-attention (FFMA2, quarter-split) ----------------
#define KR_PITCH 132
#define SS_PITCH 68
// smem floats: Qt 8192 | Ktc 4096 | Kr 8448 | Ss 4352  -> 25088 floats (100352 B)

__global__ __launch_bounds__(256, 2) void attn_kernel(const float* __restrict__ Q,
                                                      const float* __restrict__ Kh,
                                                      float* __restrict__ O0,
                                                      float* __restrict__ O1,
                                                      float* __restrict__ O2,
                                                      float* __restrict__ O3) {
    extern __shared__ float sm[];
    float* Qt  = sm;            // [d(128)][i(64)]
    float* Ktc = sm + 8192;     // [d(64 chunk)][j(64)]
    float* Kr  = sm + 12288;    // [j(64)][d(128) pitch 132]
    float* Ss  = sm + 20736;    // [j(64)][i(64) pitch 68]
    const int tid = threadIdx.x;
    const int b = blockIdx.z, qq = blockIdx.y, p = blockIdx.x;
    float* Out = (qq == 0) ? O0 : (qq == 1) ? O1 : (qq == 2) ? O2 : O3;
    const int tj = tid & 15, ti = tid >> 4;
    const float* Qb = Q + (long long)b * TT * DD;
    const float* Kb = Kh + (long long)b * TT * DD;

    for (int rep = 0; rep < 2; rep++) {
        int tb = rep ? (TT / 64 - 1 - p) : p;
        __syncthreads();
        // Q tile -> Qt [d][i]
        for (int idx = tid; idx < 2048; idx += 256) {
            int i = idx & 63, d0 = (idx >> 6) << 2;
            float4 v = *(const float4*)(Qb + ((long long)tb * 64 + i) * DD + d0);
            Qt[(d0 + 0) * 64 + i] = v.x;
            Qt[(d0 + 1) * 64 + i] = v.y;
            Qt[(d0 + 2) * 64 + i] = v.z;
            Qt[(d0 + 3) * 64 + i] = v.w;
        }
        ull O2a[4][4];
#pragma unroll
        for (int r = 0; r < 4; r++)
#pragma unroll
            for (int c = 0; c < 4; c++) O2a[r][c] = 0ull;

        int nsb = tb + 1;
        int sb0 = (nsb * qq) >> 2;
        int sb1 = (nsb * (qq + 1)) >> 2;
        for (int sb = sb0; sb < sb1; sb++) {
            ull S2[4][2];
#pragma unroll
            for (int r = 0; r < 4; r++) { S2[r][0] = 0ull; S2[r][1] = 0ull; }
            // two 64-d chunks
#pragma unroll 1
            for (int c = 0; c < 2; c++) {
                __syncthreads();
                for (int idx = tid; idx < 1024; idx += 256) {
                    int j = idx & 63, d0 = (idx >> 6) << 2;
                    float4 v = *(const float4*)(Kb + ((long long)sb * 64 + j) * DD + c * 64 + d0);
                    Ktc[(d0 + 0) * 64 + j] = v.x;
                    Ktc[(d0 + 1) * 64 + j] = v.y;
                    Ktc[(d0 + 2) * 64 + j] = v.z;
                    Ktc[(d0 + 3) * 64 + j] = v.w;
                    *(float4*)(Kr + j * KR_PITCH + c * 64 + d0) = v;
                }
                __syncthreads();
#pragma unroll 4
                for (int dd = 0; dd < 64; dd++) {
                    float4 q4 = *(const float4*)(Qt + (c * 64 + dd) * 64 + 4 * ti);
                    ulonglong2 kk = *(const ulonglong2*)(Ktc + dd * 64 + 4 * tj);
                    ull q0 = dup2(q4.x), q1 = dup2(q4.y), q2 = dup2(q4.z), q3 = dup2(q4.w);
                    fma2(S2[0][0], q0, kk.x); fma2(S2[0][1], q0, kk.y);
                    fma2(S2[1][0], q1, kk.x); fma2(S2[1][1], q1, kk.y);
                    fma2(S2[2][0], q2, kk.x); fma2(S2[2][1], q2, kk.y);
                    fma2(S2[3][0], q3, kk.x); fma2(S2[3][1], q3, kk.y);
                }
            }
            // sin (deg-9 odd poly, |x|<=1) + causal mask on diag tile
            const bool diag = (sb == tb);
            float S[4][4];
#pragma unroll
            for (int r = 0; r < 4; r++) {
                float2 a = unpk(S2[r][0]);
                float2 bb = unpk(S2[r][1]);
                S[r][0] = a.x; S[r][1] = a.y; S[r][2] = bb.x; S[r][3] = bb.y;
            }
#pragma unroll
            for (int r = 0; r < 4; r++)
#pragma unroll
                for (int c = 0; c < 4; c++) {
                    float x  = S[r][c];
                    float x2 = x * x;
                    float pp = fmaf(x2, 2.7557319e-06f, -1.9841270e-04f);
                    pp = fmaf(x2, pp, 8.3333333e-03f);
                    pp = fmaf(x2, pp, -1.6666667e-01f);
                    float sv = fmaf(x * x2, pp, x);
                    if (diag && (4 * tj + c) > (4 * ti + r)) sv = 0.f;
                    S[r][c] = sv;
                }
#pragma unroll
            for (int c = 0; c < 4; c++)
                *(float4*)(Ss + (4 * tj + c) * SS_PITCH + 4 * ti) =
                    make_float4(S[0][c], S[1][c], S[2][c], S[3][c]);
            __syncthreads();
            // O accumulation: O[i][d] += S[i][j] * K[j][d]
#pragma unroll 2
            for (int j = 0; j < 64; j++) {
                float4 s4 = *(const float4*)(Ss + j * SS_PITCH + 4 * ti);
                ulonglong2 ka = *(const ulonglong2*)(Kr + j * KR_PITCH + 8 * tj);
                ulonglong2 kb2 = *(const ulonglong2*)(Kr + j * KR_PITCH + 8 * tj + 4);
                ull s0 = dup2(s4.x), s1 = dup2(s4.y), s2 = dup2(s4.z), s3 = dup2(s4.w);
                fma2(O2a[0][0], s0, ka.x); fma2(O2a[0][1], s0, ka.y);
                fma2(O2a[0][2], s0, kb2.x); fma2(O2a[0][3], s0, kb2.y);
                fma2(O2a[1][0], s1, ka.x); fma2(O2a[1][1], s1, ka.y);
                fma2(O2a[1][2], s1, kb2.x); fma2(O2a[1][3], s1, kb2.y);
                fma2(O2a[2][0], s2, ka.x); fma2(O2a[2][1], s2, ka.y);
                fma2(O2a[2][2], s2, kb2.x); fma2(O2a[2][3], s2, kb2.y);
                fma2(O2a[3][0], s3, ka.x); fma2(O2a[3][1], s3, ka.y);
                fma2(O2a[3][2], s3, kb2.x); fma2(O2a[3][3], s3, kb2.y);
            }
        }
#pragma unroll
        for (int r = 0; r < 4; r++) {
            float2 p0 = unpk(O2a[r][0]), p1 = unpk(O2a[r][1]);
            float2 p2 = unpk(O2a[r][2]), p3 = unpk(O2a[r][3]);
            long long off = ((long long)b * TT + (long long)tb * 64 + 4 * ti + r) * DD + 8 * tj;
            *(float4*)(Out + off)     = make_float4(p0.x, p0.y, p1.x, p1.y);
            *(float4*)(Out + off + 4) = make_float4(p2.x, p2.y, p3.x, p3.y);
        }
    }
}

// ---------------- final retraction ----------------
__global__ __launch_bounds__(128) void final_kernel(const float* __restrict__ z,
                                                    const float* __restrict__ va,
                                                    float* __restrict__ out) {
    __shared__ float red[4];
    int d = threadIdx.x;
    long long off = (long long)blockIdx.x * DD + d;
    float v = z[off] + va[off];
    float x = v * v;
#pragma unroll
    for (int o = 16; o; o >>= 1) x += __shfl_xor_sync(0xffffffffu, x, o);
    if ((d & 31) == 0) red[d >> 5] = x;
    __syncthreads();
    float ss = red[0] + red[1] + red[2] + red[3];
    out[off] = __fdividef(v, fmaxf(sqrtf(ss), 1e-8f));
}

// ---------------- launch ----------------
extern "C" void kernel_launch(void* const* d_in, const int* in_sizes, int n_in,
                              void* d_out, int out_size) {
    const float* z  = (const float*)d_in[0];
    const float* ck = (const float*)d_in[1];
    const float* cb = (const float*)d_in[2];
    const float* Wq = (const float*)d_in[3];
    const float* bq = (const float*)d_in[4];
    const float* Wk = (const float*)d_in[5];
    const float* bk = (const float*)d_in[6];
    const float* Wo = (const float*)d_in[7];
    const float* bo = (const float*)d_in[8];
    float* out = (float*)d_out;

    float *kh, *mf, *qh, *a0, *a1, *a2, *a3, *zc, *va;
    cudaGetSymbolAddress((void**)&kh, g_kh);
    cudaGetSymbolAddress((void**)&mf, g_mf);
    cudaGetSymbolAddress((void**)&qh, g_qh);
    cudaGetSymbolAddress((void**)&a0, g_a0);
    cudaGetSymbolAddress((void**)&a1, g_a1);
    cudaGetSymbolAddress((void**)&a2, g_a2);
    cudaGetSymbolAddress((void**)&a3, g_a3);
    cudaGetSymbolAddress((void**)&zc, g_zc);
    cudaGetSymbolAddress((void**)&va, g_va);

    const int GEMM_SMEM = (16384 + 512 + 16) * 4;
    const int EPI_SMEM  = (32768 + 512 + 16) * 4;
    const int ATTN_SMEM = 25088 * 4;
    cudaFuncSetAttribute(gemm_norm_kernel, cudaFuncAttributeMaxDynamicSharedMemorySize, GEMM_SMEM);
    cudaFuncSetAttribute(epilogue_kernel, cudaFuncAttributeMaxDynamicSharedMemorySize, EPI_SMEM);
    cudaFuncSetAttribute(attn_kernel, cudaFuncAttributeMaxDynamicSharedMemorySize, ATTN_SMEM);

    conv_kernel<<<dim3(TT / 4, BB), dim3(128, 4)>>>(z, ck, cb, mf);
    gemm_norm_kernel<<<BT / 16, 128, GEMM_SMEM>>>(z, Wk, bk, kh);
    gemm_norm_kernel<<<BT / 16, 128, GEMM_SMEM>>>(z, Wq, bq, qh);

    const float sws[4] = {1.f / 6.f, 2.f / 6.f, 2.f / 6.f, 1.f / 6.f};
    const float rcs[4] = {0.5f, 0.5f, 1.0f, 0.f};
    const float* zcur = z;
    for (int s = 0; s < 4; s++) {
        attn_kernel<<<dim3(32, 4, BB), 256, ATTN_SMEM>>>(qh, kh, a0, a1, a2, a3);
        epilogue_kernel<<<BT / 16, 128, EPI_SMEM>>>(a0, a1, a2, a3, Wo, bo, Wq, bq,
                                                    mf, zcur, z, va, zc, qh,
                                                    sws[s], rcs[s], s == 0 ? 1 : 0, s < 3 ? 1 : 0);
        zcur = zc;
    }
    final_kernel<<<BT, 128>>>(z, va, out);
}

// round 5
// speedup vs baseline: 2.0017x; 2.0017x over previous
#include <cuda_runtime.h>
#include <cstdint>

#define BB 2
#define TT 4096
#define DD 128
#define KK 256
#define BT (BB * TT)

// ---------------- scratch ----------------
__device__ float g_kh[BT * DD];
__device__ float g_mf[BT * DD];
__device__ float g_qh[BT * DD];
__device__ float g_a0[BT * DD];
__device__ float g_a1[BT * DD];
__device__ float g_a2[BT * DD];
__device__ float g_a3[BT * DD];
__device__ float g_zc[BT * DD];
__device__ float g_va[BT * DD];

// ================= helpers =================
__device__ __forceinline__ uint32_t smem_u32(const void* p) {
    uint32_t a;
    asm("{ .reg .u64 t; cvta.to.shared.u64 t, %1; cvt.u32.u64 %0, t; }" : "=r"(a) : "l"(p));
    return a;
}
__device__ __forceinline__ void ldsm4(uint32_t& r0, uint32_t& r1, uint32_t& r2, uint32_t& r3,
                                      uint32_t addr) {
    asm volatile("ldmatrix.sync.aligned.m8n8.x4.shared.b16 {%0,%1,%2,%3}, [%4];"
                 : "=r"(r0), "=r"(r1), "=r"(r2), "=r"(r3) : "r"(addr));
}
__device__ __forceinline__ void ldsm4t(uint32_t& r0, uint32_t& r1, uint32_t& r2, uint32_t& r3,
                                       uint32_t addr) {
    asm volatile("ldmatrix.sync.aligned.m8n8.x4.trans.shared.b16 {%0,%1,%2,%3}, [%4];"
                 : "=r"(r0), "=r"(r1), "=r"(r2), "=r"(r3) : "r"(addr));
}
__device__ __forceinline__ void mma16816(float* c, uint32_t a0, uint32_t a1, uint32_t a2,
                                         uint32_t a3, uint32_t b0, uint32_t b1) {
    asm volatile(
        "mma.sync.aligned.m16n8k16.row.col.f32.bf16.bf16.f32 "
        "{%0,%1,%2,%3}, {%4,%5,%6,%7}, {%8,%9}, {%0,%1,%2,%3};"
        : "+f"(c[0]), "+f"(c[1]), "+f"(c[2]), "+f"(c[3])
        : "r"(a0), "r"(a1), "r"(a2), "r"(a3), "r"(b0), "r"(b1));
}
// split two fp32 into packed bf16 hi-pair + lo-pair (Dekker: lo = x - bf16(x) exact)
__device__ __forceinline__ void bsplit2(float x0, float x1, uint32_t& h, uint32_t& l) {
    uint16_t h0, h1, l0, l1;
    asm("cvt.rn.bf16.f32 %0, %1;" : "=h"(h0) : "f"(x0));
    asm("cvt.rn.bf16.f32 %0, %1;" : "=h"(h1) : "f"(x1));
    float f0 = __uint_as_float((uint32_t)h0 << 16);
    float f1 = __uint_as_float((uint32_t)h1 << 16);
    asm("cvt.rn.bf16.f32 %0, %1;" : "=h"(l0) : "f"(x0 - f0));
    asm("cvt.rn.bf16.f32 %0, %1;" : "=h"(l1) : "f"(x1 - f1));
    h = (uint32_t)h0 | ((uint32_t)h1 << 16);
    l = (uint32_t)l0 | ((uint32_t)l1 << 16);
}
// byte offset in a [rows][128]bf16 tile with XOR swizzle (16B chunks)
__device__ __forceinline__ uint32_t sw_off(int row, int d) {
    return (uint32_t)(row * 256 + ((((d >> 3) ^ (row & 7)) & 15) << 4) + (d & 7) * 2);
}
__device__ __forceinline__ float sinpoly(float x) {
    float x2 = x * x;
    float pp = fmaf(x2, 2.7557319e-06f, -1.9841270e-04f);
    pp = fmaf(x2, pp, 8.3333333e-03f);
    pp = fmaf(x2, pp, -1.6666667e-01f);
    return fmaf(x * x2, pp, x);
}

// smem byte offsets: Qhi 32K | Qlo 32K | Khi 16K | Klo 16K = 96K
#define QH_OFF 0
#define QL_OFF 32768
#define KH_OFF 65536
#define KL_OFF 81920
#define ATTN_SMEM 98304

// ---------------- causal sin-attention: mma.sync bf16 3-pass ----------------
// O[i,:] = sum_{j<=i} sin(q_i . k_j) k_j.  M-tile 128, N-tile 64.
__global__ __launch_bounds__(256) void attn_kernel(const float* __restrict__ Q,
                                                   const float* __restrict__ Kh,
                                                   float* __restrict__ O0,
                                                   float* __restrict__ O1,
                                                   float* __restrict__ O2,
                                                   float* __restrict__ O3) {
    extern __shared__ char smc[];
    const uint32_t sbase = smem_u32(smc);
    const int tid = threadIdx.x;
    const int lane = tid & 31, w = tid >> 5;
    const int p = blockIdx.x, qq = blockIdx.y, b = blockIdx.z;
    float* Out = (qq == 0) ? O0 : (qq == 1) ? O1 : (qq == 2) ? O2 : O3;
    const float* Qb = Q + (long long)b * TT * DD;
    const float* Kb = Kh + (long long)b * TT * DD;
    const int g = lane >> 3, r = lane & 7;

    for (int rep = 0; rep < 2; rep++) {
        const int R = rep ? (31 - p) : p;
        __syncthreads();  // prior rep's smem reads done before overwrite
        // ---- Q tile (128x128) -> Qhi/Qlo bf16, swizzled ----
        for (int t = tid; t < 2048; t += 256) {
            int row = t >> 4, d0 = (t & 15) * 8;
            const float* src = Qb + ((long long)R * 128 + row) * DD + d0;
            float4 u = *(const float4*)src;
            float4 v = *(const float4*)(src + 4);
            uint32_t hw[4], lw[4];
            bsplit2(u.x, u.y, hw[0], lw[0]);
            bsplit2(u.z, u.w, hw[1], lw[1]);
            bsplit2(v.x, v.y, hw[2], lw[2]);
            bsplit2(v.z, v.w, hw[3], lw[3]);
            uint32_t off = sw_off(row, d0);
            *(uint4*)(smc + QH_OFF + off) = make_uint4(hw[0], hw[1], hw[2], hw[3]);
            *(uint4*)(smc + QL_OFF + off) = make_uint4(lw[0], lw[1], lw[2], lw[3]);
        }

        float Oc[16][4];
#pragma unroll
        for (int nf = 0; nf < 16; nf++)
#pragma unroll
            for (int e = 0; e < 4; e++) Oc[nf][e] = 0.f;

        const int nblk = 2 * R + 2;
        const int sb0 = (nblk * qq) >> 2;
        const int sb1 = (nblk * (qq + 1)) >> 2;

        for (int sb = sb0; sb < sb1; sb++) {
            __syncthreads();  // prior s-block reads done; Q stores visible (1st iter)
            // ---- K s-block (64x128) -> Khi/Klo ----
            for (int t = tid; t < 1024; t += 256) {
                int row = t >> 4, d0 = (t & 15) * 8;
                const float* src = Kb + ((long long)sb * 64 + row) * DD + d0;
                float4 u = *(const float4*)src;
                float4 v = *(const float4*)(src + 4);
                uint32_t hw[4], lw[4];
                bsplit2(u.x, u.y, hw[0], lw[0]);
                bsplit2(u.z, u.w, hw[1], lw[1]);
                bsplit2(v.x, v.y, hw[2], lw[2]);
                bsplit2(v.z, v.w, hw[3], lw[3]);
                uint32_t off = sw_off(row, d0);
                *(uint4*)(smc + KH_OFF + off) = make_uint4(hw[0], hw[1], hw[2], hw[3]);
                *(uint4*)(smc + KL_OFF + off) = make_uint4(lw[0], lw[1], lw[2], lw[3]);
            }
            __syncthreads();

            // ---- MMA1: C[16x64] = Q . K^T (3-pass bf16) ----
            float C[8][4];
#pragma unroll
            for (int nf = 0; nf < 8; nf++)
#pragma unroll
                for (int e = 0; e < 4; e++) C[nf][e] = 0.f;
#pragma unroll
            for (int kc = 0; kc < 8; kc++) {
                int d0 = kc * 16;
                // A frag: m0 rows0-7/k0-7, m1 rows8-15/k0-7, m2 rows0-7/k8-15, m3 rows8-15/k8-15
                uint32_t aoff = sw_off(w * 16 + ((g & 1) ? 8 : 0) + r, d0 + ((g >> 1) ? 8 : 0));
                uint32_t ah0, ah1, ah2, ah3, al0, al1, al2, al3;
                ldsm4(ah0, ah1, ah2, ah3, sbase + QH_OFF + aoff);
                ldsm4(al0, al1, al2, al3, sbase + QL_OFF + aoff);
#pragma unroll
                for (int nfp = 0; nfp < 4; nfp++) {
                    int j0 = nfp * 16;
                    // B frag (n=j, k=d): m0 (j0..7,d0..7), m1 (j0..7,d8..15), m2 (j8..15,d0..7), m3 (j8..15,d8..15)
                    uint32_t boff = sw_off(j0 + ((g >> 1) ? 8 : 0) + r, d0 + ((g & 1) ? 8 : 0));
                    uint32_t bh0, bh1, bh2, bh3, bl0, bl1, bl2, bl3;
                    ldsm4(bh0, bh1, bh2, bh3, sbase + KH_OFF + boff);
                    ldsm4(bl0, bl1, bl2, bl3, sbase + KL_OFF + boff);
                    mma16816(C[2 * nfp],     ah0, ah1, ah2, ah3, bh0, bh1);
                    mma16816(C[2 * nfp + 1], ah0, ah1, ah2, ah3, bh2, bh3);
                    mma16816(C[2 * nfp],     ah0, ah1, ah2, ah3, bl0, bl1);
                    mma16816(C[2 * nfp + 1], ah0, ah1, ah2, ah3, bl2, bl3);
                    mma16816(C[2 * nfp],     al0, al1, al2, al3, bh0, bh1);
                    mma16816(C[2 * nfp + 1], al0, al1, al2, al3, bh2, bh3);
                }
            }

            // ---- sin + causal mask + repack C-frags -> A-frags of MMA2 ----
            uint32_t a2h[4][4], a2l[4][4];
            const int ig = R * 128 + w * 16 + (lane >> 2);
#pragma unroll
            for (int nf = 0; nf < 8; nf++) {
                int jb = sb * 64 + nf * 8 + 2 * (lane & 3);
                float s0 = sinpoly(C[nf][0]); if (jb > ig) s0 = 0.f;
                float s1 = sinpoly(C[nf][1]); if (jb + 1 > ig) s1 = 0.f;
                float s2 = sinpoly(C[nf][2]); if (jb > ig + 8) s2 = 0.f;
                float s3 = sinpoly(C[nf][3]); if (jb + 1 > ig + 8) s3 = 0.f;
                int kc2 = nf >> 1, hk = (nf & 1) ? 2 : 0;
                bsplit2(s0, s1, a2h[kc2][hk], a2l[kc2][hk]);
                bsplit2(s2, s3, a2h[kc2][hk + 1], a2l[kc2][hk + 1]);
            }

            // ---- MMA2: O[16x128] += S . K (3-pass bf16) ----
#pragma unroll
            for (int kc2 = 0; kc2 < 4; kc2++) {
                int j0 = kc2 * 16;
#pragma unroll
                for (int nfp = 0; nfp < 8; nfp++) {
                    int d0 = nfp * 16;
                    // B frag (k=j, n=d) via trans: m0 (j0..7,d0..7), m1 (j8..15,d0..7), m2 (j0..7,d8..15), m3 (j8..15,d8..15)
                    uint32_t boff = sw_off(j0 + ((g & 1) ? 8 : 0) + r, d0 + ((g >> 1) ? 8 : 0));
                    uint32_t th0, th1, th2, th3, tl0, tl1, tl2, tl3;
                    ldsm4t(th0, th1, th2, th3, sbase + KH_OFF + boff);
                    ldsm4t(tl0, tl1, tl2, tl3, sbase + KL_OFF + boff);
                    mma16816(Oc[2 * nfp],     a2h[kc2][0], a2h[kc2][1], a2h[kc2][2], a2h[kc2][3], th0, th1);
                    mma16816(Oc[2 * nfp + 1], a2h[kc2][0], a2h[kc2][1], a2h[kc2][2], a2h[kc2][3], th2, th3);
                    mma16816(Oc[2 * nfp],     a2h[kc2][0], a2h[kc2][1], a2h[kc2][2], a2h[kc2][3], tl0, tl1);
                    mma16816(Oc[2 * nfp + 1], a2h[kc2][0], a2h[kc2][1], a2h[kc2][2], a2h[kc2][3], tl2, tl3);
                    mma16816(Oc[2 * nfp],     a2l[kc2][0], a2l[kc2][1], a2l[kc2][2], a2l[kc2][3], th0, th1);
                    mma16816(Oc[2 * nfp + 1], a2l[kc2][0], a2l[kc2][1], a2l[kc2][2], a2l[kc2][3], th2, th3);
                }
            }
        }

        // ---- write O tile ----
        {
            long long rbase = (long long)b * TT + (long long)R * 128 + w * 16 + (lane >> 2);
#pragma unroll
            for (int nf = 0; nf < 16; nf++) {
                int d = nf * 8 + 2 * (lane & 3);
                *(float2*)(Out + rbase * DD + d) = make_float2(Oc[nf][0], Oc[nf][1]);
                *(float2*)(Out + (rbase + 8) * DD + d) = make_float2(Oc[nf][2], Oc[nf][3]);
            }
        }
    }
}

// ---------------- depthwise causal conv ----------------
__global__ __launch_bounds__(512) void conv_kernel(const float* __restrict__ z,
                                                   const float* __restrict__ w,
                                                   const float* __restrict__ bias,
                                                   float* __restrict__ mf) {
    int d = threadIdx.x;
    int t = blockIdx.x * 4 + threadIdx.y;
    int b = blockIdx.y;
    float acc = bias[d];
    int kstart = (KK - 1) - t;
    if (kstart < 0) kstart = 0;
    const float* zp = z + ((long long)b * TT + t - (KK - 1)) * DD + d;
    const float* wp = w + d;
#pragma unroll 4
    for (int k = kstart; k < KK; k++)
        acc = fmaf(zp[(long long)k * DD], wp[(long long)k * DD], acc);
    mf[((long long)b * TT + t) * DD + d] = acc;
}

// ---------------- block reduce of 4 values (128 threads) ----------------
__device__ __forceinline__ void block_reduce4(float v[4], float* red) {
#pragma unroll
    for (int k = 0; k < 4; k++) {
        float x = v[k];
#pragma unroll
        for (int o = 16; o; o >>= 1) x += __shfl_xor_sync(0xffffffffu, x, o);
        if ((threadIdx.x & 31) == 0) red[((threadIdx.x >> 5) << 2) + k] = x;
    }
    __syncthreads();
#pragma unroll
    for (int k = 0; k < 4; k++) v[k] = red[k] + red[4 + k] + red[8 + k] + red[12 + k];
    __syncthreads();
}

// ---------------- Y = sphere_norm(X @ W + bias) ----------------
__global__ __launch_bounds__(128) void gemm_norm_kernel(const float* __restrict__ X,
                                                        const float* __restrict__ W,
                                                        const float* __restrict__ bias,
                                                        float* __restrict__ Y) {
    extern __shared__ float sm[];
    float* Ws  = sm;
    float* xs  = sm + 16384;
    float* red = sm + 16896;
    int d = threadIdx.x;
    for (int idx = d; idx < 16384; idx += 128) Ws[idx] = W[idx];
    float bv = bias[d];
    __syncthreads();
    long long row0 = (long long)blockIdx.x * 16;
    for (int gg = 0; gg < 16; gg += 4) {
#pragma unroll
        for (int k = 0; k < 4; k++) xs[k * 128 + d] = X[(row0 + gg + k) * DD + d];
        __syncthreads();
        float a0 = bv, a1 = bv, a2 = bv, a3 = bv;
#pragma unroll 4
        for (int j = 0; j < 128; j++) {
            float wv = Ws[j * 128 + d];
            a0 = fmaf(xs[j], wv, a0);
            a1 = fmaf(xs[128 + j], wv, a1);
            a2 = fmaf(xs[256 + j], wv, a2);
            a3 = fmaf(xs[384 + j], wv, a3);
        }
        float acc[4] = {a0, a1, a2, a3};
        float v[4] = {a0 * a0, a1 * a1, a2 * a2, a3 * a3};
        block_reduce4(v, red);
#pragma unroll
        for (int k = 0; k < 4; k++) {
            float norm = fmaxf(sqrtf(v[k]), 1e-8f);
            Y[(row0 + gg + k) * DD + d] = __fdividef(acc[k], norm);
        }
        __syncthreads();
    }
}

// ---------------- fused epilogue + next-stage q projection ----------------
__global__ __launch_bounds__(128) void epilogue_kernel(
    const float* __restrict__ A0, const float* __restrict__ A1,
    const float* __restrict__ A2, const float* __restrict__ A3,
    const float* __restrict__ Wo, const float* __restrict__ bo,
    const float* __restrict__ Wq, const float* __restrict__ bq,
    const float* __restrict__ mf, const float* __restrict__ zin,
    const float* __restrict__ zbase, float* __restrict__ vacc,
    float* __restrict__ zc, float* __restrict__ qh,
    float sw, float rc, int first, int has_next) {
    extern __shared__ float sm[];
    float* Wos = sm;
    float* Wqs = sm + 16384;
    float* xs  = sm + 32768;
    float* red = sm + 33280;
    int d = threadIdx.x;
    for (int idx = d; idx < 16384; idx += 128) { Wos[idx] = Wo[idx]; Wqs[idx] = Wq[idx]; }
    float bov = bo[d], bqv = bq[d];
    __syncthreads();
    long long row0 = (long long)blockIdx.x * 16;
    for (int gg = 0; gg < 16; gg += 4) {
#pragma unroll
        for (int k = 0; k < 4; k++) {
            long long off = (row0 + gg + k) * DD + d;
            xs[k * 128 + d] = A0[off] + A1[off] + A2[off] + A3[off];
        }
        __syncthreads();
        float a0 = bov, a1 = bov, a2 = bov, a3 = bov;
#pragma unroll 4
        for (int j = 0; j < 128; j++) {
            float wv = Wos[j * 128 + d];
            a0 = fmaf(xs[j], wv, a0);
            a1 = fmaf(xs[128 + j], wv, a1);
            a2 = fmaf(xs[256 + j], wv, a2);
            a3 = fmaf(xs[384 + j], wv, a3);
        }
        float acc[4] = {a0, a1, a2, a3};
        float tot[4], zcd[4], v[4];
#pragma unroll
        for (int k = 0; k < 4; k++) {
            long long off = (row0 + gg + k) * DD + d;
            tot[k] = acc[k] + mf[off];
            zcd[k] = zin[off];
            v[k]   = tot[k] * zcd[k];
        }
        block_reduce4(v, red);
        float proj[4];
#pragma unroll
        for (int k = 0; k < 4; k++) {
            proj[k] = tot[k] - v[k] * zcd[k];
            long long off = (row0 + gg + k) * DD + d;
            float vp = first ? 0.f : vacc[off];
            vacc[off] = vp + sw * proj[k];
        }
        if (has_next) {
            float zn[4], u[4];
#pragma unroll
            for (int k = 0; k < 4; k++) {
                long long off = (row0 + gg + k) * DD + d;
                zn[k] = zbase[off] + rc * proj[k];
                u[k]  = zn[k] * zn[k];
            }
            block_reduce4(u, red);
#pragma unroll
            for (int k = 0; k < 4; k++) {
                long long off = (row0 + gg + k) * DD + d;
                float znv = __fdividef(zn[k], fmaxf(sqrtf(u[k]), 1e-8f));
                zc[off] = znv;
                xs[k * 128 + d] = znv;
            }
            __syncthreads();
            float q0 = bqv, q1 = bqv, q2 = bqv, q3 = bqv;
#pragma unroll 4
            for (int j = 0; j < 128; j++) {
                float wv = Wqs[j * 128 + d];
                q0 = fmaf(xs[j], wv, q0);
                q1 = fmaf(xs[128 + j], wv, q1);
                q2 = fmaf(xs[256 + j], wv, q2);
                q3 = fmaf(xs[384 + j], wv, q3);
            }
            float qa[4] = {q0, q1, q2, q3};
            float w2[4] = {q0 * q0, q1 * q1, q2 * q2, q3 * q3};
            block_reduce4(w2, red);
#pragma unroll
            for (int k = 0; k < 4; k++) {
                long long off = (row0 + gg + k) * DD + d;
                qh[off] = __fdividef(qa[k], fmaxf(sqrtf(w2[k]), 1e-8f));
            }
        }
        __syncthreads();
    }
}

// ---------------- final retraction ----------------
__global__ __launch_bounds__(128) void final_kernel(const float* __restrict__ z,
                                                    const float* __restrict__ va,
                                                    float* __restrict__ out) {
    __shared__ float red[4];
    int d = threadIdx.x;
    long long off = (long long)blockIdx.x * DD + d;
    float v = z[off] + va[off];
    float x = v * v;
#pragma unroll
    for (int o = 16; o; o >>= 1) x += __shfl_xor_sync(0xffffffffu, x, o);
    if ((d & 31) == 0) red[d >> 5] = x;
    __syncthreads();
    float ss = red[0] + red[1] + red[2] + red[3];
    out[off] = __fdividef(v, fmaxf(sqrtf(ss), 1e-8f));
}

// ---------------- launch ----------------
extern "C" void kernel_launch(void* const* d_in, const int* in_sizes, int n_in,
                              void* d_out, int out_size) {
    const float* z  = (const float*)d_in[0];
    const float* ck = (const float*)d_in[1];
    const float* cb = (const float*)d_in[2];
    const float* Wq = (const float*)d_in[3];
    const float* bq = (const float*)d_in[4];
    const float* Wk = (const float*)d_in[5];
    const float* bk = (const float*)d_in[6];
    const float* Wo = (const float*)d_in[7];
    const float* bo = (const float*)d_in[8];
    float* out = (float*)d_out;

    float *kh, *mf, *qh, *a0, *a1, *a2, *a3, *zc, *va;
    cudaGetSymbolAddress((void**)&kh, g_kh);
    cudaGetSymbolAddress((void**)&mf, g_mf);
    cudaGetSymbolAddress((void**)&qh, g_qh);
    cudaGetSymbolAddress((void**)&a0, g_a0);
    cudaGetSymbolAddress((void**)&a1, g_a1);
    cudaGetSymbolAddress((void**)&a2, g_a2);
    cudaGetSymbolAddress((void**)&a3, g_a3);
    cudaGetSymbolAddress((void**)&zc, g_zc);
    cudaGetSymbolAddress((void**)&va, g_va);

    const int GEMM_SMEM = (16384 + 512 + 16) * 4;
    const int EPI_SMEM  = (32768 + 512 + 16) * 4;
    cudaFuncSetAttribute(gemm_norm_kernel, cudaFuncAttributeMaxDynamicSharedMemorySize, GEMM_SMEM);
    cudaFuncSetAttribute(epilogue_kernel, cudaFuncAttributeMaxDynamicSharedMemorySize, EPI_SMEM);
    cudaFuncSetAttribute(attn_kernel, cudaFuncAttributeMaxDynamicSharedMemorySize, ATTN_SMEM);

    conv_kernel<<<dim3(TT / 4, BB), dim3(128, 4)>>>(z, ck, cb, mf);
    gemm_norm_kernel<<<BT / 16, 128, GEMM_SMEM>>>(z, Wk, bk, kh);
    gemm_norm_kernel<<<BT / 16, 128, GEMM_SMEM>>>(z, Wq, bq, qh);

    const float sws[4] = {1.f / 6.f, 2.f / 6.f, 2.f / 6.f, 1.f / 6.f};
    const float rcs[4] = {0.5f, 0.5f, 1.0f, 0.f};
    const float* zcur = z;
    for (int s = 0; s < 4; s++) {
        attn_kernel<<<dim3(16, 4, BB), 256, ATTN_SMEM>>>(qh, kh, a0, a1, a2, a3);
        epilogue_kernel<<<BT / 16, 128, EPI_SMEM>>>(a0, a1, a2, a3, Wo, bo, Wq, bq,
                                                    mf, zcur, z, va, zc, qh,
                                                    sws[s], rcs[s], s == 0 ? 1 : 0, s < 3 ? 1 : 0);
        zcur = zc;
    }
    final_kernel<<<BT, 128>>>(z, va, out);
}

// round 6
// speedup vs baseline: 2.8379x; 1.4177x over previous
#include <cuda_runtime.h>
#include <cstdint>

#define BB 2
#define TT 4096
#define DD 128
#define KK 256
#define BT (BB * TT)

// ---------------- scratch ----------------
__device__ float g_kh[BT * DD];
__device__ float g_mf[BT * DD];
__device__ float g_qh[BT * DD];
__device__ float g_a0[BT * DD];
__device__ float g_a1[BT * DD];
__device__ float g_a2[BT * DD];
__device__ float g_a3[BT * DD];
__device__ float g_zc[BT * DD];
__device__ float g_va[BT * DD];

// ================= helpers =================
typedef unsigned long long ull;
__device__ __forceinline__ uint32_t smem_u32(const void* p) {
    uint32_t a;
    asm("{ .reg .u64 t; cvta.to.shared.u64 t, %1; cvt.u32.u64 %0, t; }" : "=r"(a) : "l"(p));
    return a;
}
__device__ __forceinline__ void ldsm4(uint32_t& r0, uint32_t& r1, uint32_t& r2, uint32_t& r3,
                                      uint32_t addr) {
    asm volatile("ldmatrix.sync.aligned.m8n8.x4.shared.b16 {%0,%1,%2,%3}, [%4];"
                 : "=r"(r0), "=r"(r1), "=r"(r2), "=r"(r3) : "r"(addr));
}
__device__ __forceinline__ void ldsm4t(uint32_t& r0, uint32_t& r1, uint32_t& r2, uint32_t& r3,
                                       uint32_t addr) {
    asm volatile("ldmatrix.sync.aligned.m8n8.x4.trans.shared.b16 {%0,%1,%2,%3}, [%4];"
                 : "=r"(r0), "=r"(r1), "=r"(r2), "=r"(r3) : "r"(addr));
}
__device__ __forceinline__ void mma16816(float* c, uint32_t a0, uint32_t a1, uint32_t a2,
                                         uint32_t a3, uint32_t b0, uint32_t b1) {
    asm volatile(
        "mma.sync.aligned.m16n8k16.row.col.f32.bf16.bf16.f32 "
        "{%0,%1,%2,%3}, {%4,%5,%6,%7}, {%8,%9}, {%0,%1,%2,%3};"
        : "+f"(c[0]), "+f"(c[1]), "+f"(c[2]), "+f"(c[3])
        : "r"(a0), "r"(a1), "r"(a2), "r"(a3), "r"(b0), "r"(b1));
}
__device__ __forceinline__ void bsplit2(float x0, float x1, uint32_t& h, uint32_t& l) {
    uint16_t h0, h1, l0, l1;
    asm("cvt.rn.bf16.f32 %0, %1;" : "=h"(h0) : "f"(x0));
    asm("cvt.rn.bf16.f32 %0, %1;" : "=h"(h1) : "f"(x1));
    float f0 = __uint_as_float((uint32_t)h0 << 16);
    float f1 = __uint_as_float((uint32_t)h1 << 16);
    asm("cvt.rn.bf16.f32 %0, %1;" : "=h"(l0) : "f"(x0 - f0));
    asm("cvt.rn.bf16.f32 %0, %1;" : "=h"(l1) : "f"(x1 - f1));
    h = (uint32_t)h0 | ((uint32_t)h1 << 16);
    l = (uint32_t)l0 | ((uint32_t)l1 << 16);
}
__device__ __forceinline__ uint32_t sw_off(int row, int d) {
    return (uint32_t)(row * 256 + ((((d >> 3) ^ (row & 7)) & 15) << 4) + (d & 7) * 2);
}
__device__ __forceinline__ float sinpoly(float x) {
    float x2 = x * x;
    float pp = fmaf(x2, 2.7557319e-06f, -1.9841270e-04f);
    pp = fmaf(x2, pp, 8.3333333e-03f);
    pp = fmaf(x2, pp, -1.6666667e-01f);
    return fmaf(x * x2, pp, x);
}
__device__ __forceinline__ ull dup2(float x) {
    ull r; asm("mov.b64 %0, {%1, %1};" : "=l"(r) : "f"(x)); return r;
}
__device__ __forceinline__ void fma2(ull& d, ull a, ull b) {
    asm("fma.rn.f32x2 %0, %1, %2, %0;" : "+l"(d) : "l"(a), "l"(b));
}
__device__ __forceinline__ float2 unpk(ull v) {
    float2 r; asm("mov.b64 {%0, %1}, %2;" : "=f"(r.x), "=f"(r.y) : "l"(v)); return r;
}

// smem: Qhi 32K | Qlo 32K | K double-buffered (hi/lo 16K each) x2 = 128KB
#define QH_OFF 0
#define QL_OFF 32768
#define KBASE  65536
#define ATTN_SMEM 131072

// ---------------- causal sin-attention: mma.sync bf16 3-pass, pipelined K ----------------
__global__ __launch_bounds__(256) void attn_kernel(const float* __restrict__ Q,
                                                   const float* __restrict__ Kh,
                                                   float* __restrict__ O0,
                                                   float* __restrict__ O1,
                                                   float* __restrict__ O2,
                                                   float* __restrict__ O3) {
    extern __shared__ char smc[];
    const uint32_t sbase = smem_u32(smc);
    const int tid = threadIdx.x;
    const int lane = tid & 31, w = tid >> 5;
    const int p = blockIdx.x, qq = blockIdx.y, b = blockIdx.z;
    float* Out = (qq == 0) ? O0 : (qq == 1) ? O1 : (qq == 2) ? O2 : O3;
    const float* Qb = Q + (long long)b * TT * DD;
    const float* Kb = Kh + (long long)b * TT * DD;
    const int g = lane >> 3, r = lane & 7;
    const int krow = tid >> 2, kc0 = (tid & 3) * 32;

    for (int rep = 0; rep < 2; rep++) {
        const int R = rep ? (31 - p) : p;
        if (rep) __syncthreads();
        // ---- Q tile (128x128) -> Qhi/Qlo bf16, swizzled ----
        for (int t = tid; t < 2048; t += 256) {
            int row = t >> 4, d0 = (t & 15) * 8;
            const float* src = Qb + ((long long)R * 128 + row) * DD + d0;
            float4 u = *(const float4*)src;
            float4 v = *(const float4*)(src + 4);
            uint32_t hw[4], lw[4];
            bsplit2(u.x, u.y, hw[0], lw[0]);
            bsplit2(u.z, u.w, hw[1], lw[1]);
            bsplit2(v.x, v.y, hw[2], lw[2]);
            bsplit2(v.z, v.w, hw[3], lw[3]);
            uint32_t off = sw_off(row, d0);
            *(uint4*)(smc + QH_OFF + off) = make_uint4(hw[0], hw[1], hw[2], hw[3]);
            *(uint4*)(smc + QL_OFF + off) = make_uint4(lw[0], lw[1], lw[2], lw[3]);
        }

        const int nblk = 2 * R + 2;
        const int sb0 = (nblk * qq) >> 2;
        const int sb1 = (nblk * (qq + 1)) >> 2;

        // ---- preload K(sb0) -> buffer 0 ----
        {
            const float* src = Kb + ((long long)sb0 * 64 + krow) * DD + kc0;
            float4 pf[8];
#pragma unroll
            for (int q = 0; q < 8; q++) pf[q] = *(const float4*)(src + 4 * q);
#pragma unroll
            for (int q = 0; q < 4; q++) {
                uint32_t hw[4], lw[4];
                bsplit2(pf[2 * q].x, pf[2 * q].y, hw[0], lw[0]);
                bsplit2(pf[2 * q].z, pf[2 * q].w, hw[1], lw[1]);
                bsplit2(pf[2 * q + 1].x, pf[2 * q + 1].y, hw[2], lw[2]);
                bsplit2(pf[2 * q + 1].z, pf[2 * q + 1].w, hw[3], lw[3]);
                uint32_t off = sw_off(krow, kc0 + 8 * q);
                *(uint4*)(smc + KBASE + off) = make_uint4(hw[0], hw[1], hw[2], hw[3]);
                *(uint4*)(smc + KBASE + 16384 + off) = make_uint4(lw[0], lw[1], lw[2], lw[3]);
            }
        }

        float Oc[16][4];
#pragma unroll
        for (int nf = 0; nf < 16; nf++)
#pragma unroll
            for (int e = 0; e < 4; e++) Oc[nf][e] = 0.f;
        __syncthreads();

        for (int sb = sb0; sb < sb1; sb++) {
            const int cur = (sb - sb0) & 1;
            const uint32_t KH = KBASE + (uint32_t)cur * 32768;
            const uint32_t KL = KH + 16384;
            const bool pre = (sb + 1 < sb1);
            const float* psrc = Kb + ((long long)(sb + 1) * 64 + krow) * DD + kc0;
            float4 pf[8];
            if (pre) {
#pragma unroll
                for (int q = 0; q < 4; q++) pf[q] = *(const float4*)(psrc + 4 * q);
            }

            // ---- MMA1: C[16x64] = Q . K^T (3-pass bf16) ----
            float C[8][4];
#pragma unroll
            for (int nf = 0; nf < 8; nf++)
#pragma unroll
                for (int e = 0; e < 4; e++) C[nf][e] = 0.f;
#pragma unroll
            for (int kc = 0; kc < 8; kc++) {
                int d0 = kc * 16;
                uint32_t aoff = sw_off(w * 16 + ((g & 1) ? 8 : 0) + r, d0 + ((g >> 1) ? 8 : 0));
                uint32_t ah0, ah1, ah2, ah3, al0, al1, al2, al3;
                ldsm4(ah0, ah1, ah2, ah3, sbase + QH_OFF + aoff);
                ldsm4(al0, al1, al2, al3, sbase + QL_OFF + aoff);
#pragma unroll
                for (int nfp = 0; nfp < 4; nfp++) {
                    int j0 = nfp * 16;
                    uint32_t boff = sw_off(j0 + ((g >> 1) ? 8 : 0) + r, d0 + ((g & 1) ? 8 : 0));
                    uint32_t bh0, bh1, bh2, bh3, bl0, bl1, bl2, bl3;
                    ldsm4(bh0, bh1, bh2, bh3, sbase + KH + boff);
                    ldsm4(bl0, bl1, bl2, bl3, sbase + KL + boff);
                    mma16816(C[2 * nfp],     ah0, ah1, ah2, ah3, bh0, bh1);
                    mma16816(C[2 * nfp + 1], ah0, ah1, ah2, ah3, bh2, bh3);
                    mma16816(C[2 * nfp],     ah0, ah1, ah2, ah3, bl0, bl1);
                    mma16816(C[2 * nfp + 1], ah0, ah1, ah2, ah3, bl2, bl3);
                    mma16816(C[2 * nfp],     al0, al1, al2, al3, bh0, bh1);
                    mma16816(C[2 * nfp + 1], al0, al1, al2, al3, bh2, bh3);
                }
            }
            if (pre) {
#pragma unroll
                for (int q = 4; q < 8; q++) pf[q] = *(const float4*)(psrc + 4 * q);
            }

            // ---- sin + causal mask + repack C-frags -> A-frags of MMA2 ----
            uint32_t a2h[4][4], a2l[4][4];
            const int ig = R * 128 + w * 16 + (lane >> 2);
#pragma unroll
            for (int nf = 0; nf < 8; nf++) {
                int jb = sb * 64 + nf * 8 + 2 * (lane & 3);
                float s0 = sinpoly(C[nf][0]); if (jb > ig) s0 = 0.f;
                float s1 = sinpoly(C[nf][1]); if (jb + 1 > ig) s1 = 0.f;
                float s2 = sinpoly(C[nf][2]); if (jb > ig + 8) s2 = 0.f;
                float s3 = sinpoly(C[nf][3]); if (jb + 1 > ig + 8) s3 = 0.f;
                int kc2 = nf >> 1, hk = (nf & 1) ? 2 : 0;
                bsplit2(s0, s1, a2h[kc2][hk], a2l[kc2][hk]);
                bsplit2(s2, s3, a2h[kc2][hk + 1], a2l[kc2][hk + 1]);
            }

            // ---- MMA2: O[16x128] += S . K (3-pass bf16) ----
#pragma unroll
            for (int kc2 = 0; kc2 < 4; kc2++) {
                int j0 = kc2 * 16;
#pragma unroll
                for (int nfp = 0; nfp < 8; nfp++) {
                    int d0 = nfp * 16;
                    uint32_t boff = sw_off(j0 + ((g & 1) ? 8 : 0) + r, d0 + ((g >> 1) ? 8 : 0));
                    uint32_t th0, th1, th2, th3, tl0, tl1, tl2, tl3;
                    ldsm4t(th0, th1, th2, th3, sbase + KH + boff);
                    ldsm4t(tl0, tl1, tl2, tl3, sbase + KL + boff);
                    mma16816(Oc[2 * nfp],     a2h[kc2][0], a2h[kc2][1], a2h[kc2][2], a2h[kc2][3], th0, th1);
                    mma16816(Oc[2 * nfp + 1], a2h[kc2][0], a2h[kc2][1], a2h[kc2][2], a2h[kc2][3], th2, th3);
                    mma16816(Oc[2 * nfp],     a2h[kc2][0], a2h[kc2][1], a2h[kc2][2], a2h[kc2][3], tl0, tl1);
                    mma16816(Oc[2 * nfp + 1], a2h[kc2][0], a2h[kc2][1], a2h[kc2][2], a2h[kc2][3], tl2, tl3);
                    mma16816(Oc[2 * nfp],     a2l[kc2][0], a2l[kc2][1], a2l[kc2][2], a2l[kc2][3], th0, th1);
                    mma16816(Oc[2 * nfp + 1], a2l[kc2][0], a2l[kc2][1], a2l[kc2][2], a2l[kc2][3], th2, th3);
                }
            }

            // ---- convert + store prefetched K(sb+1) into other buffer ----
            if (pre) {
                const uint32_t NH = KBASE + (uint32_t)(1 - cur) * 32768;
#pragma unroll
                for (int q = 0; q < 4; q++) {
                    uint32_t hw[4], lw[4];
                    bsplit2(pf[2 * q].x, pf[2 * q].y, hw[0], lw[0]);
                    bsplit2(pf[2 * q].z, pf[2 * q].w, hw[1], lw[1]);
                    bsplit2(pf[2 * q + 1].x, pf[2 * q + 1].y, hw[2], lw[2]);
                    bsplit2(pf[2 * q + 1].z, pf[2 * q + 1].w, hw[3], lw[3]);
                    uint32_t off = sw_off(krow, kc0 + 8 * q);
                    *(uint4*)(smc + NH + off) = make_uint4(hw[0], hw[1], hw[2], hw[3]);
                    *(uint4*)(smc + NH + 16384 + off) = make_uint4(lw[0], lw[1], lw[2], lw[3]);
                }
            }
            __syncthreads();
        }

        // ---- write O tile ----
        {
            long long rbase = (long long)b * TT + (long long)R * 128 + w * 16 + (lane >> 2);
#pragma unroll
            for (int nf = 0; nf < 16; nf++) {
                int d = nf * 8 + 2 * (lane & 3);
                *(float2*)(Out + rbase * DD + d) = make_float2(Oc[nf][0], Oc[nf][1]);
                *(float2*)(Out + (rbase + 8) * DD + d) = make_float2(Oc[nf][2], Oc[nf][3]);
            }
        }
    }
}

// ---------------- depthwise causal conv ----------------
__global__ __launch_bounds__(512) void conv_kernel(const float* __restrict__ z,
                                                   const float* __restrict__ w,
                                                   const float* __restrict__ bias,
                                                   float* __restrict__ mf) {
    int d = threadIdx.x;
    int t = blockIdx.x * 4 + threadIdx.y;
    int b = blockIdx.y;
    float acc = bias[d];
    int kstart = (KK - 1) - t;
    if (kstart < 0) kstart = 0;
    const float* zp = z + ((long long)b * TT + t - (KK - 1)) * DD + d;
    const float* wp = w + d;
#pragma unroll 4
    for (int k = kstart; k < KK; k++)
        acc = fmaf(zp[(long long)k * DD], wp[(long long)k * DD], acc);
    mf[((long long)b * TT + t) * DD + d] = acc;
}

// ---------------- group reduce of 8 values (128-thread group of a 512 block) ----------------
__device__ __forceinline__ void group_reduce8(float v[8], float* red, int grp, int wig, int lane) {
#pragma unroll
    for (int k = 0; k < 8; k++) {
        float x = v[k];
#pragma unroll
        for (int o = 16; o; o >>= 1) x += __shfl_xor_sync(0xffffffffu, x, o);
        if (lane == 0) red[grp * 32 + wig * 8 + k] = x;
    }
    __syncthreads();
#pragma unroll
    for (int k = 0; k < 8; k++)
        v[k] = red[grp * 32 + k] + red[grp * 32 + 8 + k] + red[grp * 32 + 16 + k] +
               red[grp * 32 + 24 + k];
    __syncthreads();
}

// FFMA2 matvec: 8 rows (4 pairs in xg), result rows written to tot[8]
__device__ __forceinline__ void matvec8(const float* Ws, const float* xg, int d, float bias,
                                        float tot[8]) {
    ull acc0 = dup2(bias), acc1 = dup2(bias), acc2 = dup2(bias), acc3 = dup2(bias);
#pragma unroll 4
    for (int j = 0; j < 128; j++) {
        ull w2 = dup2(Ws[j * 128 + d]);
        fma2(acc0, *(const ull*)(xg + 2 * j), w2);
        fma2(acc1, *(const ull*)(xg + 256 + 2 * j), w2);
        fma2(acc2, *(const ull*)(xg + 512 + 2 * j), w2);
        fma2(acc3, *(const ull*)(xg + 768 + 2 * j), w2);
    }
    float2 a0 = unpk(acc0), a1 = unpk(acc1), a2 = unpk(acc2), a3 = unpk(acc3);
    tot[0] = a0.x; tot[1] = a0.y; tot[2] = a1.x; tot[3] = a1.y;
    tot[4] = a2.x; tot[5] = a2.y; tot[6] = a3.x; tot[7] = a3.y;
}

#define EPI_SMEM ((16384 + 16384 + 4096 + 128) * 4)

// ---------------- dual projection: kh = norm(z Wk + bk), qh = norm(z Wq + bq) ----------------
__global__ __launch_bounds__(512) void dual_gemm_norm(const float* __restrict__ X,
                                                      const float* __restrict__ W1,
                                                      const float* __restrict__ b1,
                                                      const float* __restrict__ W2,
                                                      const float* __restrict__ b2,
                                                      float* __restrict__ Y1,
                                                      float* __restrict__ Y2) {
    extern __shared__ float sm[];
    float* W1s = sm;
    float* W2s = sm + 16384;
    float* xp  = sm + 32768;
    float* red = sm + 36864;
    int tid = threadIdx.x, grp = tid >> 7, d = tid & 127, wig = (tid >> 5) & 3, lane = tid & 31;
    for (int i = tid; i < 16384; i += 512) { W1s[i] = W1[i]; W2s[i] = W2[i]; }
    float b1v = b1[d], b2v = b2[d];
    __syncthreads();
    long long row0 = (long long)blockIdx.x * 64 + grp * 16;
    float* xg = xp + grp * 1024;
    for (int gg = 0; gg < 16; gg += 8) {
#pragma unroll
        for (int q = 0; q < 4; q++) {
            long long o0 = (row0 + gg + 2 * q) * DD + d;
            *(float2*)(xg + q * 256 + 2 * d) = make_float2(X[o0], X[o0 + DD]);
        }
        __syncthreads();
        float tot[8], v[8];
        matvec8(W1s, xg, d, b1v, tot);
#pragma unroll
        for (int k = 0; k < 8; k++) v[k] = tot[k] * tot[k];
        group_reduce8(v, red, grp, wig, lane);
#pragma unroll
        for (int k = 0; k < 8; k++)
            Y1[(row0 + gg + k) * DD + d] = __fdividef(tot[k], fmaxf(sqrtf(v[k]), 1e-8f));
        matvec8(W2s, xg, d, b2v, tot);
#pragma unroll
        for (int k = 0; k < 8; k++) v[k] = tot[k] * tot[k];
        group_reduce8(v, red, grp, wig, lane);
#pragma unroll
        for (int k = 0; k < 8; k++)
            Y2[(row0 + gg + k) * DD + d] = __fdividef(tot[k], fmaxf(sqrtf(v[k]), 1e-8f));
        __syncthreads();
    }
}

// ---------------- fused epilogue + next q projection (or final retraction) ----------------
__global__ __launch_bounds__(512) void epilogue_kernel(
    const float* __restrict__ A0, const float* __restrict__ A1,
    const float* __restrict__ A2, const float* __restrict__ A3,
    const float* __restrict__ Wo, const float* __restrict__ bo,
    const float* __restrict__ Wq, const float* __restrict__ bq,
    const float* __restrict__ mf, const float* __restrict__ zin,
    const float* __restrict__ zbase, float* __restrict__ vacc,
    float* __restrict__ zc, float* __restrict__ qh, float* __restrict__ out,
    float sw, float rc, int first, int has_next) {
    extern __shared__ float sm[];
    float* Wos = sm;
    float* Wqs = sm + 16384;
    float* xp  = sm + 32768;
    float* red = sm + 36864;
    int tid = threadIdx.x, grp = tid >> 7, d = tid & 127, wig = (tid >> 5) & 3, lane = tid & 31;
    for (int i = tid; i < 16384; i += 512) { Wos[i] = Wo[i]; Wqs[i] = Wq[i]; }
    float bov = bo[d], bqv = bq[d];
    __syncthreads();
    long long row0 = (long long)blockIdx.x * 64 + grp * 16;
    float* xg = xp + grp * 1024;
    for (int gg = 0; gg < 16; gg += 8) {
#pragma unroll
        for (int q = 0; q < 4; q++) {
            long long o0 = (row0 + gg + 2 * q) * DD + d;
            long long o1 = o0 + DD;
            float v0 = A0[o0] + A1[o0] + A2[o0] + A3[o0];
            float v1 = A0[o1] + A1[o1] + A2[o1] + A3[o1];
            *(float2*)(xg + q * 256 + 2 * d) = make_float2(v0, v1);
        }
        __syncthreads();
        float tot[8], zcd[8], v[8];
        matvec8(Wos, xg, d, bov, tot);
#pragma unroll
        for (int k = 0; k < 8; k++) {
            long long off = (row0 + gg + k) * DD + d;
            tot[k] += mf[off];
            zcd[k] = zin[off];
            v[k] = tot[k] * zcd[k];
        }
        group_reduce8(v, red, grp, wig, lane);
        float va_new[8];
#pragma unroll
        for (int k = 0; k < 8; k++) {
            long long off = (row0 + gg + k) * DD + d;
            float proj = tot[k] - v[k] * zcd[k];
            float vp = first ? 0.f : vacc[off];
            va_new[k] = vp + sw * proj;
            vacc[off] = va_new[k];
            tot[k] = proj;  // keep proj
        }
        if (has_next) {
            float zn[8], u[8];
#pragma unroll
            for (int k = 0; k < 8; k++) {
                long long off = (row0 + gg + k) * DD + d;
                zn[k] = zbase[off] + rc * tot[k];
                u[k] = zn[k] * zn[k];
            }
            group_reduce8(u, red, grp, wig, lane);
#pragma unroll
            for (int q = 0; q < 4; q++) {
                float z0 = __fdividef(zn[2 * q], fmaxf(sqrtf(u[2 * q]), 1e-8f));
                float z1 = __fdividef(zn[2 * q + 1], fmaxf(sqrtf(u[2 * q + 1]), 1e-8f));
                long long off = (row0 + gg + 2 * q) * DD + d;
                zc[off] = z0;
                zc[off + DD] = z1;
                *(float2*)(xg + q * 256 + 2 * d) = make_float2(z0, z1);
            }
            __syncthreads();
            float qv[8], w2[8];
            matvec8(Wqs, xg, d, bqv, qv);
#pragma unroll
            for (int k = 0; k < 8; k++) w2[k] = qv[k] * qv[k];
            group_reduce8(w2, red, grp, wig, lane);
#pragma unroll
            for (int k = 0; k < 8; k++)
                qh[(row0 + gg + k) * DD + d] =
                    __fdividef(qv[k], fmaxf(sqrtf(w2[k]), 1e-8f));
        } else {
            float fin[8], u[8];
#pragma unroll
            for (int k = 0; k < 8; k++) {
                long long off = (row0 + gg + k) * DD + d;
                fin[k] = zbase[off] + va_new[k];
                u[k] = fin[k] * fin[k];
            }
            group_reduce8(u, red, grp, wig, lane);
#pragma unroll
            for (int k = 0; k < 8; k++)
                out[(row0 + gg + k) * DD + d] =
                    __fdividef(fin[k], fmaxf(sqrtf(u[k]), 1e-8f));
        }
        __syncthreads();
    }
}

// ---------------- launch ----------------
extern "C" void kernel_launch(void* const* d_in, const int* in_sizes, int n_in,
                              void* d_out, int out_size) {
    const float* z  = (const float*)d_in[0];
    const float* ck = (const float*)d_in[1];
    const float* cb = (const float*)d_in[2];
    const float* Wq = (const float*)d_in[3];
    const float* bq = (const float*)d_in[4];
    const float* Wk = (const float*)d_in[5];
    const float* bk = (const float*)d_in[6];
    const float* Wo = (const float*)d_in[7];
    const float* bo = (const float*)d_in[8];
    float* out = (float*)d_out;

    float *kh, *mf, *qh, *a0, *a1, *a2, *a3, *zc, *va;
    cudaGetSymbolAddress((void**)&kh, g_kh);
    cudaGetSymbolAddress((void**)&mf, g_mf);
    cudaGetSymbolAddress((void**)&qh, g_qh);
    cudaGetSymbolAddress((void**)&a0, g_a0);
    cudaGetSymbolAddress((void**)&a1, g_a1);
    cudaGetSymbolAddress((void**)&a2, g_a2);
    cudaGetSymbolAddress((void**)&a3, g_a3);
    cudaGetSymbolAddress((void**)&zc, g_zc);
    cudaGetSymbolAddress((void**)&va, g_va);

    cudaFuncSetAttribute(dual_gemm_norm, cudaFuncAttributeMaxDynamicSharedMemorySize, EPI_SMEM);
    cudaFuncSetAttribute(epilogue_kernel, cudaFuncAttributeMaxDynamicSharedMemorySize, EPI_SMEM);
    cudaFuncSetAttribute(attn_kernel, cudaFuncAttributeMaxDynamicSharedMemorySize, ATTN_SMEM);

    conv_kernel<<<dim3(TT / 4, BB), dim3(128, 4)>>>(z, ck, cb, mf);
    dual_gemm_norm<<<BT / 64, 512, EPI_SMEM>>>(z, Wk, bk, Wq, bq, kh, qh);

    const float sws[4] = {1.f / 6.f, 2.f / 6.f, 2.f / 6.f, 1.f / 6.f};
    const float rcs[4] = {0.5f, 0.5f, 1.0f, 0.f};
    const float* zcur = z;
    for (int s = 0; s < 4; s++) {
        attn_kernel<<<dim3(16, 4, BB), 256, ATTN_SMEM>>>(qh, kh, a0, a1, a2, a3);
        epilogue_kernel<<<BT / 64, 512, EPI_SMEM>>>(a0, a1, a2, a3, Wo, bo, Wq, bq,
                                                    mf, zcur, z, va, zc, qh, out,
                                                    sws[s], rcs[s], s == 0 ? 1 : 0,
                                                    s < 3 ? 1 : 0);
        zcur = zc;
    }
}

// round 7
// speedup vs baseline: 2.9085x; 1.0249x over previous
#include <cuda_runtime.h>
#include <cstdint>

#define BB 2
#define TT 4096
#define DD 128
#define KK 256
#define BT (BB * TT)

// ---------------- scratch ----------------
__device__ float g_kh[BT * DD];
__device__ float g_mf[BT * DD];
__device__ float g_qh[BT * DD];
__device__ float g_a0[BT * DD];
__device__ float g_zc[BT * DD];
__device__ float g_va[BT * DD];

// ================= helpers =================
typedef unsigned long long ull;
__device__ __forceinline__ uint32_t smem_u32(const void* p) {
    uint32_t a;
    asm("{ .reg .u64 t; cvta.to.shared.u64 t, %1; cvt.u32.u64 %0, t; }" : "=r"(a) : "l"(p));
    return a;
}
__device__ __forceinline__ void ldsm4(uint32_t& r0, uint32_t& r1, uint32_t& r2, uint32_t& r3,
                                      uint32_t addr) {
    asm volatile("ldmatrix.sync.aligned.m8n8.x4.shared.b16 {%0,%1,%2,%3}, [%4];"
                 : "=r"(r0), "=r"(r1), "=r"(r2), "=r"(r3) : "r"(addr));
}
__device__ __forceinline__ void ldsm4t(uint32_t& r0, uint32_t& r1, uint32_t& r2, uint32_t& r3,
                                       uint32_t addr) {
    asm volatile("ldmatrix.sync.aligned.m8n8.x4.trans.shared.b16 {%0,%1,%2,%3}, [%4];"
                 : "=r"(r0), "=r"(r1), "=r"(r2), "=r"(r3) : "r"(addr));
}
__device__ __forceinline__ void mma16816(float* c, uint32_t a0, uint32_t a1, uint32_t a2,
                                         uint32_t a3, uint32_t b0, uint32_t b1) {
    asm volatile(
        "mma.sync.aligned.m16n8k16.row.col.f32.bf16.bf16.f32 "
        "{%0,%1,%2,%3}, {%4,%5,%6,%7}, {%8,%9}, {%0,%1,%2,%3};"
        : "+f"(c[0]), "+f"(c[1]), "+f"(c[2]), "+f"(c[3])
        : "r"(a0), "r"(a1), "r"(a2), "r"(a3), "r"(b0), "r"(b1));
}
__device__ __forceinline__ void bsplit2(float x0, float x1, uint32_t& h, uint32_t& l) {
    uint16_t h0, h1, l0, l1;
    asm("cvt.rn.bf16.f32 %0, %1;" : "=h"(h0) : "f"(x0));
    asm("cvt.rn.bf16.f32 %0, %1;" : "=h"(h1) : "f"(x1));
    float f0 = __uint_as_float((uint32_t)h0 << 16);
    float f1 = __uint_as_float((uint32_t)h1 << 16);
    asm("cvt.rn.bf16.f32 %0, %1;" : "=h"(l0) : "f"(x0 - f0));
    asm("cvt.rn.bf16.f32 %0, %1;" : "=h"(l1) : "f"(x1 - f1));
    h = (uint32_t)h0 | ((uint32_t)h1 << 16);
    l = (uint32_t)l0 | ((uint32_t)l1 << 16);
}
__device__ __forceinline__ uint32_t sw_off(int row, int d) {
    return (uint32_t)(row * 256 + ((((d >> 3) ^ (row & 7)) & 15) << 4) + (d & 7) * 2);
}
__device__ __forceinline__ float sinpoly(float x) {
    float x2 = x * x;
    float pp = fmaf(x2, 2.7557319e-06f, -1.9841270e-04f);
    pp = fmaf(x2, pp, 8.3333333e-03f);
    pp = fmaf(x2, pp, -1.6666667e-01f);
    return fmaf(x * x2, pp, x);
}
__device__ __forceinline__ ull dup2(float x) {
    ull r; asm("mov.b64 %0, {%1, %1};" : "=l"(r) : "f"(x)); return r;
}
__device__ __forceinline__ void fma2(ull& d, ull a, ull b) {
    asm("fma.rn.f32x2 %0, %1, %2, %0;" : "+l"(d) : "l"(a), "l"(b));
}
__device__ __forceinline__ float2 unpk(ull v) {
    float2 r; asm("mov.b64 {%0, %1}, %2;" : "=f"(r.x), "=f"(r.y) : "l"(v)); return r;
}

// attn smem: Qhi 16K | Qlo 16K | K double-buffered (hi 16K + lo 16K) x2 = 96KB
#define QH_OFF 0
#define QL_OFF 16384
#define KBASE_OFF 32768
#define ATTN_SMEM 98304

__device__ __forceinline__ void cvt_store8(char* smcp, uint32_t hoff, int krow, int col,
                                           float4 a, float4 b) {
    uint32_t hw[4], lw[4];
    bsplit2(a.x, a.y, hw[0], lw[0]);
    bsplit2(a.z, a.w, hw[1], lw[1]);
    bsplit2(b.x, b.y, hw[2], lw[2]);
    bsplit2(b.z, b.w, hw[3], lw[3]);
    uint32_t off = sw_off(krow, col);
    *(uint4*)(smcp + hoff + off) = make_uint4(hw[0], hw[1], hw[2], hw[3]);
    *(uint4*)(smcp + hoff + 16384 + off) = make_uint4(lw[0], lw[1], lw[2], lw[3]);
}

// ---------------- causal sin-attention: M=64 tile, 128 threads, 2 CTAs/SM ----------------
// Grid (32 pairs, 9 splits). Each CTA walks 4 sub-problems (b in {0,1}) x (R in {P, 63-P}),
// processing the s-block window [lo,hi) of the 130 total causal units. Output via atomicAdd.
__global__ __launch_bounds__(128, 2) void attn_kernel(const float* __restrict__ Q,
                                                      const float* __restrict__ Kh,
                                                      float* __restrict__ O) {
    extern __shared__ char smc[];
    const uint32_t sbase = smem_u32(smc);
    const int tid = threadIdx.x;
    const int lane = tid & 31, w = tid >> 5;
    const int P = blockIdx.x, split = blockIdx.y;
    const int g = lane >> 3, r = lane & 7;
    const int krow = tid >> 1, kc0 = (tid & 1) * 64;
    const int lo = (130 * split) / 9, hi = (130 * (split + 1)) / 9;

    int c = 0;
    for (int sp = 0; sp < 4; sp++) {
        const int b = sp >> 1;
        const int R = (sp & 1) ? (63 - P) : P;
        const int n = R + 1;
        int s_lo = lo - c; if (s_lo < 0) s_lo = 0;
        int s_hi = hi - c; if (s_hi > n) s_hi = n;
        c += n;
        if (s_lo >= s_hi) continue;

        const float* Qb = Q + (long long)b * TT * DD;
        const float* Kb = Kh + (long long)b * TT * DD;

        __syncthreads();  // prior sub-problem smem reads complete
        // ---- Q tile (64x128) -> Qhi/Qlo ----
        for (int t = tid; t < 1024; t += 128) {
            int row = t >> 4, d0 = (t & 15) * 8;
            const float* src = Qb + ((long long)R * 64 + row) * DD + d0;
            float4 u = *(const float4*)src;
            float4 v = *(const float4*)(src + 4);
            uint32_t hw[4], lw[4];
            bsplit2(u.x, u.y, hw[0], lw[0]);
            bsplit2(u.z, u.w, hw[1], lw[1]);
            bsplit2(v.x, v.y, hw[2], lw[2]);
            bsplit2(v.z, v.w, hw[3], lw[3]);
            uint32_t off = sw_off(row, d0);
            *(uint4*)(smc + QH_OFF + off) = make_uint4(hw[0], hw[1], hw[2], hw[3]);
            *(uint4*)(smc + QL_OFF + off) = make_uint4(lw[0], lw[1], lw[2], lw[3]);
        }
        // ---- preload K(s_lo) -> buffer 0 ----
        {
            const float* src = Kb + ((long long)s_lo * 64 + krow) * DD + kc0;
#pragma unroll
            for (int q = 0; q < 8; q++) {
                float4 a = *(const float4*)(src + 8 * q);
                float4 bb = *(const float4*)(src + 8 * q + 4);
                cvt_store8(smc, KBASE_OFF, krow, kc0 + 8 * q, a, bb);
            }
        }
        float Oc[16][4];
#pragma unroll
        for (int nf = 0; nf < 16; nf++)
#pragma unroll
            for (int e = 0; e < 4; e++) Oc[nf][e] = 0.f;
        __syncthreads();

        for (int sb = s_lo; sb < s_hi; sb++) {
            const int cur = (sb - s_lo) & 1;
            const uint32_t KH = KBASE_OFF + (uint32_t)cur * 32768;
            const uint32_t KL = KH + 16384;
            const bool pre = (sb + 1 < s_hi);
            const uint32_t NH = KBASE_OFF + (uint32_t)(1 - cur) * 32768;
            const float* psrc = Kb + ((long long)(sb + 1) * 64 + krow) * DD + kc0;
            float4 pf[4];
            if (pre) {
#pragma unroll
                for (int q = 0; q < 4; q++) pf[q] = *(const float4*)(psrc + 4 * q);
            }

            // ---- MMA1: C[16x64] = Q . K^T (3-pass bf16) ----
            float C[8][4];
#pragma unroll
            for (int nf = 0; nf < 8; nf++)
#pragma unroll
                for (int e = 0; e < 4; e++) C[nf][e] = 0.f;
#pragma unroll
            for (int kc = 0; kc < 8; kc++) {
                int d0 = kc * 16;
                uint32_t aoff = sw_off(w * 16 + ((g & 1) ? 8 : 0) + r, d0 + ((g >> 1) ? 8 : 0));
                uint32_t ah0, ah1, ah2, ah3, al0, al1, al2, al3;
                ldsm4(ah0, ah1, ah2, ah3, sbase + QH_OFF + aoff);
                ldsm4(al0, al1, al2, al3, sbase + QL_OFF + aoff);
#pragma unroll
                for (int nfp = 0; nfp < 4; nfp++) {
                    int j0 = nfp * 16;
                    uint32_t boff = sw_off(j0 + ((g >> 1) ? 8 : 0) + r, d0 + ((g & 1) ? 8 : 0));
                    uint32_t bh0, bh1, bh2, bh3, bl0, bl1, bl2, bl3;
                    ldsm4(bh0, bh1, bh2, bh3, sbase + KH + boff);
                    ldsm4(bl0, bl1, bl2, bl3, sbase + KL + boff);
                    mma16816(C[2 * nfp],     ah0, ah1, ah2, ah3, bh0, bh1);
                    mma16816(C[2 * nfp + 1], ah0, ah1, ah2, ah3, bh2, bh3);
                    mma16816(C[2 * nfp],     ah0, ah1, ah2, ah3, bl0, bl1);
                    mma16816(C[2 * nfp + 1], ah0, ah1, ah2, ah3, bl2, bl3);
                    mma16816(C[2 * nfp],     al0, al1, al2, al3, bh0, bh1);
                    mma16816(C[2 * nfp + 1], al0, al1, al2, al3, bh2, bh3);
                }
            }
            if (pre) {
                cvt_store8(smc, NH, krow, kc0,     pf[0], pf[1]);
                cvt_store8(smc, NH, krow, kc0 + 8, pf[2], pf[3]);
#pragma unroll
                for (int q = 0; q < 4; q++) pf[q] = *(const float4*)(psrc + 16 + 4 * q);
            }

            // ---- sin + causal mask + repack C-frags -> A-frags of MMA2 ----
            uint32_t a2h[4][4], a2l[4][4];
            const int ig = R * 64 + w * 16 + (lane >> 2);
#pragma unroll
            for (int nf = 0; nf < 8; nf++) {
                int jb = sb * 64 + nf * 8 + 2 * (lane & 3);
                float s0 = sinpoly(C[nf][0]); if (jb > ig) s0 = 0.f;
                float s1 = sinpoly(C[nf][1]); if (jb + 1 > ig) s1 = 0.f;
                float s2 = sinpoly(C[nf][2]); if (jb > ig + 8) s2 = 0.f;
                float s3 = sinpoly(C[nf][3]); if (jb + 1 > ig + 8) s3 = 0.f;
                int kc2 = nf >> 1, hk = (nf & 1) ? 2 : 0;
                bsplit2(s0, s1, a2h[kc2][hk], a2l[kc2][hk]);
                bsplit2(s2, s3, a2h[kc2][hk + 1], a2l[kc2][hk + 1]);
            }
            if (pre) {
                cvt_store8(smc, NH, krow, kc0 + 16, pf[0], pf[1]);
                cvt_store8(smc, NH, krow, kc0 + 24, pf[2], pf[3]);
#pragma unroll
                for (int q = 0; q < 4; q++) pf[q] = *(const float4*)(psrc + 32 + 4 * q);
            }

            // ---- MMA2: O[16x128] += S . K (3-pass bf16) ----
#pragma unroll
            for (int kc2 = 0; kc2 < 4; kc2++) {
                int j0 = kc2 * 16;
#pragma unroll
                for (int nfp = 0; nfp < 8; nfp++) {
                    int d0 = nfp * 16;
                    uint32_t boff = sw_off(j0 + ((g & 1) ? 8 : 0) + r, d0 + ((g >> 1) ? 8 : 0));
                    uint32_t th0, th1, th2, th3, tl0, tl1, tl2, tl3;
                    ldsm4t(th0, th1, th2, th3, sbase + KH + boff);
                    ldsm4t(tl0, tl1, tl2, tl3, sbase + KL + boff);
                    mma16816(Oc[2 * nfp],     a2h[kc2][0], a2h[kc2][1], a2h[kc2][2], a2h[kc2][3], th0, th1);
                    mma16816(Oc[2 * nfp + 1], a2h[kc2][0], a2h[kc2][1], a2h[kc2][2], a2h[kc2][3], th2, th3);
                    mma16816(Oc[2 * nfp],     a2h[kc2][0], a2h[kc2][1], a2h[kc2][2], a2h[kc2][3], tl0, tl1);
                    mma16816(Oc[2 * nfp + 1], a2h[kc2][0], a2h[kc2][1], a2h[kc2][2], a2h[kc2][3], tl2, tl3);
                    mma16816(Oc[2 * nfp],     a2l[kc2][0], a2l[kc2][1], a2l[kc2][2], a2l[kc2][3], th0, th1);
                    mma16816(Oc[2 * nfp + 1], a2l[kc2][0], a2l[kc2][1], a2l[kc2][2], a2l[kc2][3], th2, th3);
                }
            }
            if (pre) {
                cvt_store8(smc, NH, krow, kc0 + 32, pf[0], pf[1]);
                cvt_store8(smc, NH, krow, kc0 + 40, pf[2], pf[3]);
#pragma unroll
                for (int q = 0; q < 4; q++) pf[q] = *(const float4*)(psrc + 48 + 4 * q);
                cvt_store8(smc, NH, krow, kc0 + 48, pf[0], pf[1]);
                cvt_store8(smc, NH, krow, kc0 + 56, pf[2], pf[3]);
            }
            __syncthreads();
        }

        // ---- accumulate O tile (atomic adds; tile may be shared across split CTAs) ----
        {
            long long rbase = (long long)b * TT + (long long)R * 64 + w * 16 + (lane >> 2);
#pragma unroll
            for (int nf = 0; nf < 16; nf++) {
                int d = nf * 8 + 2 * (lane & 3);
                atomicAdd(O + rbase * DD + d,       Oc[nf][0]);
                atomicAdd(O + rbase * DD + d + 1,   Oc[nf][1]);
                atomicAdd(O + (rbase + 8) * DD + d,     Oc[nf][2]);
                atomicAdd(O + (rbase + 8) * DD + d + 1, Oc[nf][3]);
            }
        }
    }
}

// ---------------- depthwise causal conv ----------------
__global__ __launch_bounds__(512) void conv_kernel(const float* __restrict__ z,
                                                   const float* __restrict__ w,
                                                   const float* __restrict__ bias,
                                                   float* __restrict__ mf) {
    int d = threadIdx.x;
    int t = blockIdx.x * 4 + threadIdx.y;
    int b = blockIdx.y;
    float acc = bias[d];
    int kstart = (KK - 1) - t;
    if (kstart < 0) kstart = 0;
    const float* zp = z + ((long long)b * TT + t - (KK - 1)) * DD + d;
    const float* wp = w + d;
#pragma unroll 4
    for (int k = kstart; k < KK; k++)
        acc = fmaf(zp[(long long)k * DD], wp[(long long)k * DD], acc);
    mf[((long long)b * TT + t) * DD + d] = acc;
}

// ---------------- group reduce of 8 values (128-thread group of a 512 block) ----------------
__device__ __forceinline__ void group_reduce8(float v[8], float* red, int grp, int wig, int lane) {
#pragma unroll
    for (int k = 0; k < 8; k++) {
        float x = v[k];
#pragma unroll
        for (int o = 16; o; o >>= 1) x += __shfl_xor_sync(0xffffffffu, x, o);
        if (lane == 0) red[grp * 32 + wig * 8 + k] = x;
    }
    __syncthreads();
#pragma unroll
    for (int k = 0; k < 8; k++)
        v[k] = red[grp * 32 + k] + red[grp * 32 + 8 + k] + red[grp * 32 + 16 + k] +
               red[grp * 32 + 24 + k];
    __syncthreads();
}

// FFMA2 matvec over xg[j*8 + row] layout: broadcast LDS.128 pairs (3 wavefronts / j)
__device__ __forceinline__ void matvec8(const float* Ws, const float* xg, int d, float bias,
                                        float tot[8]) {
    ull acc0 = dup2(bias), acc1 = dup2(bias), acc2 = dup2(bias), acc3 = dup2(bias);
#pragma unroll 4
    for (int j = 0; j < 128; j++) {
        ull w2 = dup2(Ws[j * 128 + d]);
        ulonglong2 x01 = *(const ulonglong2*)(xg + j * 8);
        ulonglong2 x23 = *(const ulonglong2*)(xg + j * 8 + 4);
        fma2(acc0, x01.x, w2);
        fma2(acc1, x01.y, w2);
        fma2(acc2, x23.x, w2);
        fma2(acc3, x23.y, w2);
    }
    float2 a0 = unpk(acc0), a1 = unpk(acc1), a2 = unpk(acc2), a3 = unpk(acc3);
    tot[0] = a0.x; tot[1] = a0.y; tot[2] = a1.x; tot[3] = a1.y;
    tot[4] = a2.x; tot[5] = a2.y; tot[6] = a3.x; tot[7] = a3.y;
}

#define EPI_SMEM ((16384 + 16384 + 4096 + 128) * 4)

// ---------------- dual projection: kh = norm(z Wk + bk), qh = norm(z Wq + bq) ----------------
__global__ __launch_bounds__(512) void dual_gemm_norm(const float* __restrict__ X,
                                                      const float* __restrict__ W1,
                                                      const float* __restrict__ b1,
                                                      const float* __restrict__ W2,
                                                      const float* __restrict__ b2,
                                                      float* __restrict__ Y1,
                                                      float* __restrict__ Y2) {
    extern __shared__ float sm[];
    float* W1s = sm;
    float* W2s = sm + 16384;
    float* xp  = sm + 32768;
    float* red = sm + 36864;
    int tid = threadIdx.x, grp = tid >> 7, d = tid & 127, wig = (tid >> 5) & 3, lane = tid & 31;
    for (int i = tid; i < 16384; i += 512) { W1s[i] = W1[i]; W2s[i] = W2[i]; }
    float b1v = b1[d], b2v = b2[d];
    __syncthreads();
    long long row0 = (long long)blockIdx.x * 64 + grp * 16;
    float* xg = xp + grp * 1024;
    for (int gg = 0; gg < 16; gg += 8) {
#pragma unroll
        for (int k = 0; k < 8; k++)
            xg[d * 8 + k] = X[(row0 + gg + k) * DD + d];
        __syncthreads();
        float tot[8], v[8];
        matvec8(W1s, xg, d, b1v, tot);
#pragma unroll
        for (int k = 0; k < 8; k++) v[k] = tot[k] * tot[k];
        group_reduce8(v, red, grp, wig, lane);
#pragma unroll
        for (int k = 0; k < 8; k++)
            Y1[(row0 + gg + k) * DD + d] = __fdividef(tot[k], fmaxf(sqrtf(v[k]), 1e-8f));
        matvec8(W2s, xg, d, b2v, tot);
#pragma unroll
        for (int k = 0; k < 8; k++) v[k] = tot[k] * tot[k];
        group_reduce8(v, red, grp, wig, lane);
#pragma unroll
        for (int k = 0; k < 8; k++)
            Y2[(row0 + gg + k) * DD + d] = __fdividef(tot[k], fmaxf(sqrtf(v[k]), 1e-8f));
        __syncthreads();
    }
}

// ---------------- fused epilogue + next q projection (or final retraction) ----------------
__global__ __launch_bounds__(512) void epilogue_kernel(
    const float* __restrict__ A0,
    const float* __restrict__ Wo, const float* __restrict__ bo,
    const float* __restrict__ Wq, const float* __restrict__ bq,
    const float* __restrict__ mf, const float* __restrict__ zin,
    const float* __restrict__ zbase, float* __restrict__ vacc,
    float* __restrict__ zc, float* __restrict__ qh, float* __restrict__ out,
    float sw, float rc, int first, int has_next) {
    extern __shared__ float sm[];
    float* Wos = sm;
    float* Wqs = sm + 16384;
    float* xp  = sm + 32768;
    float* red = sm + 36864;
    int tid = threadIdx.x, grp = tid >> 7, d = tid & 127, wig = (tid >> 5) & 3, lane = tid & 31;
    for (int i = tid; i < 16384; i += 512) { Wos[i] = Wo[i]; Wqs[i] = Wq[i]; }
    float bov = bo[d], bqv = bq[d];
    __syncthreads();
    long long row0 = (long long)blockIdx.x * 64 + grp * 16;
    float* xg = xp + grp * 1024;
    for (int gg = 0; gg < 16; gg += 8) {
#pragma unroll
        for (int k = 0; k < 8; k++)
            xg[d * 8 + k] = A0[(row0 + gg + k) * DD + d];
        __syncthreads();
        float tot[8], zcd[8], v[8];
        matvec8(Wos, xg, d, bov, tot);
#pragma unroll
        for (int k = 0; k < 8; k++) {
            long long off = (row0 + gg + k) * DD + d;
            tot[k] += mf[off];
            zcd[k] = zin[off];
            v[k] = tot[k] * zcd[k];
        }
        group_reduce8(v, red, grp, wig, lane);
        float va_new[8];
#pragma unroll
        for (int k = 0; k < 8; k++) {
            long long off = (row0 + gg + k) * DD + d;
            float proj = tot[k] - v[k] * zcd[k];
            float vp = first ? 0.f : vacc[off];
            va_new[k] = vp + sw * proj;
            vacc[off] = va_new[k];
            tot[k] = proj;
        }
        if (has_next) {
            float zn[8], u[8];
#pragma unroll
            for (int k = 0; k < 8; k++) {
                long long off = (row0 + gg + k) * DD + d;
                zn[k] = zbase[off] + rc * tot[k];
                u[k] = zn[k] * zn[k];
            }
            group_reduce8(u, red, grp, wig, lane);
#pragma unroll
            for (int k = 0; k < 8; k++) {
                float z0 = __fdividef(zn[k], fmaxf(sqrtf(u[k]), 1e-8f));
                zc[(row0 + gg + k) * DD + d] = z0;
                xg[d * 8 + k] = z0;
            }
            __syncthreads();
            float qv[8], w2[8];
            matvec8(Wqs, xg, d, bqv, qv);
#pragma unroll
            for (int k = 0; k < 8; k++) w2[k] = qv[k] * qv[k];
            group_reduce8(w2, red, grp, wig, lane);
#pragma unroll
            for (int k = 0; k < 8; k++)
                qh[(row0 + gg + k) * DD + d] =
                    __fdividef(qv[k], fmaxf(sqrtf(w2[k]), 1e-8f));
        } else {
            float fin[8], u[8];
#pragma unroll
            for (int k = 0; k < 8; k++) {
                long long off = (row0 + gg + k) * DD + d;
                fin[k] = zbase[off] + va_new[k];
                u[k] = fin[k] * fin[k];
            }
            group_reduce8(u, red, grp, wig, lane);
#pragma unroll
            for (int k = 0; k < 8; k++)
                out[(row0 + gg + k) * DD + d] =
                    __fdividef(fin[k], fmaxf(sqrtf(u[k]), 1e-8f));
        }
        __syncthreads();
    }
}

// ---------------- launch ----------------
extern "C" void kernel_launch(void* const* d_in, const int* in_sizes, int n_in,
                              void* d_out, int out_size) {
    const float* z  = (const float*)d_in[0];
    const float* ck = (const float*)d_in[1];
    const float* cb = (const float*)d_in[2];
    const float* Wq = (const float*)d_in[3];
    const float* bq = (const float*)d_in[4];
    const float* Wk = (const float*)d_in[5];
    const float* bk = (const float*)d_in[6];
    const float* Wo = (const float*)d_in[7];
    const float* bo = (const float*)d_in[8];
    float* out = (float*)d_out;

    float *kh, *mf, *qh, *a0, *zc, *va;
    cudaGetSymbolAddress((void**)&kh, g_kh);
    cudaGetSymbolAddress((void**)&mf, g_mf);
    cudaGetSymbolAddress((void**)&qh, g_qh);
    cudaGetSymbolAddress((void**)&a0, g_a0);
    cudaGetSymbolAddress((void**)&zc, g_zc);
    cudaGetSymbolAddress((void**)&va, g_va);

    cudaFuncSetAttribute(dual_gemm_norm, cudaFuncAttributeMaxDynamicSharedMemorySize, EPI_SMEM);
    cudaFuncSetAttribute(epilogue_kernel, cudaFuncAttributeMaxDynamicSharedMemorySize, EPI_SMEM);
    cudaFuncSetAttribute(attn_kernel, cudaFuncAttributeMaxDynamicSharedMemorySize, ATTN_SMEM);

    conv_kernel<<<dim3(TT / 4, BB), dim3(128, 4)>>>(z, ck, cb, mf);
    dual_gemm_norm<<<BT / 64, 512, EPI_SMEM>>>(z, Wk, bk, Wq, bq, kh, qh);

    const float sws[4] = {1.f / 6.f, 2.f / 6.f, 2.f / 6.f, 1.f / 6.f};
    const float rcs[4] = {0.5f, 0.5f, 1.0f, 0.f};
    const float* zcur = z;
    for (int s = 0; s < 4; s++) {
        cudaMemsetAsync(a0, 0, (size_t)BT * DD * sizeof(float));
        attn_kernel<<<dim3(32, 9), 128, ATTN_SMEM>>>(qh, kh, a0);
        epilogue_kernel<<<BT / 64, 512, EPI_SMEM>>>(a0, Wo, bo, Wq, bq,
                                                    mf, zcur, z, va, zc, qh, out,
                                                    sws[s], rcs[s], s == 0 ? 1 : 0,
                                                    s < 3 ? 1 : 0);
        zcur = zc;
    }
}

// round 8
// speedup vs baseline: 3.0936x; 1.0636x over previous
#include <cuda_runtime.h>
#include <cstdint>

#define BB 2
#define TT 4096
#define DD 128
#define KK 256
#define BT (BB * TT)

// ---------------- scratch ----------------
__device__ float g_kh[BT * DD];
__device__ float g_mf[BT * DD];
__device__ float g_qh[BT * DD];
__device__ float g_a0[BT * DD];
__device__ float g_zc[BT * DD];
__device__ float g_va[BT * DD];

// ================= helpers =================
typedef unsigned long long ull;
__device__ __forceinline__ uint32_t smem_u32(const void* p) {
    uint32_t a;
    asm("{ .reg .u64 t; cvta.to.shared.u64 t, %1; cvt.u32.u64 %0, t; }" : "=r"(a) : "l"(p));
    return a;
}
__device__ __forceinline__ void ldsm4(uint32_t& r0, uint32_t& r1, uint32_t& r2, uint32_t& r3,
                                      uint32_t addr) {
    asm volatile("ldmatrix.sync.aligned.m8n8.x4.shared.b16 {%0,%1,%2,%3}, [%4];"
                 : "=r"(r0), "=r"(r1), "=r"(r2), "=r"(r3) : "r"(addr));
}
__device__ __forceinline__ void ldsm4t(uint32_t& r0, uint32_t& r1, uint32_t& r2, uint32_t& r3,
                                       uint32_t addr) {
    asm volatile("ldmatrix.sync.aligned.m8n8.x4.trans.shared.b16 {%0,%1,%2,%3}, [%4];"
                 : "=r"(r0), "=r"(r1), "=r"(r2), "=r"(r3) : "r"(addr));
}
__device__ __forceinline__ void mma16816(float* c, uint32_t a0, uint32_t a1, uint32_t a2,
                                         uint32_t a3, uint32_t b0, uint32_t b1) {
    asm volatile(
        "mma.sync.aligned.m16n8k16.row.col.f32.bf16.bf16.f32 "
        "{%0,%1,%2,%3}, {%4,%5,%6,%7}, {%8,%9}, {%0,%1,%2,%3};"
        : "+f"(c[0]), "+f"(c[1]), "+f"(c[2]), "+f"(c[3])
        : "r"(a0), "r"(a1), "r"(a2), "r"(a3), "r"(b0), "r"(b1));
}
__device__ __forceinline__ void bsplit2(float x0, float x1, uint32_t& h, uint32_t& l) {
    uint16_t h0, h1, l0, l1;
    asm("cvt.rn.bf16.f32 %0, %1;" : "=h"(h0) : "f"(x0));
    asm("cvt.rn.bf16.f32 %0, %1;" : "=h"(h1) : "f"(x1));
    float f0 = __uint_as_float((uint32_t)h0 << 16);
    float f1 = __uint_as_float((uint32_t)h1 << 16);
    asm("cvt.rn.bf16.f32 %0, %1;" : "=h"(l0) : "f"(x0 - f0));
    asm("cvt.rn.bf16.f32 %0, %1;" : "=h"(l1) : "f"(x1 - f1));
    h = (uint32_t)h0 | ((uint32_t)h1 << 16);
    l = (uint32_t)l0 | ((uint32_t)l1 << 16);
}
__device__ __forceinline__ uint32_t sw_off(int row, int d) {
    return (uint32_t)(row * 256 + ((((d >> 3) ^ (row & 7)) & 15) << 4) + (d & 7) * 2);
}
__device__ __forceinline__ float sinpoly(float x) {
    float x2 = x * x;
    float pp = fmaf(x2, 2.7557319e-06f, -1.9841270e-04f);
    pp = fmaf(x2, pp, 8.3333333e-03f);
    pp = fmaf(x2, pp, -1.6666667e-01f);
    return fmaf(x * x2, pp, x);
}
__device__ __forceinline__ ull dup2(float x) {
    ull r; asm("mov.b64 %0, {%1, %1};" : "=l"(r) : "f"(x)); return r;
}
__device__ __forceinline__ void fma2(ull& d, ull a, ull b) {
    asm("fma.rn.f32x2 %0, %1, %2, %0;" : "+l"(d) : "l"(a), "l"(b));
}
__device__ __forceinline__ float2 unpk(ull v) {
    float2 r; asm("mov.b64 {%0, %1}, %2;" : "=f"(r.x), "=f"(r.y) : "l"(v)); return r;
}

// generic: convert 8 fp32 cols -> bf16 hi/lo at (hoff, loff)
__device__ __forceinline__ void cvt_store8o(char* smcp, uint32_t hoff, uint32_t loff,
                                            int row, int col, float4 a, float4 b) {
    uint32_t hw[4], lw[4];
    bsplit2(a.x, a.y, hw[0], lw[0]);
    bsplit2(a.z, a.w, hw[1], lw[1]);
    bsplit2(b.x, b.y, hw[2], lw[2]);
    bsplit2(b.z, b.w, hw[3], lw[3]);
    uint32_t off = sw_off(row, col);
    *(uint4*)(smcp + hoff + off) = make_uint4(hw[0], hw[1], hw[2], hw[3]);
    *(uint4*)(smcp + loff + off) = make_uint4(lw[0], lw[1], lw[2], lw[3]);
}

// attn smem: Qhi 16K | Qlo 16K | K double-buffered (hi 16K + lo 16K) x2 = 96KB
#define QH_OFF 0
#define QL_OFF 16384
#define KBASE_OFF 32768
#define ATTN_SMEM 98304

__device__ __forceinline__ void cvt_store8(char* smcp, uint32_t hoff, int krow, int col,
                                           float4 a, float4 b) {
    cvt_store8o(smcp, hoff, hoff + 16384, krow, col, a, b);
}

// ---------------- causal sin-attention: M=64 tile, 128 threads, 2 CTAs/SM ----------------
__global__ __launch_bounds__(128, 2) void attn_kernel(const float* __restrict__ Q,
                                                      const float* __restrict__ Kh,
                                                      float* __restrict__ O) {
    extern __shared__ char smc[];
    const uint32_t sbase = smem_u32(smc);
    const int tid = threadIdx.x;
    const int lane = tid & 31, w = tid >> 5;
    const int P = blockIdx.x, split = blockIdx.y;
    const int g = lane >> 3, r = lane & 7;
    const int krow = tid >> 1, kc0 = (tid & 1) * 64;
    const int lo = (130 * split) / 9, hi = (130 * (split + 1)) / 9;

    int c = 0;
    for (int sp = 0; sp < 4; sp++) {
        const int b = sp >> 1;
        const int R = (sp & 1) ? (63 - P) : P;
        const int n = R + 1;
        int s_lo = lo - c; if (s_lo < 0) s_lo = 0;
        int s_hi = hi - c; if (s_hi > n) s_hi = n;
        c += n;
        if (s_lo >= s_hi) continue;

        const float* Qb = Q + (long long)b * TT * DD;
        const float* Kb = Kh + (long long)b * TT * DD;

        __syncthreads();
        for (int t = tid; t < 1024; t += 128) {
            int row = t >> 4, d0 = (t & 15) * 8;
            const float* src = Qb + ((long long)R * 64 + row) * DD + d0;
            cvt_store8o(smc, QH_OFF, QL_OFF, row, d0,
                        *(const float4*)src, *(const float4*)(src + 4));
        }
        {
            const float* src = Kb + ((long long)s_lo * 64 + krow) * DD + kc0;
#pragma unroll
            for (int q = 0; q < 8; q++) {
                float4 a = *(const float4*)(src + 8 * q);
                float4 bb = *(const float4*)(src + 8 * q + 4);
                cvt_store8(smc, KBASE_OFF, krow, kc0 + 8 * q, a, bb);
            }
        }
        float Oc[16][4];
#pragma unroll
        for (int nf = 0; nf < 16; nf++)
#pragma unroll
            for (int e = 0; e < 4; e++) Oc[nf][e] = 0.f;
        __syncthreads();

        for (int sb = s_lo; sb < s_hi; sb++) {
            const int cur = (sb - s_lo) & 1;
            const uint32_t KH = KBASE_OFF + (uint32_t)cur * 32768;
            const uint32_t KL = KH + 16384;
            const bool pre = (sb + 1 < s_hi);
            const uint32_t NH = KBASE_OFF + (uint32_t)(1 - cur) * 32768;
            const float* psrc = Kb + ((long long)(sb + 1) * 64 + krow) * DD + kc0;
            float4 pf[4];
            if (pre) {
#pragma unroll
                for (int q = 0; q < 4; q++) pf[q] = *(const float4*)(psrc + 4 * q);
            }

            // ---- MMA1: C = Q . K^T (3-pass, pass-outer for dep distance 8) ----
            float C[8][4];
#pragma unroll
            for (int nf = 0; nf < 8; nf++)
#pragma unroll
                for (int e = 0; e < 4; e++) C[nf][e] = 0.f;
#pragma unroll
            for (int kc = 0; kc < 8; kc++) {
                int d0 = kc * 16;
                uint32_t aoff = sw_off(w * 16 + ((g & 1) ? 8 : 0) + r, d0 + ((g >> 1) ? 8 : 0));
                uint32_t ah0, ah1, ah2, ah3, al0, al1, al2, al3;
                ldsm4(ah0, ah1, ah2, ah3, sbase + QH_OFF + aoff);
                ldsm4(al0, al1, al2, al3, sbase + QL_OFF + aoff);
                uint32_t bh[4][4], bl[4][4];
#pragma unroll
                for (int nfp = 0; nfp < 4; nfp++) {
                    uint32_t boff = sw_off(nfp * 16 + ((g >> 1) ? 8 : 0) + r,
                                           d0 + ((g & 1) ? 8 : 0));
                    ldsm4(bh[nfp][0], bh[nfp][1], bh[nfp][2], bh[nfp][3], sbase + KH + boff);
                    ldsm4(bl[nfp][0], bl[nfp][1], bl[nfp][2], bl[nfp][3], sbase + KL + boff);
                }
#pragma unroll
                for (int nfp = 0; nfp < 4; nfp++) {
                    mma16816(C[2 * nfp],     ah0, ah1, ah2, ah3, bh[nfp][0], bh[nfp][1]);
                    mma16816(C[2 * nfp + 1], ah0, ah1, ah2, ah3, bh[nfp][2], bh[nfp][3]);
                }
#pragma unroll
                for (int nfp = 0; nfp < 4; nfp++) {
                    mma16816(C[2 * nfp],     ah0, ah1, ah2, ah3, bl[nfp][0], bl[nfp][1]);
                    mma16816(C[2 * nfp + 1], ah0, ah1, ah2, ah3, bl[nfp][2], bl[nfp][3]);
                }
#pragma unroll
                for (int nfp = 0; nfp < 4; nfp++) {
                    mma16816(C[2 * nfp],     al0, al1, al2, al3, bh[nfp][0], bh[nfp][1]);
                    mma16816(C[2 * nfp + 1], al0, al1, al2, al3, bh[nfp][2], bh[nfp][3]);
                }
            }
            if (pre) {
                cvt_store8(smc, NH, krow, kc0,     pf[0], pf[1]);
                cvt_store8(smc, NH, krow, kc0 + 8, pf[2], pf[3]);
#pragma unroll
                for (int q = 0; q < 4; q++) pf[q] = *(const float4*)(psrc + 16 + 4 * q);
            }

            // ---- sin + causal mask + repack ----
            uint32_t a2h[4][4], a2l[4][4];
            const int ig = R * 64 + w * 16 + (lane >> 2);
#pragma unroll
            for (int nf = 0; nf < 8; nf++) {
                int jb = sb * 64 + nf * 8 + 2 * (lane & 3);
                float s0 = sinpoly(C[nf][0]); if (jb > ig) s0 = 0.f;
                float s1 = sinpoly(C[nf][1]); if (jb + 1 > ig) s1 = 0.f;
                float s2 = sinpoly(C[nf][2]); if (jb > ig + 8) s2 = 0.f;
                float s3 = sinpoly(C[nf][3]); if (jb + 1 > ig + 8) s3 = 0.f;
                int kc2 = nf >> 1, hk = (nf & 1) ? 2 : 0;
                bsplit2(s0, s1, a2h[kc2][hk], a2l[kc2][hk]);
                bsplit2(s2, s3, a2h[kc2][hk + 1], a2l[kc2][hk + 1]);
            }
            if (pre) {
                cvt_store8(smc, NH, krow, kc0 + 16, pf[0], pf[1]);
                cvt_store8(smc, NH, krow, kc0 + 24, pf[2], pf[3]);
#pragma unroll
                for (int q = 0; q < 4; q++) pf[q] = *(const float4*)(psrc + 32 + 4 * q);
            }

            // ---- MMA2: O += S . K (3-pass, pass-outer over nfp-halves) ----
#pragma unroll
            for (int kc2 = 0; kc2 < 4; kc2++) {
                int j0 = kc2 * 16;
#pragma unroll
                for (int hh = 0; hh < 2; hh++) {
                    uint32_t th[4][4], tl[4][4];
#pragma unroll
                    for (int q = 0; q < 4; q++) {
                        int nfp = hh * 4 + q;
                        uint32_t boff = sw_off(j0 + ((g & 1) ? 8 : 0) + r,
                                               nfp * 16 + ((g >> 1) ? 8 : 0));
                        ldsm4t(th[q][0], th[q][1], th[q][2], th[q][3], sbase + KH + boff);
                        ldsm4t(tl[q][0], tl[q][1], tl[q][2], tl[q][3], sbase + KL + boff);
                    }
#pragma unroll
                    for (int q = 0; q < 4; q++) {
                        int nfp = hh * 4 + q;
                        mma16816(Oc[2 * nfp],     a2h[kc2][0], a2h[kc2][1], a2h[kc2][2], a2h[kc2][3], th[q][0], th[q][1]);
                        mma16816(Oc[2 * nfp + 1], a2h[kc2][0], a2h[kc2][1], a2h[kc2][2], a2h[kc2][3], th[q][2], th[q][3]);
                    }
#pragma unroll
                    for (int q = 0; q < 4; q++) {
                        int nfp = hh * 4 + q;
                        mma16816(Oc[2 * nfp],     a2h[kc2][0], a2h[kc2][1], a2h[kc2][2], a2h[kc2][3], tl[q][0], tl[q][1]);
                        mma16816(Oc[2 * nfp + 1], a2h[kc2][0], a2h[kc2][1], a2h[kc2][2], a2h[kc2][3], tl[q][2], tl[q][3]);
                    }
#pragma unroll
                    for (int q = 0; q < 4; q++) {
                        int nfp = hh * 4 + q;
                        mma16816(Oc[2 * nfp],     a2l[kc2][0], a2l[kc2][1], a2l[kc2][2], a2l[kc2][3], th[q][0], th[q][1]);
                        mma16816(Oc[2 * nfp + 1], a2l[kc2][0], a2l[kc2][1], a2l[kc2][2], a2l[kc2][3], th[q][2], th[q][3]);
                    }
                }
            }
            if (pre) {
                cvt_store8(smc, NH, krow, kc0 + 32, pf[0], pf[1]);
                cvt_store8(smc, NH, krow, kc0 + 40, pf[2], pf[3]);
#pragma unroll
                for (int q = 0; q < 4; q++) pf[q] = *(const float4*)(psrc + 48 + 4 * q);
                cvt_store8(smc, NH, krow, kc0 + 48, pf[0], pf[1]);
                cvt_store8(smc, NH, krow, kc0 + 56, pf[2], pf[3]);
            }
            __syncthreads();
        }

        {
            long long rbase = (long long)b * TT + (long long)R * 64 + w * 16 + (lane >> 2);
#pragma unroll
            for (int nf = 0; nf < 16; nf++) {
                int d = nf * 8 + 2 * (lane & 3);
                atomicAdd(O + rbase * DD + d,       Oc[nf][0]);
                atomicAdd(O + rbase * DD + d + 1,   Oc[nf][1]);
                atomicAdd(O + (rbase + 8) * DD + d,     Oc[nf][2]);
                atomicAdd(O + (rbase + 8) * DD + d + 1, Oc[nf][3]);
            }
        }
    }
}

// ---------------- depthwise causal conv ----------------
__global__ __launch_bounds__(512) void conv_kernel(const float* __restrict__ z,
                                                   const float* __restrict__ w,
                                                   const float* __restrict__ bias,
                                                   float* __restrict__ mf) {
    int d = threadIdx.x;
    int t = blockIdx.x * 4 + threadIdx.y;
    int b = blockIdx.y;
    float acc = bias[d];
    int kstart = (KK - 1) - t;
    if (kstart < 0) kstart = 0;
    const float* zp = z + ((long long)b * TT + t - (KK - 1)) * DD + d;
    const float* wp = w + d;
#pragma unroll 4
    for (int k = kstart; k < KK; k++)
        acc = fmaf(zp[(long long)k * DD], wp[(long long)k * DD], acc);
    mf[((long long)b * TT + t) * DD + d] = acc;
}

// ---------------- group reduce (dual_gemm_norm) ----------------
__device__ __forceinline__ void group_reduce8(float v[8], float* red, int grp, int wig, int lane) {
#pragma unroll
    for (int k = 0; k < 8; k++) {
        float x = v[k];
#pragma unroll
        for (int o = 16; o; o >>= 1) x += __shfl_xor_sync(0xffffffffu, x, o);
        if (lane == 0) red[grp * 32 + wig * 8 + k] = x;
    }
    __syncthreads();
#pragma unroll
    for (int k = 0; k < 8; k++)
        v[k] = red[grp * 32 + k] + red[grp * 32 + 8 + k] + red[grp * 32 + 16 + k] +
               red[grp * 32 + 24 + k];
    __syncthreads();
}

__device__ __forceinline__ void matvec8(const float* Ws, const float* xg, int d, float bias,
                                        float tot[8]) {
    ull acc0 = dup2(bias), acc1 = dup2(bias), acc2 = dup2(bias), acc3 = dup2(bias);
#pragma unroll 4
    for (int j = 0; j < 128; j++) {
        ull w2 = dup2(Ws[j * 128 + d]);
        ulonglong2 x01 = *(const ulonglong2*)(xg + j * 8);
        ulonglong2 x23 = *(const ulonglong2*)(xg + j * 8 + 4);
        fma2(acc0, x01.x, w2);
        fma2(acc1, x01.y, w2);
        fma2(acc2, x23.x, w2);
        fma2(acc3, x23.y, w2);
    }
    float2 a0 = unpk(acc0), a1 = unpk(acc1), a2 = unpk(acc2), a3 = unpk(acc3);
    tot[0] = a0.x; tot[1] = a0.y; tot[2] = a1.x; tot[3] = a1.y;
    tot[4] = a2.x; tot[5] = a2.y; tot[6] = a3.x; tot[7] = a3.y;
}

#define DUAL_SMEM ((16384 + 16384 + 4096 + 128) * 4)

__global__ __launch_bounds__(512) void dual_gemm_norm(const float* __restrict__ X,
                                                      const float* __restrict__ W1,
                                                      const float* __restrict__ b1,
                                                      const float* __restrict__ W2,
                                                      const float* __restrict__ b2,
                                                      float* __restrict__ Y1,
                                                      float* __restrict__ Y2) {
    extern __shared__ float sm[];
    float* W1s = sm;
    float* W2s = sm + 16384;
    float* xp  = sm + 32768;
    float* red = sm + 36864;
    int tid = threadIdx.x, grp = tid >> 7, d = tid & 127, wig = (tid >> 5) & 3, lane = tid & 31;
    for (int i = tid; i < 16384; i += 512) { W1s[i] = W1[i]; W2s[i] = W2[i]; }
    float b1v = b1[d], b2v = b2[d];
    __syncthreads();
    long long row0 = (long long)blockIdx.x * 64 + grp * 16;
    float* xg = xp + grp * 1024;
    for (int gg = 0; gg < 16; gg += 8) {
#pragma unroll
        for (int k = 0; k < 8; k++)
            xg[d * 8 + k] = X[(row0 + gg + k) * DD + d];
        __syncthreads();
        float tot[8], v[8];
        matvec8(W1s, xg, d, b1v, tot);
#pragma unroll
        for (int k = 0; k < 8; k++) v[k] = tot[k] * tot[k];
        group_reduce8(v, red, grp, wig, lane);
#pragma unroll
        for (int k = 0; k < 8; k++)
            Y1[(row0 + gg + k) * DD + d] = __fdividef(tot[k], fmaxf(sqrtf(v[k]), 1e-8f));
        matvec8(W2s, xg, d, b2v, tot);
#pragma unroll
        for (int k = 0; k < 8; k++) v[k] = tot[k] * tot[k];
        group_reduce8(v, red, grp, wig, lane);
#pragma unroll
        for (int k = 0; k < 8; k++)
            Y2[(row0 + gg + k) * DD + d] = __fdividef(tot[k], fmaxf(sqrtf(v[k]), 1e-8f));
        __syncthreads();
    }
}

// ================== MMA epilogue ==================
// smem: A tile hi 16K | A lo 16K | W buf0 (hi 4K, lo 4K) | W buf1 (hi 4K, lo 4K) = 48K
#define E_AH 0
#define E_AL 16384
#define E_W(buf) (32768u + (uint32_t)(buf) * 8192u)
#define EPI2_SMEM 49152

__global__ __launch_bounds__(128) void epilogue_mma(
    const float* __restrict__ A0,
    const float* __restrict__ Wo, const float* __restrict__ bo,
    const float* __restrict__ Wq, const float* __restrict__ bq,
    const float* __restrict__ mf, const float* __restrict__ zin,
    const float* __restrict__ zbase, float* __restrict__ vacc,
    float* __restrict__ zc, float* __restrict__ qh, float* __restrict__ out,
    float sw, float rc, int first, int has_next) {
    extern __shared__ char smc[];
    const uint32_t sbase = smem_u32(smc);
    const int tid = threadIdx.x;
    const int lane = tid & 31, w = tid >> 5;
    const int g = lane >> 3, r = lane & 7;
    const int wrow = tid >> 3, wc0 = (tid & 7) * 16;
    const long long row0 = (long long)blockIdx.x * 64;
    const long long gA = row0 + w * 16 + (lane >> 2);
    const long long gB = gA + 8;

    // stage A tile (64x128) hi/lo
    for (int t = tid; t < 1024; t += 128) {
        int row = t >> 4, d0 = (t & 15) * 8;
        const float* src = A0 + (row0 + row) * DD + d0;
        cvt_store8o(smc, E_AH, E_AL, row, d0, *(const float4*)src, *(const float4*)(src + 4));
    }
    // preload Wo chunk0
    {
        const float* src = Wo + (long long)wrow * DD + wc0;
        cvt_store8o(smc, E_W(0), E_W(0) + 4096, wrow, wc0,
                    *(const float4*)src, *(const float4*)(src + 4));
        cvt_store8o(smc, E_W(0), E_W(0) + 4096, wrow, wc0 + 8,
                    *(const float4*)(src + 8), *(const float4*)(src + 12));
    }
    __syncthreads();

    float C[16][4];
#pragma unroll
    for (int nf = 0; nf < 16; nf++)
#pragma unroll
        for (int e = 0; e < 4; e++) C[nf][e] = 0.f;

    // ---- GEMM1: C = A @ Wo (3-pass bf16) ----
#pragma unroll 1
    for (int kc = 0; kc < 8; kc++) {
        const int cur = kc & 1;
        const uint32_t WH = E_W(cur), WL = WH + 4096;
        const bool pre = (kc < 7);
        float4 wp[4];
        if (pre) {
            const float* src = Wo + (long long)((kc + 1) * 16 + wrow) * DD + wc0;
#pragma unroll
            for (int q = 0; q < 4; q++) wp[q] = *(const float4*)(src + 4 * q);
        }
        uint32_t aoff = sw_off(w * 16 + ((g & 1) ? 8 : 0) + r, kc * 16 + ((g >> 1) ? 8 : 0));
        uint32_t ah0, ah1, ah2, ah3, al0, al1, al2, al3;
        ldsm4(ah0, ah1, ah2, ah3, sbase + E_AH + aoff);
        ldsm4(al0, al1, al2, al3, sbase + E_AL + aoff);
#pragma unroll
        for (int hh = 0; hh < 2; hh++) {
            uint32_t th[4][4], tl[4][4];
#pragma unroll
            for (int q = 0; q < 4; q++) {
                int nfp = hh * 4 + q;
                uint32_t boff = sw_off(((g & 1) ? 8 : 0) + r, nfp * 16 + ((g >> 1) ? 8 : 0));
                ldsm4t(th[q][0], th[q][1], th[q][2], th[q][3], sbase + WH + boff);
                ldsm4t(tl[q][0], tl[q][1], tl[q][2], tl[q][3], sbase + WL + boff);
            }
#pragma unroll
            for (int q = 0; q < 4; q++) {
                int nfp = hh * 4 + q;
                mma16816(C[2 * nfp],     ah0, ah1, ah2, ah3, th[q][0], th[q][1]);
                mma16816(C[2 * nfp + 1], ah0, ah1, ah2, ah3, th[q][2], th[q][3]);
            }
#pragma unroll
            for (int q = 0; q < 4; q++) {
                int nfp = hh * 4 + q;
                mma16816(C[2 * nfp],     ah0, ah1, ah2, ah3, tl[q][0], tl[q][1]);
                mma16816(C[2 * nfp + 1], ah0, ah1, ah2, ah3, tl[q][2], tl[q][3]);
            }
#pragma unroll
            for (int q = 0; q < 4; q++) {
                int nfp = hh * 4 + q;
                mma16816(C[2 * nfp],     al0, al1, al2, al3, th[q][0], th[q][1]);
                mma16816(C[2 * nfp + 1], al0, al1, al2, al3, th[q][2], th[q][3]);
            }
        }
        if (pre) {
            const uint32_t NW = E_W(1 - cur);
            cvt_store8o(smc, NW, NW + 4096, wrow, wc0, wp[0], wp[1]);
            cvt_store8o(smc, NW, NW + 4096, wrow, wc0 + 8, wp[2], wp[3]);
        }
        __syncthreads();
    }

    // ---- bias + mf, tangent dot ----
    float dotA = 0.f, dotB = 0.f;
#pragma unroll
    for (int nf = 0; nf < 16; nf++) {
        int col = nf * 8 + 2 * (lane & 3);
        float2 bov = *(const float2*)(bo + col);
        float2 mA = *(const float2*)(mf + gA * DD + col);
        float2 mB = *(const float2*)(mf + gB * DD + col);
        C[nf][0] += bov.x + mA.x; C[nf][1] += bov.y + mA.y;
        C[nf][2] += bov.x + mB.x; C[nf][3] += bov.y + mB.y;
        float2 zA = *(const float2*)(zin + gA * DD + col);
        float2 zB = *(const float2*)(zin + gB * DD + col);
        dotA += C[nf][0] * zA.x + C[nf][1] * zA.y;
        dotB += C[nf][2] * zB.x + C[nf][3] * zB.y;
    }
    dotA += __shfl_xor_sync(0xffffffffu, dotA, 1);
    dotA += __shfl_xor_sync(0xffffffffu, dotA, 2);
    dotB += __shfl_xor_sync(0xffffffffu, dotB, 1);
    dotB += __shfl_xor_sync(0xffffffffu, dotB, 2);

    // ---- proj, vacc update, zn sumsq (proj kept in C) ----
    float ssA = 0.f, ssB = 0.f;
#pragma unroll
    for (int nf = 0; nf < 16; nf++) {
        int col = nf * 8 + 2 * (lane & 3);
        float2 zA = *(const float2*)(zin + gA * DD + col);
        float2 zB = *(const float2*)(zin + gB * DD + col);
        C[nf][0] -= dotA * zA.x; C[nf][1] -= dotA * zA.y;
        C[nf][2] -= dotB * zB.x; C[nf][3] -= dotB * zB.y;
        float2* vA = (float2*)(vacc + gA * DD + col);
        float2* vB = (float2*)(vacc + gB * DD + col);
        float2 vpA = first ? make_float2(0.f, 0.f) : *vA;
        float2 vpB = first ? make_float2(0.f, 0.f) : *vB;
        float2 vnA = make_float2(vpA.x + sw * C[nf][0], vpA.y + sw * C[nf][1]);
        float2 vnB = make_float2(vpB.x + sw * C[nf][2], vpB.y + sw * C[nf][3]);
        *vA = vnA; *vB = vnB;
        float2 zbA = *(const float2*)(zbase + gA * DD + col);
        float2 zbB = *(const float2*)(zbase + gB * DD + col);
        if (has_next) {
            float a0v = zbA.x + rc * C[nf][0], a1v = zbA.y + rc * C[nf][1];
            float b0v = zbB.x + rc * C[nf][2], b1v = zbB.y + rc * C[nf][3];
            ssA += a0v * a0v + a1v * a1v;
            ssB += b0v * b0v + b1v * b1v;
        } else {
            float a0v = zbA.x + vnA.x, a1v = zbA.y + vnA.y;
            float b0v = zbB.x + vnB.x, b1v = zbB.y + vnB.y;
            ssA += a0v * a0v + a1v * a1v;
            ssB += b0v * b0v + b1v * b1v;
            C[nf][0] = a0v; C[nf][1] = a1v; C[nf][2] = b0v; C[nf][3] = b1v;
        }
    }
    ssA += __shfl_xor_sync(0xffffffffu, ssA, 1);
    ssA += __shfl_xor_sync(0xffffffffu, ssA, 2);
    ssB += __shfl_xor_sync(0xffffffffu, ssB, 1);
    ssB += __shfl_xor_sync(0xffffffffu, ssB, 2);
    float invA = __fdividef(1.f, fmaxf(sqrtf(ssA), 1e-8f));
    float invB = __fdividef(1.f, fmaxf(sqrtf(ssB), 1e-8f));

    if (!has_next) {
#pragma unroll
        for (int nf = 0; nf < 16; nf++) {
            int col = nf * 8 + 2 * (lane & 3);
            *(float2*)(out + gA * DD + col) = make_float2(C[nf][0] * invA, C[nf][1] * invA);
            *(float2*)(out + gB * DD + col) = make_float2(C[nf][2] * invB, C[nf][3] * invB);
        }
        return;
    }

    // ---- z0 = norm(zbase + rc*proj): store zc + restage into A tile (bf16 hi/lo) ----
    // preload Wq chunk0 into buf0 (safe: GEMM1 fully done after last sync)
    {
        const float* src = Wq + (long long)wrow * DD + wc0;
        cvt_store8o(smc, E_W(0), E_W(0) + 4096, wrow, wc0,
                    *(const float4*)src, *(const float4*)(src + 4));
        cvt_store8o(smc, E_W(0), E_W(0) + 4096, wrow, wc0 + 8,
                    *(const float4*)(src + 8), *(const float4*)(src + 12));
    }
    const int rowA = w * 16 + (lane >> 2), rowB = rowA + 8;
#pragma unroll
    for (int nf = 0; nf < 16; nf++) {
        int col = nf * 8 + 2 * (lane & 3);
        float2 zbA = *(const float2*)(zbase + gA * DD + col);
        float2 zbB = *(const float2*)(zbase + gB * DD + col);
        float a0v = (zbA.x + rc * C[nf][0]) * invA, a1v = (zbA.y + rc * C[nf][1]) * invA;
        float b0v = (zbB.x + rc * C[nf][2]) * invB, b1v = (zbB.y + rc * C[nf][3]) * invB;
        *(float2*)(zc + gA * DD + col) = make_float2(a0v, a1v);
        *(float2*)(zc + gB * DD + col) = make_float2(b0v, b1v);
        uint32_t h, l;
        bsplit2(a0v, a1v, h, l);
        *(uint32_t*)(smc + E_AH + sw_off(rowA, col)) = h;
        *(uint32_t*)(smc + E_AL + sw_off(rowA, col)) = l;
        bsplit2(b0v, b1v, h, l);
        *(uint32_t*)(smc + E_AH + sw_off(rowB, col)) = h;
        *(uint32_t*)(smc + E_AL + sw_off(rowB, col)) = l;
    }
    __syncthreads();

    // ---- GEMM2: C = z0 @ Wq (3-pass bf16) ----
#pragma unroll
    for (int nf = 0; nf < 16; nf++)
#pragma unroll
        for (int e = 0; e < 4; e++) C[nf][e] = 0.f;
#pragma unroll 1
    for (int kc = 0; kc < 8; kc++) {
        const int cur = kc & 1;
        const uint32_t WH = E_W(cur), WL = WH + 4096;
        const bool pre = (kc < 7);
        float4 wp[4];
        if (pre) {
            const float* src = Wq + (long long)((kc + 1) * 16 + wrow) * DD + wc0;
#pragma unroll
            for (int q = 0; q < 4; q++) wp[q] = *(const float4*)(src + 4 * q);
        }
        uint32_t aoff = sw_off(w * 16 + ((g & 1) ? 8 : 0) + r, kc * 16 + ((g >> 1) ? 8 : 0));
        uint32_t ah0, ah1, ah2, ah3, al0, al1, al2, al3;
        ldsm4(ah0, ah1, ah2, ah3, sbase + E_AH + aoff);
        ldsm4(al0, al1, al2, al3, sbase + E_AL + aoff);
#pragma unroll
        for (int hh = 0; hh < 2; hh++) {
            uint32_t th[4][4], tl[4][4];
#pragma unroll
            for (int q = 0; q < 4; q++) {
                int nfp = hh * 4 + q;
                uint32_t boff = sw_off(((g & 1) ? 8 : 0) + r, nfp * 16 + ((g >> 1) ? 8 : 0));
                ldsm4t(th[q][0], th[q][1], th[q][2], th[q][3], sbase + WH + boff);
                ldsm4t(tl[q][0], tl[q][1], tl[q][2], tl[q][3], sbase + WL + boff);
            }
#pragma unroll
            for (int q = 0; q < 4; q++) {
                int nfp = hh * 4 + q;
                mma16816(C[2 * nfp],     ah0, ah1, ah2, ah3, th[q][0], th[q][1]);
                mma16816(C[2 * nfp + 1], ah0, ah1, ah2, ah3, th[q][2], th[q][3]);
            }
#pragma unroll
            for (int q = 0; q < 4; q++) {
                int nfp = hh * 4 + q;
                mma16816(C[2 * nfp],     ah0, ah1, ah2, ah3, tl[q][0], tl[q][1]);
                mma16816(C[2 * nfp + 1], ah0, ah1, ah2, ah3, tl[q][2], tl[q][3]);
            }
#pragma unroll
            for (int q = 0; q < 4; q++) {
                int nfp = hh * 4 + q;
                mma16816(C[2 * nfp],     al0, al1, al2, al3, th[q][0], th[q][1]);
                mma16816(C[2 * nfp + 1], al0, al1, al2, al3, th[q][2], th[q][3]);
            }
        }
        if (pre) {
            const uint32_t NW = E_W(1 - cur);
            cvt_store8o(smc, NW, NW + 4096, wrow, wc0, wp[0], wp[1]);
            cvt_store8o(smc, NW, NW + 4096, wrow, wc0 + 8, wp[2], wp[3]);
        }
        __syncthreads();
    }

    // ---- qh = norm(C + bq) ----
    float qsA = 0.f, qsB = 0.f;
#pragma unroll
    for (int nf = 0; nf < 16; nf++) {
        int col = nf * 8 + 2 * (lane & 3);
        float2 bqv = *(const float2*)(bq + col);
        C[nf][0] += bqv.x; C[nf][1] += bqv.y;
        C[nf][2] += bqv.x; C[nf][3] += bqv.y;
        qsA += C[nf][0] * C[nf][0] + C[nf][1] * C[nf][1];
        qsB += C[nf][2] * C[nf][2] + C[nf][3] * C[nf][3];
    }
    qsA += __shfl_xor_sync(0xffffffffu, qsA, 1);
    qsA += __shfl_xor_sync(0xffffffffu, qsA, 2);
    qsB += __shfl_xor_sync(0xffffffffu, qsB, 1);
    qsB += __shfl_xor_sync(0xffffffffu, qsB, 2);
    float qiA = __fdividef(1.f, fmaxf(sqrtf(qsA), 1e-8f));
    float qiB = __fdividef(1.f, fmaxf(sqrtf(qsB), 1e-8f));
#pragma unroll
    for (int nf = 0; nf < 16; nf++) {
        int col = nf * 8 + 2 * (lane & 3);
        *(float2*)(qh + gA * DD + col) = make_float2(C[nf][0] * qiA, C[nf][1] * qiA);
        *(float2*)(qh + gB * DD + col) = make_float2(C[nf][2] * qiB, C[nf][3] * qiB);
    }
}

// ---------------- launch ----------------
extern "C" void kernel_launch(void* const* d_in, const int* in_sizes, int n_in,
                              void* d_out, int out_size) {
    const float* z  = (const float*)d_in[0];
    const float* ck = (const float*)d_in[1];
    const float* cb = (const float*)d_in[2];
    const float* Wq = (const float*)d_in[3];
    const float* bq = (const float*)d_in[4];
    const float* Wk = (const float*)d_in[5];
    const float* bk = (const float*)d_in[6];
    const float* Wo = (const float*)d_in[7];
    const float* bo = (const float*)d_in[8];
    float* out = (float*)d_out;

    float *kh, *mf, *qh, *a0, *zc, *va;
    cudaGetSymbolAddress((void**)&kh, g_kh);
    cudaGetSymbolAddress((void**)&mf, g_mf);
    cudaGetSymbolAddress((void**)&qh, g_qh);
    cudaGetSymbolAddress((void**)&a0, g_a0);
    cudaGetSymbolAddress((void**)&zc, g_zc);
    cudaGetSymbolAddress((void**)&va, g_va);

    cudaFuncSetAttribute(dual_gemm_norm, cudaFuncAttributeMaxDynamicSharedMemorySize, DUAL_SMEM);
    cudaFuncSetAttribute(epilogue_mma, cudaFuncAttributeMaxDynamicSharedMemorySize, EPI2_SMEM);
    cudaFuncSetAttribute(attn_kernel, cudaFuncAttributeMaxDynamicSharedMemorySize, ATTN_SMEM);

    conv_kernel<<<dim3(TT / 4, BB), dim3(128, 4)>>>(z, ck, cb, mf);
    dual_gemm_norm<<<BT / 64, 512, DUAL_SMEM>>>(z, Wk, bk, Wq, bq, kh, qh);

    const float sws[4] = {1.f / 6.f, 2.f / 6.f, 2.f / 6.f, 1.f / 6.f};
    const float rcs[4] = {0.5f, 0.5f, 1.0f, 0.f};
    const float* zcur = z;
    for (int s = 0; s < 4; s++) {
        cudaMemsetAsync(a0, 0, (size_t)BT * DD * sizeof(float));
        attn_kernel<<<dim3(32, 9), 128, ATTN_SMEM>>>(qh, kh, a0);
        epilogue_mma<<<BT / 64, 128, EPI2_SMEM>>>(a0, Wo, bo, Wq, bq,
                                                  mf, zcur, z, va, zc, qh, out,
                                                  sws[s], rcs[s], s == 0 ? 1 : 0,
                                                  s < 3 ? 1 : 0);
        zcur = zc;
    }
}

// round 9
// speedup vs baseline: 3.3709x; 1.0896x over previous
#include <cuda_runtime.h>
#include <cstdint>

#define BB 2
#define TT 4096
#define DD 128
#define KK 256
#define BT (BB * TT)

// ---------------- scratch ----------------
__device__ float g_kh[BT * DD];
__device__ float g_mf[BT * DD];
__device__ float g_qh[BT * DD];
__device__ float g_a0[BT * DD];
__device__ float g_zc[BT * DD];
__device__ float g_va[BT * DD];

// ================= helpers =================
typedef unsigned long long ull;
__device__ __forceinline__ uint32_t smem_u32(const void* p) {
    uint32_t a;
    asm("{ .reg .u64 t; cvta.to.shared.u64 t, %1; cvt.u32.u64 %0, t; }" : "=r"(a) : "l"(p));
    return a;
}
__device__ __forceinline__ void ldsm4(uint32_t& r0, uint32_t& r1, uint32_t& r2, uint32_t& r3,
                                      uint32_t addr) {
    asm volatile("ldmatrix.sync.aligned.m8n8.x4.shared.b16 {%0,%1,%2,%3}, [%4];"
                 : "=r"(r0), "=r"(r1), "=r"(r2), "=r"(r3) : "r"(addr));
}
__device__ __forceinline__ void ldsm4t(uint32_t& r0, uint32_t& r1, uint32_t& r2, uint32_t& r3,
                                       uint32_t addr) {
    asm volatile("ldmatrix.sync.aligned.m8n8.x4.trans.shared.b16 {%0,%1,%2,%3}, [%4];"
                 : "=r"(r0), "=r"(r1), "=r"(r2), "=r"(r3) : "r"(addr));
}
__device__ __forceinline__ void mma16816(float* c, uint32_t a0, uint32_t a1, uint32_t a2,
                                         uint32_t a3, uint32_t b0, uint32_t b1) {
    asm volatile(
        "mma.sync.aligned.m16n8k16.row.col.f32.bf16.bf16.f32 "
        "{%0,%1,%2,%3}, {%4,%5,%6,%7}, {%8,%9}, {%0,%1,%2,%3};"
        : "+f"(c[0]), "+f"(c[1]), "+f"(c[2]), "+f"(c[3])
        : "r"(a0), "r"(a1), "r"(a2), "r"(a3), "r"(b0), "r"(b1));
}
__device__ __forceinline__ void bsplit2(float x0, float x1, uint32_t& h, uint32_t& l) {
    uint16_t h0, h1, l0, l1;
    asm("cvt.rn.bf16.f32 %0, %1;" : "=h"(h0) : "f"(x0));
    asm("cvt.rn.bf16.f32 %0, %1;" : "=h"(h1) : "f"(x1));
    float f0 = __uint_as_float((uint32_t)h0 << 16);
    float f1 = __uint_as_float((uint32_t)h1 << 16);
    asm("cvt.rn.bf16.f32 %0, %1;" : "=h"(l0) : "f"(x0 - f0));
    asm("cvt.rn.bf16.f32 %0, %1;" : "=h"(l1) : "f"(x1 - f1));
    h = (uint32_t)h0 | ((uint32_t)h1 << 16);
    l = (uint32_t)l0 | ((uint32_t)l1 << 16);
}
__device__ __forceinline__ uint32_t sw_off(int row, int d) {
    return (uint32_t)(row * 256 + ((((d >> 3) ^ (row & 7)) & 15) << 4) + (d & 7) * 2);
}
__device__ __forceinline__ float sinpoly(float x) {
    float x2 = x * x;
    float pp = fmaf(x2, 2.7557319e-06f, -1.9841270e-04f);
    pp = fmaf(x2, pp, 8.3333333e-03f);
    pp = fmaf(x2, pp, -1.6666667e-01f);
    return fmaf(x * x2, pp, x);
}
__device__ __forceinline__ ull dup2(float x) {
    ull r; asm("mov.b64 %0, {%1, %1};" : "=l"(r) : "f"(x)); return r;
}
__device__ __forceinline__ ull pack2(float x, float y) {
    ull r; asm("mov.b64 %0, {%1, %2};" : "=l"(r) : "f"(x), "f"(y)); return r;
}
__device__ __forceinline__ void fma2(ull& d, ull a, ull b) {
    asm("fma.rn.f32x2 %0, %1, %2, %0;" : "+l"(d) : "l"(a), "l"(b));
}
__device__ __forceinline__ float2 unpk(ull v) {
    float2 r; asm("mov.b64 {%0, %1}, %2;" : "=f"(r.x), "=f"(r.y) : "l"(v)); return r;
}

__device__ __forceinline__ void cvt_store8o(char* smcp, uint32_t hoff, uint32_t loff,
                                            int row, int col, float4 a, float4 b) {
    uint32_t hw[4], lw[4];
    bsplit2(a.x, a.y, hw[0], lw[0]);
    bsplit2(a.z, a.w, hw[1], lw[1]);
    bsplit2(b.x, b.y, hw[2], lw[2]);
    bsplit2(b.z, b.w, hw[3], lw[3]);
    uint32_t off = sw_off(row, col);
    *(uint4*)(smcp + hoff + off) = make_uint4(hw[0], hw[1], hw[2], hw[3]);
    *(uint4*)(smcp + loff + off) = make_uint4(lw[0], lw[1], lw[2], lw[3]);
}

// attn smem: Qhi 16K | Qlo 16K | K double-buffered (hi 16K + lo 16K) x2 = 96KB
#define QH_OFF 0
#define QL_OFF 16384
#define KBASE_OFF 32768
#define ATTN_SMEM 98304

__device__ __forceinline__ void cvt_store8(char* smcp, uint32_t hoff, int krow, int col,
                                           float4 a, float4 b) {
    cvt_store8o(smcp, hoff, hoff + 16384, krow, col, a, b);
}

// ---------------- causal sin-attention: M=64 tile, 128 threads, 2 CTAs/SM ----------------
__global__ __launch_bounds__(128, 2) void attn_kernel(const float* __restrict__ Q,
                                                      const float* __restrict__ Kh,
                                                      float* __restrict__ O) {
    extern __shared__ char smc[];
    const uint32_t sbase = smem_u32(smc);
    const int tid = threadIdx.x;
    const int lane = tid & 31, w = tid >> 5;
    const int P = blockIdx.x, split = blockIdx.y;
    const int g = lane >> 3, r = lane & 7;
    const int krow = tid >> 1, kc0 = (tid & 1) * 64;
    const int lo = (130 * split) / 9, hi = (130 * (split + 1)) / 9;

    int c = 0;
    for (int sp = 0; sp < 4; sp++) {
        const int b = sp >> 1;
        const int R = (sp & 1) ? (63 - P) : P;
        const int n = R + 1;
        int s_lo = lo - c; if (s_lo < 0) s_lo = 0;
        int s_hi = hi - c; if (s_hi > n) s_hi = n;
        c += n;
        if (s_lo >= s_hi) continue;

        const float* Qb = Q + (long long)b * TT * DD;
        const float* Kb = Kh + (long long)b * TT * DD;

        __syncthreads();
        for (int t = tid; t < 1024; t += 128) {
            int row = t >> 4, d0 = (t & 15) * 8;
            const float* src = Qb + ((long long)R * 64 + row) * DD + d0;
            cvt_store8o(smc, QH_OFF, QL_OFF, row, d0,
                        *(const float4*)src, *(const float4*)(src + 4));
        }
        {
            const float* src = Kb + ((long long)s_lo * 64 + krow) * DD + kc0;
#pragma unroll
            for (int q = 0; q < 8; q++) {
                float4 a = *(const float4*)(src + 8 * q);
                float4 bb = *(const float4*)(src + 8 * q + 4);
                cvt_store8(smc, KBASE_OFF, krow, kc0 + 8 * q, a, bb);
            }
        }
        float Oc[16][4];
#pragma unroll
        for (int nf = 0; nf < 16; nf++)
#pragma unroll
            for (int e = 0; e < 4; e++) Oc[nf][e] = 0.f;
        __syncthreads();

        // ---- hoist Q A-frags into registers (constant over s-loop) ----
        uint32_t qah[8][4], qal[8][4];
#pragma unroll
        for (int kc = 0; kc < 8; kc++) {
            uint32_t aoff = sw_off(w * 16 + ((g & 1) ? 8 : 0) + r, kc * 16 + ((g >> 1) ? 8 : 0));
            ldsm4(qah[kc][0], qah[kc][1], qah[kc][2], qah[kc][3], sbase + QH_OFF + aoff);
            ldsm4(qal[kc][0], qal[kc][1], qal[kc][2], qal[kc][3], sbase + QL_OFF + aoff);
        }

        for (int sb = s_lo; sb < s_hi; sb++) {
            const int cur = (sb - s_lo) & 1;
            const uint32_t KH = KBASE_OFF + (uint32_t)cur * 32768;
            const uint32_t KL = KH + 16384;
            const bool pre = (sb + 1 < s_hi);
            const uint32_t NH = KBASE_OFF + (uint32_t)(1 - cur) * 32768;
            const float* psrc = Kb + ((long long)(sb + 1) * 64 + krow) * DD + kc0;
            float4 pf[4];
            if (pre) {
#pragma unroll
                for (int q = 0; q < 4; q++) pf[q] = *(const float4*)(psrc + 4 * q);
            }

            // ---- MMA1: C = Q . K^T (3-pass, Q frags in regs) ----
            float C[8][4];
#pragma unroll
            for (int nf = 0; nf < 8; nf++)
#pragma unroll
                for (int e = 0; e < 4; e++) C[nf][e] = 0.f;
#pragma unroll
            for (int kc = 0; kc < 8; kc++) {
                int d0 = kc * 16;
                uint32_t bh[4][4], bl[4][4];
#pragma unroll
                for (int nfp = 0; nfp < 4; nfp++) {
                    uint32_t boff = sw_off(nfp * 16 + ((g >> 1) ? 8 : 0) + r,
                                           d0 + ((g & 1) ? 8 : 0));
                    ldsm4(bh[nfp][0], bh[nfp][1], bh[nfp][2], bh[nfp][3], sbase + KH + boff);
                    ldsm4(bl[nfp][0], bl[nfp][1], bl[nfp][2], bl[nfp][3], sbase + KL + boff);
                }
#pragma unroll
                for (int nfp = 0; nfp < 4; nfp++) {
                    mma16816(C[2 * nfp],     qah[kc][0], qah[kc][1], qah[kc][2], qah[kc][3], bh[nfp][0], bh[nfp][1]);
                    mma16816(C[2 * nfp + 1], qah[kc][0], qah[kc][1], qah[kc][2], qah[kc][3], bh[nfp][2], bh[nfp][3]);
                }
#pragma unroll
                for (int nfp = 0; nfp < 4; nfp++) {
                    mma16816(C[2 * nfp],     qah[kc][0], qah[kc][1], qah[kc][2], qah[kc][3], bl[nfp][0], bl[nfp][1]);
                    mma16816(C[2 * nfp + 1], qah[kc][0], qah[kc][1], qah[kc][2], qah[kc][3], bl[nfp][2], bl[nfp][3]);
                }
#pragma unroll
                for (int nfp = 0; nfp < 4; nfp++) {
                    mma16816(C[2 * nfp],     qal[kc][0], qal[kc][1], qal[kc][2], qal[kc][3], bh[nfp][0], bh[nfp][1]);
                    mma16816(C[2 * nfp + 1], qal[kc][0], qal[kc][1], qal[kc][2], qal[kc][3], bh[nfp][2], bh[nfp][3]);
                }
            }
            if (pre) {
                cvt_store8(smc, NH, krow, kc0,     pf[0], pf[1]);
                cvt_store8(smc, NH, krow, kc0 + 8, pf[2], pf[3]);
#pragma unroll
                for (int q = 0; q < 4; q++) pf[q] = *(const float4*)(psrc + 16 + 4 * q);
            }

            // ---- sin + causal mask + repack ----
            uint32_t a2h[4][4], a2l[4][4];
            const int ig = R * 64 + w * 16 + (lane >> 2);
#pragma unroll
            for (int nf = 0; nf < 8; nf++) {
                int jb = sb * 64 + nf * 8 + 2 * (lane & 3);
                float s0 = sinpoly(C[nf][0]); if (jb > ig) s0 = 0.f;
                float s1 = sinpoly(C[nf][1]); if (jb + 1 > ig) s1 = 0.f;
                float s2 = sinpoly(C[nf][2]); if (jb > ig + 8) s2 = 0.f;
                float s3 = sinpoly(C[nf][3]); if (jb + 1 > ig + 8) s3 = 0.f;
                int kc2 = nf >> 1, hk = (nf & 1) ? 2 : 0;
                bsplit2(s0, s1, a2h[kc2][hk], a2l[kc2][hk]);
                bsplit2(s2, s3, a2h[kc2][hk + 1], a2l[kc2][hk + 1]);
            }
            if (pre) {
                cvt_store8(smc, NH, krow, kc0 + 16, pf[0], pf[1]);
                cvt_store8(smc, NH, krow, kc0 + 24, pf[2], pf[3]);
#pragma unroll
                for (int q = 0; q < 4; q++) pf[q] = *(const float4*)(psrc + 32 + 4 * q);
            }

            // ---- MMA2: O += S . K (3-pass, pass-outer over nfp-halves) ----
#pragma unroll
            for (int kc2 = 0; kc2 < 4; kc2++) {
                int j0 = kc2 * 16;
#pragma unroll
                for (int hh = 0; hh < 2; hh++) {
                    uint32_t th[4][4], tl[4][4];
#pragma unroll
                    for (int q = 0; q < 4; q++) {
                        int nfp = hh * 4 + q;
                        uint32_t boff = sw_off(j0 + ((g & 1) ? 8 : 0) + r,
                                               nfp * 16 + ((g >> 1) ? 8 : 0));
                        ldsm4t(th[q][0], th[q][1], th[q][2], th[q][3], sbase + KH + boff);
                        ldsm4t(tl[q][0], tl[q][1], tl[q][2], tl[q][3], sbase + KL + boff);
                    }
#pragma unroll
                    for (int q = 0; q < 4; q++) {
                        int nfp = hh * 4 + q;
                        mma16816(Oc[2 * nfp],     a2h[kc2][0], a2h[kc2][1], a2h[kc2][2], a2h[kc2][3], th[q][0], th[q][1]);
                        mma16816(Oc[2 * nfp + 1], a2h[kc2][0], a2h[kc2][1], a2h[kc2][2], a2h[kc2][3], th[q][2], th[q][3]);
                    }
#pragma unroll
                    for (int q = 0; q < 4; q++) {
                        int nfp = hh * 4 + q;
                        mma16816(Oc[2 * nfp],     a2h[kc2][0], a2h[kc2][1], a2h[kc2][2], a2h[kc2][3], tl[q][0], tl[q][1]);
                        mma16816(Oc[2 * nfp + 1], a2h[kc2][0], a2h[kc2][1], a2h[kc2][2], a2h[kc2][3], tl[q][2], tl[q][3]);
                    }
#pragma unroll
                    for (int q = 0; q < 4; q++) {
                        int nfp = hh * 4 + q;
                        mma16816(Oc[2 * nfp],     a2l[kc2][0], a2l[kc2][1], a2l[kc2][2], a2l[kc2][3], th[q][0], th[q][1]);
                        mma16816(Oc[2 * nfp + 1], a2l[kc2][0], a2l[kc2][1], a2l[kc2][2], a2l[kc2][3], th[q][2], th[q][3]);
                    }
                }
            }
            if (pre) {
                cvt_store8(smc, NH, krow, kc0 + 32, pf[0], pf[1]);
                cvt_store8(smc, NH, krow, kc0 + 40, pf[2], pf[3]);
#pragma unroll
                for (int q = 0; q < 4; q++) pf[q] = *(const float4*)(psrc + 48 + 4 * q);
                cvt_store8(smc, NH, krow, kc0 + 48, pf[0], pf[1]);
                cvt_store8(smc, NH, krow, kc0 + 56, pf[2], pf[3]);
            }
            __syncthreads();
        }

        {
            long long rbase = (long long)b * TT + (long long)R * 64 + w * 16 + (lane >> 2);
#pragma unroll
            for (int nf = 0; nf < 16; nf++) {
                int d = nf * 8 + 2 * (lane & 3);
                atomicAdd(O + rbase * DD + d,       Oc[nf][0]);
                atomicAdd(O + rbase * DD + d + 1,   Oc[nf][1]);
                atomicAdd(O + (rbase + 8) * DD + d,     Oc[nf][2]);
                atomicAdd(O + (rbase + 8) * DD + d + 1, Oc[nf][3]);
            }
        }
    }
}

// ---------------- depthwise causal conv (FFMA2, d-pairs) ----------------
__global__ __launch_bounds__(512) void conv_kernel(const float* __restrict__ z,
                                                   const float* __restrict__ w,
                                                   const float* __restrict__ bias,
                                                   float* __restrict__ mf) {
    int d0 = threadIdx.x * 2;
    int t = blockIdx.x * 8 + threadIdx.y;
    int b = blockIdx.y;
    float2 bv = *(const float2*)(bias + d0);
    ull acc = pack2(bv.x, bv.y);
    int kstart = (KK - 1) - t;
    if (kstart < 0) kstart = 0;
    const float* zp = z + ((long long)b * TT + t - (KK - 1)) * DD + d0;
    const float* wp = w + d0;
#pragma unroll 4
    for (int k = kstart; k < KK; k++)
        fma2(acc, *(const ull*)(zp + (long long)k * DD), *(const ull*)(wp + (long long)k * DD));
    float2 res = unpk(acc);
    *(float2*)(mf + ((long long)b * TT + t) * DD + d0) = res;
}

// ---------------- group reduce (dual_gemm_norm) ----------------
__device__ __forceinline__ void group_reduce8(float v[8], float* red, int grp, int wig, int lane) {
#pragma unroll
    for (int k = 0; k < 8; k++) {
        float x = v[k];
#pragma unroll
        for (int o = 16; o; o >>= 1) x += __shfl_xor_sync(0xffffffffu, x, o);
        if (lane == 0) red[grp * 32 + wig * 8 + k] = x;
    }
    __syncthreads();
#pragma unroll
    for (int k = 0; k < 8; k++)
        v[k] = red[grp * 32 + k] + red[grp * 32 + 8 + k] + red[grp * 32 + 16 + k] +
               red[grp * 32 + 24 + k];
    __syncthreads();
}

__device__ __forceinline__ void matvec8(const float* Ws, const float* xg, int d, float bias,
                                        float tot[8]) {
    ull acc0 = dup2(bias), acc1 = dup2(bias), acc2 = dup2(bias), acc3 = dup2(bias);
#pragma unroll 4
    for (int j = 0; j < 128; j++) {
        ull w2 = dup2(Ws[j * 128 + d]);
        ulonglong2 x01 = *(const ulonglong2*)(xg + j * 8);
        ulonglong2 x23 = *(const ulonglong2*)(xg + j * 8 + 4);
        fma2(acc0, x01.x, w2);
        fma2(acc1, x01.y, w2);
        fma2(acc2, x23.x, w2);
        fma2(acc3, x23.y, w2);
    }
    float2 a0 = unpk(acc0), a1 = unpk(acc1), a2 = unpk(acc2), a3 = unpk(acc3);
    tot[0] = a0.x; tot[1] = a0.y; tot[2] = a1.x; tot[3] = a1.y;
    tot[4] = a2.x; tot[5] = a2.y; tot[6] = a3.x; tot[7] = a3.y;
}

#define DUAL_SMEM ((16384 + 16384 + 4096 + 128) * 4)

__global__ __launch_bounds__(512) void dual_gemm_norm(const float* __restrict__ X,
                                                      const float* __restrict__ W1,
                                                      const float* __restrict__ b1,
                                                      const float* __restrict__ W2,
                                                      const float* __restrict__ b2,
                                                      float* __restrict__ Y1,
                                                      float* __restrict__ Y2) {
    extern __shared__ float sm[];
    float* W1s = sm;
    float* W2s = sm + 16384;
    float* xp  = sm + 32768;
    float* red = sm + 36864;
    int tid = threadIdx.x, grp = tid >> 7, d = tid & 127, wig = (tid >> 5) & 3, lane = tid & 31;
    for (int i = tid; i < 16384; i += 512) { W1s[i] = W1[i]; W2s[i] = W2[i]; }
    float b1v = b1[d], b2v = b2[d];
    __syncthreads();
    long long row0 = (long long)blockIdx.x * 64 + grp * 16;
    float* xg = xp + grp * 1024;
    for (int gg = 0; gg < 16; gg += 8) {
#pragma unroll
        for (int k = 0; k < 8; k++)
            xg[d * 8 + k] = X[(row0 + gg + k) * DD + d];
        __syncthreads();
        float tot[8], v[8];
        matvec8(W1s, xg, d, b1v, tot);
#pragma unroll
        for (int k = 0; k < 8; k++) v[k] = tot[k] * tot[k];
        group_reduce8(v, red, grp, wig, lane);
#pragma unroll
        for (int k = 0; k < 8; k++)
            Y1[(row0 + gg + k) * DD + d] = __fdividef(tot[k], fmaxf(sqrtf(v[k]), 1e-8f));
        matvec8(W2s, xg, d, b2v, tot);
#pragma unroll
        for (int k = 0; k < 8; k++) v[k] = tot[k] * tot[k];
        group_reduce8(v, red, grp, wig, lane);
#pragma unroll
        for (int k = 0; k < 8; k++)
            Y2[(row0 + gg + k) * DD + d] = __fdividef(tot[k], fmaxf(sqrtf(v[k]), 1e-8f));
        __syncthreads();
    }
}

// ================== MMA epilogue (256 threads, N-split) ==================
// smem: A hi 16K | A lo 16K | W buf0 8K | W buf1 8K | red 512B
#define E_AH 0
#define E_AL 16384
#define E_W(buf) (32768u + (uint32_t)(buf) * 8192u)
#define E_RED 49152
#define EPI2_SMEM 49664

__global__ __launch_bounds__(256) void epilogue_mma(
    const float* __restrict__ A0,
    const float* __restrict__ Wo, const float* __restrict__ bo,
    const float* __restrict__ Wq, const float* __restrict__ bq,
    const float* __restrict__ mf, const float* __restrict__ zin,
    const float* __restrict__ zbase, float* __restrict__ vacc,
    float* __restrict__ zc, float* __restrict__ qh, float* __restrict__ out,
    float sw, float rc, int first, int has_next) {
    extern __shared__ char smc[];
    const uint32_t sbase = smem_u32(smc);
    float* red = (float*)(smc + E_RED);
    const int tid = threadIdx.x;
    const int lane = tid & 31, w = tid >> 5;
    const int wr = w & 3, whalf = w >> 2;
    const int ncol0 = whalf * 64;
    const int g = lane >> 3, r = lane & 7;
    const int wrow = tid >> 4, wc0 = (tid & 15) * 8;
    const long long row0 = (long long)blockIdx.x * 64;
    const int rowL = wr * 16 + (lane >> 2);
    const long long gA = row0 + rowL;
    const long long gB = gA + 8;

    // stage A tile (64x128) hi/lo
    for (int t = tid; t < 1024; t += 256) {
        int row = t >> 4, d0 = (t & 15) * 8;
        const float* src = A0 + (row0 + row) * DD + d0;
        cvt_store8o(smc, E_AH, E_AL, row, d0, *(const float4*)src, *(const float4*)(src + 4));
    }
    // preload Wo chunk0
    {
        const float* src = Wo + (long long)wrow * DD + wc0;
        cvt_store8o(smc, E_W(0), E_W(0) + 4096, wrow, wc0,
                    *(const float4*)src, *(const float4*)(src + 4));
    }
    __syncthreads();

    float C[8][4];
#pragma unroll
    for (int nf = 0; nf < 8; nf++)
#pragma unroll
        for (int e = 0; e < 4; e++) C[nf][e] = 0.f;

    // ---- GEMM1: C = A @ Wo (3-pass bf16; warp computes its 64-col half) ----
#pragma unroll 1
    for (int kc = 0; kc < 8; kc++) {
        const int cur = kc & 1;
        const uint32_t WH = E_W(cur), WL = WH + 4096;
        const bool pre = (kc < 7);
        float4 wp0, wp1;
        if (pre) {
            const float* src = Wo + (long long)((kc + 1) * 16 + wrow) * DD + wc0;
            wp0 = *(const float4*)src;
            wp1 = *(const float4*)(src + 4);
        }
        uint32_t aoff = sw_off(wr * 16 + ((g & 1) ? 8 : 0) + r, kc * 16 + ((g >> 1) ? 8 : 0));
        uint32_t ah0, ah1, ah2, ah3, al0, al1, al2, al3;
        ldsm4(ah0, ah1, ah2, ah3, sbase + E_AH + aoff);
        ldsm4(al0, al1, al2, al3, sbase + E_AL + aoff);
        uint32_t th[4][4], tl[4][4];
#pragma unroll
        for (int nfp = 0; nfp < 4; nfp++) {
            uint32_t boff = sw_off(((g & 1) ? 8 : 0) + r,
                                   ncol0 + nfp * 16 + ((g >> 1) ? 8 : 0));
            ldsm4t(th[nfp][0], th[nfp][1], th[nfp][2], th[nfp][3], sbase + WH + boff);
            ldsm4t(tl[nfp][0], tl[nfp][1], tl[nfp][2], tl[nfp][3], sbase + WL + boff);
        }
#pragma unroll
        for (int nfp = 0; nfp < 4; nfp++) {
            mma16816(C[2 * nfp],     ah0, ah1, ah2, ah3, th[nfp][0], th[nfp][1]);
            mma16816(C[2 * nfp + 1], ah0, ah1, ah2, ah3, th[nfp][2], th[nfp][3]);
        }
#pragma unroll
        for (int nfp = 0; nfp < 4; nfp++) {
            mma16816(C[2 * nfp],     ah0, ah1, ah2, ah3, tl[nfp][0], tl[nfp][1]);
            mma16816(C[2 * nfp + 1], ah0, ah1, ah2, ah3, tl[nfp][2], tl[nfp][3]);
        }
#pragma unroll
        for (int nfp = 0; nfp < 4; nfp++) {
            mma16816(C[2 * nfp],     al0, al1, al2, al3, th[nfp][0], th[nfp][1]);
            mma16816(C[2 * nfp + 1], al0, al1, al2, al3, th[nfp][2], th[nfp][3]);
        }
        if (pre) {
            const uint32_t NW = E_W(1 - cur);
            cvt_store8o(smc, NW, NW + 4096, wrow, wc0, wp0, wp1);
        }
        __syncthreads();
    }

    // ---- bias + mf, tangent dot (per warp: its 64 cols) ----
    float dotA = 0.f, dotB = 0.f;
#pragma unroll
    for (int nf = 0; nf < 8; nf++) {
        int col = ncol0 + nf * 8 + 2 * (lane & 3);
        float2 bov = *(const float2*)(bo + col);
        float2 mA = *(const float2*)(mf + gA * DD + col);
        float2 mB = *(const float2*)(mf + gB * DD + col);
        C[nf][0] += bov.x + mA.x; C[nf][1] += bov.y + mA.y;
        C[nf][2] += bov.x + mB.x; C[nf][3] += bov.y + mB.y;
        float2 zA = *(const float2*)(zin + gA * DD + col);
        float2 zB = *(const float2*)(zin + gB * DD + col);
        dotA += C[nf][0] * zA.x + C[nf][1] * zA.y;
        dotB += C[nf][2] * zB.x + C[nf][3] * zB.y;
    }
    dotA += __shfl_xor_sync(0xffffffffu, dotA, 1);
    dotA += __shfl_xor_sync(0xffffffffu, dotA, 2);
    dotB += __shfl_xor_sync(0xffffffffu, dotB, 1);
    dotB += __shfl_xor_sync(0xffffffffu, dotB, 2);
    if ((lane & 3) == 0) {
        red[whalf * 64 + rowL] = dotA;
        red[whalf * 64 + rowL + 8] = dotB;
    }
    __syncthreads();
    dotA = red[rowL] + red[64 + rowL];
    dotB = red[rowL + 8] + red[64 + rowL + 8];
    __syncthreads();

    // ---- proj, vacc update, zn sumsq ----
    float ssA = 0.f, ssB = 0.f;
    float va_keep[8][4];
#pragma unroll
    for (int nf = 0; nf < 8; nf++) {
        int col = ncol0 + nf * 8 + 2 * (lane & 3);
        float2 zA = *(const float2*)(zin + gA * DD + col);
        float2 zB = *(const float2*)(zin + gB * DD + col);
        C[nf][0] -= dotA * zA.x; C[nf][1] -= dotA * zA.y;
        C[nf][2] -= dotB * zB.x; C[nf][3] -= dotB * zB.y;
        float2* vA = (float2*)(vacc + gA * DD + col);
        float2* vB = (float2*)(vacc + gB * DD + col);
        float2 vpA = first ? make_float2(0.f, 0.f) : *vA;
        float2 vpB = first ? make_float2(0.f, 0.f) : *vB;
        float2 vnA = make_float2(vpA.x + sw * C[nf][0], vpA.y + sw * C[nf][1]);
        float2 vnB = make_float2(vpB.x + sw * C[nf][2], vpB.y + sw * C[nf][3]);
        *vA = vnA; *vB = vnB;
        va_keep[nf][0] = vnA.x; va_keep[nf][1] = vnA.y;
        va_keep[nf][2] = vnB.x; va_keep[nf][3] = vnB.y;
        float2 zbA = *(const float2*)(zbase + gA * DD + col);
        float2 zbB = *(const float2*)(zbase + gB * DD + col);
        if (has_next) {
            float a0v = zbA.x + rc * C[nf][0], a1v = zbA.y + rc * C[nf][1];
            float b0v = zbB.x + rc * C[nf][2], b1v = zbB.y + rc * C[nf][3];
            ssA += a0v * a0v + a1v * a1v;
            ssB += b0v * b0v + b1v * b1v;
            C[nf][0] = a0v; C[nf][1] = a1v; C[nf][2] = b0v; C[nf][3] = b1v;
        } else {
            float a0v = zbA.x + vnA.x, a1v = zbA.y + vnA.y;
            float b0v = zbB.x + vnB.x, b1v = zbB.y + vnB.y;
            ssA += a0v * a0v + a1v * a1v;
            ssB += b0v * b0v + b1v * b1v;
            C[nf][0] = a0v; C[nf][1] = a1v; C[nf][2] = b0v; C[nf][3] = b1v;
        }
    }
    ssA += __shfl_xor_sync(0xffffffffu, ssA, 1);
    ssA += __shfl_xor_sync(0xffffffffu, ssA, 2);
    ssB += __shfl_xor_sync(0xffffffffu, ssB, 1);
    ssB += __shfl_xor_sync(0xffffffffu, ssB, 2);
    if ((lane & 3) == 0) {
        red[whalf * 64 + rowL] = ssA;
        red[whalf * 64 + rowL + 8] = ssB;
    }
    __syncthreads();
    ssA = red[rowL] + red[64 + rowL];
    ssB = red[rowL + 8] + red[64 + rowL + 8];
    __syncthreads();
    float invA = __fdividef(1.f, fmaxf(sqrtf(ssA), 1e-8f));
    float invB = __fdividef(1.f, fmaxf(sqrtf(ssB), 1e-8f));

    if (!has_next) {
#pragma unroll
        for (int nf = 0; nf < 8; nf++) {
            int col = ncol0 + nf * 8 + 2 * (lane & 3);
            *(float2*)(out + gA * DD + col) = make_float2(C[nf][0] * invA, C[nf][1] * invA);
            *(float2*)(out + gB * DD + col) = make_float2(C[nf][2] * invB, C[nf][3] * invB);
        }
        return;
    }

    // ---- z0 = norm(zbase + rc*proj): store zc + restage into A tile ----
    {
        const float* src = Wq + (long long)wrow * DD + wc0;
        cvt_store8o(smc, E_W(0), E_W(0) + 4096, wrow, wc0,
                    *(const float4*)src, *(const float4*)(src + 4));
    }
#pragma unroll
    for (int nf = 0; nf < 8; nf++) {
        int col = ncol0 + nf * 8 + 2 * (lane & 3);
        float a0v = C[nf][0] * invA, a1v = C[nf][1] * invA;
        float b0v = C[nf][2] * invB, b1v = C[nf][3] * invB;
        *(float2*)(zc + gA * DD + col) = make_float2(a0v, a1v);
        *(float2*)(zc + gB * DD + col) = make_float2(b0v, b1v);
        uint32_t h, l;
        bsplit2(a0v, a1v, h, l);
        *(uint32_t*)(smc + E_AH + sw_off(rowL, col)) = h;
        *(uint32_t*)(smc + E_AL + sw_off(rowL, col)) = l;
        bsplit2(b0v, b1v, h, l);
        *(uint32_t*)(smc + E_AH + sw_off(rowL + 8, col)) = h;
        *(uint32_t*)(smc + E_AL + sw_off(rowL + 8, col)) = l;
    }
    __syncthreads();

    // ---- GEMM2: C = z0 @ Wq (3-pass bf16) ----
#pragma unroll
    for (int nf = 0; nf < 8; nf++)
#pragma unroll
        for (int e = 0; e < 4; e++) C[nf][e] = 0.f;
#pragma unroll 1
    for (int kc = 0; kc < 8; kc++) {
        const int cur = kc & 1;
        const uint32_t WH = E_W(cur), WL = WH + 4096;
        const bool pre = (kc < 7);
        float4 wp0, wp1;
        if (pre) {
            const float* src = Wq + (long long)((kc + 1) * 16 + wrow) * DD + wc0;
            wp0 = *(const float4*)src;
            wp1 = *(const float4*)(src + 4);
        }
        uint32_t aoff = sw_off(wr * 16 + ((g & 1) ? 8 : 0) + r, kc * 16 + ((g >> 1) ? 8 : 0));
        uint32_t ah0, ah1, ah2, ah3, al0, al1, al2, al3;
        ldsm4(ah0, ah1, ah2, ah3, sbase + E_AH + aoff);
        ldsm4(al0, al1, al2, al3, sbase + E_AL + aoff);
        uint32_t th[4][4], tl[4][4];
#pragma unroll
        for (int nfp = 0; nfp < 4; nfp++) {
            uint32_t boff = sw_off(((g & 1) ? 8 : 0) + r,
                                   ncol0 + nfp * 16 + ((g >> 1) ? 8 : 0));
            ldsm4t(th[nfp][0], th[nfp][1], th[nfp][2], th[nfp][3], sbase + WH + boff);
            ldsm4t(tl[nfp][0], tl[nfp][1], tl[nfp][2], tl[nfp][3], sbase + WL + boff);
        }
#pragma unroll
        for (int nfp = 0; nfp < 4; nfp++) {
            mma16816(C[2 * nfp],     ah0, ah1, ah2, ah3, th[nfp][0], th[nfp][1]);
            mma16816(C[2 * nfp + 1], ah0, ah1, ah2, ah3, th[nfp][2], th[nfp][3]);
        }
#pragma unroll
        for (int nfp = 0; nfp < 4; nfp++) {
            mma16816(C[2 * nfp],     ah0, ah1, ah2, ah3, tl[nfp][0], tl[nfp][1]);
            mma16816(C[2 * nfp + 1], ah0, ah1, ah2, ah3, tl[nfp][2], tl[nfp][3]);
        }
#pragma unroll
        for (int nfp = 0; nfp < 4; nfp++) {
            mma16816(C[2 * nfp],     al0, al1, al2, al3, th[nfp][0], th[nfp][1]);
            mma16816(C[2 * nfp + 1], al0, al1, al2, al3, th[nfp][2], th[nfp][3]);
        }
        if (pre) {
            const uint32_t NW = E_W(1 - cur);
            cvt_store8o(smc, NW, NW + 4096, wrow, wc0, wp0, wp1);
        }
        __syncthreads();
    }

    // ---- qh = norm(C + bq) ----
    float qsA = 0.f, qsB = 0.f;
#pragma unroll
    for (int nf = 0; nf < 8; nf++) {
        int col = ncol0 + nf * 8 + 2 * (lane & 3);
        float2 bqv = *(const float2*)(bq + col);
        C[nf][0] += bqv.x; C[nf][1] += bqv.y;
        C[nf][2] += bqv.x; C[nf][3] += bqv.y;
        qsA += C[nf][0] * C[nf][0] + C[nf][1] * C[nf][1];
        qsB += C[nf][2] * C[nf][2] + C[nf][3] * C[nf][3];
    }
    qsA += __shfl_xor_sync(0xffffffffu, qsA, 1);
    qsA += __shfl_xor_sync(0xffffffffu, qsA, 2);
    qsB += __shfl_xor_sync(0xffffffffu, qsB, 1);
    qsB += __shfl_xor_sync(0xffffffffu, qsB, 2);
    if ((lane & 3) == 0) {
        red[whalf * 64 + rowL] = qsA;
        red[whalf * 64 + rowL + 8] = qsB;
    }
    __syncthreads();
    qsA = red[rowL] + red[64 + rowL];
    qsB = red[rowL + 8] + red[64 + rowL + 8];
    float qiA = __fdividef(1.f, fmaxf(sqrtf(qsA), 1e-8f));
    float qiB = __fdividef(1.f, fmaxf(sqrtf(qsB), 1e-8f));
#pragma unroll
    for (int nf = 0; nf < 8; nf++) {
        int col = ncol0 + nf * 8 + 2 * (lane & 3);
        *(float2*)(qh + gA * DD + col) = make_float2(C[nf][0] * qiA, C[nf][1] * qiA);
        *(float2*)(qh + gB * DD + col) = make_float2(C[nf][2] * qiB, C[nf][3] * qiB);
    }
}

// ---------------- launch ----------------
extern "C" void kernel_launch(void* const* d_in, const int* in_sizes, int n_in,
                              void* d_out, int out_size) {
    const float* z  = (const float*)d_in[0];
    const float* ck = (const float*)d_in[1];
    const float* cb = (const float*)d_in[2];
    const float* Wq = (const float*)d_in[3];
    const float* bq = (const float*)d_in[4];
    const float* Wk = (const float*)d_in[5];
    const float* bk = (const float*)d_in[6];
    const float* Wo = (const float*)d_in[7];
    const float* bo = (const float*)d_in[8];
    float* out = (float*)d_out;

    float *kh, *mf, *qh, *a0, *zc, *va;
    cudaGetSymbolAddress((void**)&kh, g_kh);
    cudaGetSymbolAddress((void**)&mf, g_mf);
    cudaGetSymbolAddress((void**)&qh, g_qh);
    cudaGetSymbolAddress((void**)&a0, g_a0);
    cudaGetSymbolAddress((void**)&zc, g_zc);
    cudaGetSymbolAddress((void**)&va, g_va);

    cudaFuncSetAttribute(dual_gemm_norm, cudaFuncAttributeMaxDynamicSharedMemorySize, DUAL_SMEM);
    cudaFuncSetAttribute(epilogue_mma, cudaFuncAttributeMaxDynamicSharedMemorySize, EPI2_SMEM);
    cudaFuncSetAttribute(attn_kernel, cudaFuncAttributeMaxDynamicSharedMemorySize, ATTN_SMEM);

    conv_kernel<<<dim3(TT / 8, BB), dim3(64, 8)>>>(z, ck, cb, mf);
    dual_gemm_norm<<<BT / 64, 512, DUAL_SMEM>>>(z, Wk, bk, Wq, bq, kh, qh);

    const float sws[4] = {1.f / 6.f, 2.f / 6.f, 2.f / 6.f, 1.f / 6.f};
    const float rcs[4] = {0.5f, 0.5f, 1.0f, 0.f};
    const float* zcur = z;
    for (int s = 0; s < 4; s++) {
        cudaMemsetAsync(a0, 0, (size_t)BT * DD * sizeof(float));
        attn_kernel<<<dim3(32, 9), 128, ATTN_SMEM>>>(qh, kh, a0);
        epilogue_mma<<<BT / 64, 256, EPI2_SMEM>>>(a0, Wo, bo, Wq, bq,
                                                  mf, zcur, z, va, zc, qh, out,
                                                  sws[s], rcs[s], s == 0 ? 1 : 0,
                                                  s < 3 ? 1 : 0);
        zcur = zc;
    }
}

// round 10
// speedup vs baseline: 3.4532x; 1.0244x over previous
#include <cuda_runtime.h>
#include <cstdint>

#define BB 2
#define TT 4096
#define DD 128
#define KK 256
#define BT (BB * TT)

// ---------------- scratch ----------------
__device__ float g_mf[BT * DD];
__device__ float g_a0[BT * DD];
__device__ float g_zc[BT * DD];
__device__ float g_va[BT * DD];
// prepacked bf16 hi/lo planes for q_hat / k_hat
__device__ unsigned short g_qhh[BT * DD];
__device__ unsigned short g_qhl[BT * DD];
__device__ unsigned short g_khh[BT * DD];
__device__ unsigned short g_khl[BT * DD];

// ================= helpers =================
typedef unsigned long long ull;
__device__ __forceinline__ uint32_t smem_u32(const void* p) {
    uint32_t a;
    asm("{ .reg .u64 t; cvta.to.shared.u64 t, %1; cvt.u32.u64 %0, t; }" : "=r"(a) : "l"(p));
    return a;
}
__device__ __forceinline__ void ldsm4(uint32_t& r0, uint32_t& r1, uint32_t& r2, uint32_t& r3,
                                      uint32_t addr) {
    asm volatile("ldmatrix.sync.aligned.m8n8.x4.shared.b16 {%0,%1,%2,%3}, [%4];"
                 : "=r"(r0), "=r"(r1), "=r"(r2), "=r"(r3) : "r"(addr));
}
__device__ __forceinline__ void ldsm4t(uint32_t& r0, uint32_t& r1, uint32_t& r2, uint32_t& r3,
                                       uint32_t addr) {
    asm volatile("ldmatrix.sync.aligned.m8n8.x4.trans.shared.b16 {%0,%1,%2,%3}, [%4];"
                 : "=r"(r0), "=r"(r1), "=r"(r2), "=r"(r3) : "r"(addr));
}
__device__ __forceinline__ void mma16816(float* c, uint32_t a0, uint32_t a1, uint32_t a2,
                                         uint32_t a3, uint32_t b0, uint32_t b1) {
    asm volatile(
        "mma.sync.aligned.m16n8k16.row.col.f32.bf16.bf16.f32 "
        "{%0,%1,%2,%3}, {%4,%5,%6,%7}, {%8,%9}, {%0,%1,%2,%3};"
        : "+f"(c[0]), "+f"(c[1]), "+f"(c[2]), "+f"(c[3])
        : "r"(a0), "r"(a1), "r"(a2), "r"(a3), "r"(b0), "r"(b1));
}
__device__ __forceinline__ void bsplit2(float x0, float x1, uint32_t& h, uint32_t& l) {
    uint16_t h0, h1, l0, l1;
    asm("cvt.rn.bf16.f32 %0, %1;" : "=h"(h0) : "f"(x0));
    asm("cvt.rn.bf16.f32 %0, %1;" : "=h"(h1) : "f"(x1));
    float f0 = __uint_as_float((uint32_t)h0 << 16);
    float f1 = __uint_as_float((uint32_t)h1 << 16);
    asm("cvt.rn.bf16.f32 %0, %1;" : "=h"(l0) : "f"(x0 - f0));
    asm("cvt.rn.bf16.f32 %0, %1;" : "=h"(l1) : "f"(x1 - f1));
    h = (uint32_t)h0 | ((uint32_t)h1 << 16);
    l = (uint32_t)l0 | ((uint32_t)l1 << 16);
}
__device__ __forceinline__ uint32_t sw_off(int row, int d) {
    return (uint32_t)(row * 256 + ((((d >> 3) ^ (row & 7)) & 15) << 4) + (d & 7) * 2);
}
__device__ __forceinline__ float sinpoly(float x) {
    float x2 = x * x;
    float pp = fmaf(x2, 2.7557319e-06f, -1.9841270e-04f);
    pp = fmaf(x2, pp, 8.3333333e-03f);
    pp = fmaf(x2, pp, -1.6666667e-01f);
    return fmaf(x * x2, pp, x);
}
__device__ __forceinline__ ull dup2(float x) {
    ull r; asm("mov.b64 %0, {%1, %1};" : "=l"(r) : "f"(x)); return r;
}
__device__ __forceinline__ ull pack2(float x, float y) {
    ull r; asm("mov.b64 %0, {%1, %2};" : "=l"(r) : "f"(x), "f"(y)); return r;
}
__device__ __forceinline__ void fma2(ull& d, ull a, ull b) {
    asm("fma.rn.f32x2 %0, %1, %2, %0;" : "+l"(d) : "l"(a), "l"(b));
}
__device__ __forceinline__ float2 unpk(ull v) {
    float2 r; asm("mov.b64 {%0, %1}, %2;" : "=f"(r.x), "=f"(r.y) : "l"(v)); return r;
}

__device__ __forceinline__ void cvt_store8o(char* smcp, uint32_t hoff, uint32_t loff,
                                            int row, int col, float4 a, float4 b) {
    uint32_t hw[4], lw[4];
    bsplit2(a.x, a.y, hw[0], lw[0]);
    bsplit2(a.z, a.w, hw[1], lw[1]);
    bsplit2(b.x, b.y, hw[2], lw[2]);
    bsplit2(b.z, b.w, hw[3], lw[3]);
    uint32_t off = sw_off(row, col);
    *(uint4*)(smcp + hoff + off) = make_uint4(hw[0], hw[1], hw[2], hw[3]);
    *(uint4*)(smcp + loff + off) = make_uint4(lw[0], lw[1], lw[2], lw[3]);
}

// attn smem: Qhi 16K | Qlo 16K | K double-buffered (hi 16K + lo 16K) x2 = 96KB
#define QH_OFF 0
#define QL_OFF 16384
#define KBASE_OFF 32768
#define ATTN_SMEM 98304

// ---------------- causal sin-attention: prepacked bf16, M=64, 2 CTAs/SM ----------------
__global__ __launch_bounds__(128, 2) void attn_kernel(const unsigned short* __restrict__ Qhh,
                                                      const unsigned short* __restrict__ Qhl,
                                                      const unsigned short* __restrict__ Khh,
                                                      const unsigned short* __restrict__ Khl,
                                                      float* __restrict__ O) {
    extern __shared__ char smc[];
    const uint32_t sbase = smem_u32(smc);
    const int tid = threadIdx.x;
    const int lane = tid & 31, w = tid >> 5;
    const int P = blockIdx.x, split = blockIdx.y;
    const int g = lane >> 3, r = lane & 7;
    const int krow = tid >> 1, kc0 = (tid & 1) * 64;
    const int lo = (130 * split) / 9, hi = (130 * (split + 1)) / 9;

    int c = 0;
    for (int sp = 0; sp < 4; sp++) {
        const int b = sp >> 1;
        const int R = (sp & 1) ? (63 - P) : P;
        const int n = R + 1;
        int s_lo = lo - c; if (s_lo < 0) s_lo = 0;
        int s_hi = hi - c; if (s_hi > n) s_hi = n;
        c += n;
        if (s_lo >= s_hi) continue;

        const unsigned short* Qhb = Qhh + (long long)b * TT * DD;
        const unsigned short* Qlb = Qhl + (long long)b * TT * DD;
        const unsigned short* Khb = Khh + (long long)b * TT * DD;
        const unsigned short* Klb = Khl + (long long)b * TT * DD;

        __syncthreads();
        // ---- Q tile: direct copy of prepacked hi/lo ----
        for (int t = tid; t < 1024; t += 128) {
            int row = t >> 4, d0 = (t & 15) * 8;
            long long src = ((long long)R * 64 + row) * DD + d0;
            uint32_t off = sw_off(row, d0);
            *(uint4*)(smc + QH_OFF + off) = *(const uint4*)(Qhb + src);
            *(uint4*)(smc + QL_OFF + off) = *(const uint4*)(Qlb + src);
        }
        // ---- preload K(s_lo) ----
        {
            long long src = ((long long)s_lo * 64 + krow) * DD + kc0;
#pragma unroll
            for (int q = 0; q < 8; q++) {
                uint32_t off = sw_off(krow, kc0 + 8 * q);
                *(uint4*)(smc + KBASE_OFF + off) = *(const uint4*)(Khb + src + 8 * q);
                *(uint4*)(smc + KBASE_OFF + 16384 + off) = *(const uint4*)(Klb + src + 8 * q);
            }
        }
        float Oc[16][4];
#pragma unroll
        for (int nf = 0; nf < 16; nf++)
#pragma unroll
            for (int e = 0; e < 4; e++) Oc[nf][e] = 0.f;
        __syncthreads();

        // ---- hoist Q A-frags into registers ----
        uint32_t qah[8][4], qal[8][4];
#pragma unroll
        for (int kc = 0; kc < 8; kc++) {
            uint32_t aoff = sw_off(w * 16 + ((g & 1) ? 8 : 0) + r, kc * 16 + ((g >> 1) ? 8 : 0));
            ldsm4(qah[kc][0], qah[kc][1], qah[kc][2], qah[kc][3], sbase + QH_OFF + aoff);
            ldsm4(qal[kc][0], qal[kc][1], qal[kc][2], qal[kc][3], sbase + QL_OFF + aoff);
        }

        for (int sb = s_lo; sb < s_hi; sb++) {
            const int cur = (sb - s_lo) & 1;
            const uint32_t KH = KBASE_OFF + (uint32_t)cur * 32768;
            const uint32_t KL = KH + 16384;
            const bool pre = (sb + 1 < s_hi);
            const uint32_t NH = KBASE_OFF + (uint32_t)(1 - cur) * 32768;
            long long psrc = ((long long)(sb + 1) * 64 + krow) * DD + kc0;

            // ---- MMA1: C = Q . K^T (3-pass, Q frags in regs) ----
            float C[8][4];
#pragma unroll
            for (int nf = 0; nf < 8; nf++)
#pragma unroll
                for (int e = 0; e < 4; e++) C[nf][e] = 0.f;
#pragma unroll
            for (int kc = 0; kc < 8; kc++) {
                int d0 = kc * 16;
                uint32_t bh[4][4], bl[4][4];
#pragma unroll
                for (int nfp = 0; nfp < 4; nfp++) {
                    uint32_t boff = sw_off(nfp * 16 + ((g >> 1) ? 8 : 0) + r,
                                           d0 + ((g & 1) ? 8 : 0));
                    ldsm4(bh[nfp][0], bh[nfp][1], bh[nfp][2], bh[nfp][3], sbase + KH + boff);
                    ldsm4(bl[nfp][0], bl[nfp][1], bl[nfp][2], bl[nfp][3], sbase + KL + boff);
                }
#pragma unroll
                for (int nfp = 0; nfp < 4; nfp++) {
                    mma16816(C[2 * nfp],     qah[kc][0], qah[kc][1], qah[kc][2], qah[kc][3], bh[nfp][0], bh[nfp][1]);
                    mma16816(C[2 * nfp + 1], qah[kc][0], qah[kc][1], qah[kc][2], qah[kc][3], bh[nfp][2], bh[nfp][3]);
                }
#pragma unroll
                for (int nfp = 0; nfp < 4; nfp++) {
                    mma16816(C[2 * nfp],     qah[kc][0], qah[kc][1], qah[kc][2], qah[kc][3], bl[nfp][0], bl[nfp][1]);
                    mma16816(C[2 * nfp + 1], qah[kc][0], qah[kc][1], qah[kc][2], qah[kc][3], bl[nfp][2], bl[nfp][3]);
                }
#pragma unroll
                for (int nfp = 0; nfp < 4; nfp++) {
                    mma16816(C[2 * nfp],     qal[kc][0], qal[kc][1], qal[kc][2], qal[kc][3], bh[nfp][0], bh[nfp][1]);
                    mma16816(C[2 * nfp + 1], qal[kc][0], qal[kc][1], qal[kc][2], qal[kc][3], bh[nfp][2], bh[nfp][3]);
                }
            }
            // ---- prefetch next K hi plane (pure copy) ----
            if (pre) {
#pragma unroll
                for (int q = 0; q < 8; q++)
                    *(uint4*)(smc + NH + sw_off(krow, kc0 + 8 * q)) =
                        *(const uint4*)(Khb + psrc + 8 * q);
            }

            // ---- sin + causal mask + repack ----
            uint32_t a2h[4][4], a2l[4][4];
            const int ig = R * 64 + w * 16 + (lane >> 2);
#pragma unroll
            for (int nf = 0; nf < 8; nf++) {
                int jb = sb * 64 + nf * 8 + 2 * (lane & 3);
                float s0 = sinpoly(C[nf][0]); if (jb > ig) s0 = 0.f;
                float s1 = sinpoly(C[nf][1]); if (jb + 1 > ig) s1 = 0.f;
                float s2 = sinpoly(C[nf][2]); if (jb > ig + 8) s2 = 0.f;
                float s3 = sinpoly(C[nf][3]); if (jb + 1 > ig + 8) s3 = 0.f;
                int kc2 = nf >> 1, hk = (nf & 1) ? 2 : 0;
                bsplit2(s0, s1, a2h[kc2][hk], a2l[kc2][hk]);
                bsplit2(s2, s3, a2h[kc2][hk + 1], a2l[kc2][hk + 1]);
            }

            // ---- MMA2: O += S . K (3-pass, pass-outer over nfp-halves) ----
#pragma unroll
            for (int kc2 = 0; kc2 < 4; kc2++) {
                int j0 = kc2 * 16;
#pragma unroll
                for (int hh = 0; hh < 2; hh++) {
                    uint32_t th[4][4], tl[4][4];
#pragma unroll
                    for (int q = 0; q < 4; q++) {
                        int nfp = hh * 4 + q;
                        uint32_t boff = sw_off(j0 + ((g & 1) ? 8 : 0) + r,
                                               nfp * 16 + ((g >> 1) ? 8 : 0));
                        ldsm4t(th[q][0], th[q][1], th[q][2], th[q][3], sbase + KH + boff);
                        ldsm4t(tl[q][0], tl[q][1], tl[q][2], tl[q][3], sbase + KL + boff);
                    }
#pragma unroll
                    for (int q = 0; q < 4; q++) {
                        int nfp = hh * 4 + q;
                        mma16816(Oc[2 * nfp],     a2h[kc2][0], a2h[kc2][1], a2h[kc2][2], a2h[kc2][3], th[q][0], th[q][1]);
                        mma16816(Oc[2 * nfp + 1], a2h[kc2][0], a2h[kc2][1], a2h[kc2][2], a2h[kc2][3], th[q][2], th[q][3]);
                    }
#pragma unroll
                    for (int q = 0; q < 4; q++) {
                        int nfp = hh * 4 + q;
                        mma16816(Oc[2 * nfp],     a2h[kc2][0], a2h[kc2][1], a2h[kc2][2], a2h[kc2][3], tl[q][0], tl[q][1]);
                        mma16816(Oc[2 * nfp + 1], a2h[kc2][0], a2h[kc2][1], a2h[kc2][2], a2h[kc2][3], tl[q][2], tl[q][3]);
                    }
#pragma unroll
                    for (int q = 0; q < 4; q++) {
                        int nfp = hh * 4 + q;
                        mma16816(Oc[2 * nfp],     a2l[kc2][0], a2l[kc2][1], a2l[kc2][2], a2l[kc2][3], th[q][0], th[q][1]);
                        mma16816(Oc[2 * nfp + 1], a2l[kc2][0], a2l[kc2][1], a2l[kc2][2], a2l[kc2][3], th[q][2], th[q][3]);
                    }
                }
            }
            // ---- prefetch next K lo plane ----
            if (pre) {
#pragma unroll
                for (int q = 0; q < 8; q++)
                    *(uint4*)(smc + NH + 16384 + sw_off(krow, kc0 + 8 * q)) =
                        *(const uint4*)(Klb + psrc + 8 * q);
            }
            __syncthreads();
        }

        {
            long long rbase = (long long)b * TT + (long long)R * 64 + w * 16 + (lane >> 2);
#pragma unroll
            for (int nf = 0; nf < 16; nf++) {
                int d = nf * 8 + 2 * (lane & 3);
                atomicAdd(O + rbase * DD + d,       Oc[nf][0]);
                atomicAdd(O + rbase * DD + d + 1,   Oc[nf][1]);
                atomicAdd(O + (rbase + 8) * DD + d,     Oc[nf][2]);
                atomicAdd(O + (rbase + 8) * DD + d + 1, Oc[nf][3]);
            }
        }
    }
}

// ---------------- depthwise causal conv (FFMA2, d-pairs) ----------------
__global__ __launch_bounds__(512) void conv_kernel(const float* __restrict__ z,
                                                   const float* __restrict__ w,
                                                   const float* __restrict__ bias,
                                                   float* __restrict__ mf) {
    int d0 = threadIdx.x * 2;
    int t = blockIdx.x * 8 + threadIdx.y;
    int b = blockIdx.y;
    float2 bv = *(const float2*)(bias + d0);
    ull acc = pack2(bv.x, bv.y);
    int kstart = (KK - 1) - t;
    if (kstart < 0) kstart = 0;
    const float* zp = z + ((long long)b * TT + t - (KK - 1)) * DD + d0;
    const float* wp = w + d0;
#pragma unroll 4
    for (int k = kstart; k < KK; k++)
        fma2(acc, *(const ull*)(zp + (long long)k * DD), *(const ull*)(wp + (long long)k * DD));
    float2 res = unpk(acc);
    *(float2*)(mf + ((long long)b * TT + t) * DD + d0) = res;
}

// ---------------- group reduce (dual_gemm_norm) ----------------
__device__ __forceinline__ void group_reduce8(float v[8], float* red, int grp, int wig, int lane) {
#pragma unroll
    for (int k = 0; k < 8; k++) {
        float x = v[k];
#pragma unroll
        for (int o = 16; o; o >>= 1) x += __shfl_xor_sync(0xffffffffu, x, o);
        if (lane == 0) red[grp * 32 + wig * 8 + k] = x;
    }
    __syncthreads();
#pragma unroll
    for (int k = 0; k < 8; k++)
        v[k] = red[grp * 32 + k] + red[grp * 32 + 8 + k] + red[grp * 32 + 16 + k] +
               red[grp * 32 + 24 + k];
    __syncthreads();
}

__device__ __forceinline__ void matvec8(const float* Ws, const float* xg, int d, float bias,
                                        float tot[8]) {
    ull acc0 = dup2(bias), acc1 = dup2(bias), acc2 = dup2(bias), acc3 = dup2(bias);
#pragma unroll 4
    for (int j = 0; j < 128; j++) {
        ull w2 = dup2(Ws[j * 128 + d]);
        ulonglong2 x01 = *(const ulonglong2*)(xg + j * 8);
        ulonglong2 x23 = *(const ulonglong2*)(xg + j * 8 + 4);
        fma2(acc0, x01.x, w2);
        fma2(acc1, x01.y, w2);
        fma2(acc2, x23.x, w2);
        fma2(acc3, x23.y, w2);
    }
    float2 a0 = unpk(acc0), a1 = unpk(acc1), a2 = unpk(acc2), a3 = unpk(acc3);
    tot[0] = a0.x; tot[1] = a0.y; tot[2] = a1.x; tot[3] = a1.y;
    tot[4] = a2.x; tot[5] = a2.y; tot[6] = a3.x; tot[7] = a3.y;
}

#define DUAL_SMEM ((16384 + 16384 + 4096 + 128) * 4)

// ---------------- dual projection -> prepacked bf16 hi/lo ----------------
__global__ __launch_bounds__(512) void dual_gemm_norm(const float* __restrict__ X,
                                                      const float* __restrict__ W1,
                                                      const float* __restrict__ b1,
                                                      const float* __restrict__ W2,
                                                      const float* __restrict__ b2,
                                                      unsigned short* __restrict__ Y1h,
                                                      unsigned short* __restrict__ Y1l,
                                                      unsigned short* __restrict__ Y2h,
                                                      unsigned short* __restrict__ Y2l) {
    extern __shared__ float sm[];
    float* W1s = sm;
    float* W2s = sm + 16384;
    float* xp  = sm + 32768;
    float* red = sm + 36864;
    int tid = threadIdx.x, grp = tid >> 7, d = tid & 127, wig = (tid >> 5) & 3, lane = tid & 31;
    for (int i = tid; i < 16384; i += 512) { W1s[i] = W1[i]; W2s[i] = W2[i]; }
    float b1v = b1[d], b2v = b2[d];
    __syncthreads();
    long long row0 = (long long)blockIdx.x * 64 + grp * 16;
    float* xg = xp + grp * 1024;
    for (int gg = 0; gg < 16; gg += 8) {
#pragma unroll
        for (int k = 0; k < 8; k++)
            xg[d * 8 + k] = X[(row0 + gg + k) * DD + d];
        __syncthreads();
        float tot[8], v[8];
        matvec8(W1s, xg, d, b1v, tot);
#pragma unroll
        for (int k = 0; k < 8; k++) v[k] = tot[k] * tot[k];
        group_reduce8(v, red, grp, wig, lane);
#pragma unroll
        for (int k = 0; k < 8; k++) {
            float y = __fdividef(tot[k], fmaxf(sqrtf(v[k]), 1e-8f));
            uint16_t h;
            asm("cvt.rn.bf16.f32 %0, %1;" : "=h"(h) : "f"(y));
            float fh = __uint_as_float((uint32_t)h << 16);
            uint16_t l;
            asm("cvt.rn.bf16.f32 %0, %1;" : "=h"(l) : "f"(y - fh));
            long long off = (row0 + gg + k) * DD + d;
            Y1h[off] = h; Y1l[off] = l;
        }
        matvec8(W2s, xg, d, b2v, tot);
#pragma unroll
        for (int k = 0; k < 8; k++) v[k] = tot[k] * tot[k];
        group_reduce8(v, red, grp, wig, lane);
#pragma unroll
        for (int k = 0; k < 8; k++) {
            float y = __fdividef(tot[k], fmaxf(sqrtf(v[k]), 1e-8f));
            uint16_t h;
            asm("cvt.rn.bf16.f32 %0, %1;" : "=h"(h) : "f"(y));
            float fh = __uint_as_float((uint32_t)h << 16);
            uint16_t l;
            asm("cvt.rn.bf16.f32 %0, %1;" : "=h"(l) : "f"(y - fh));
            long long off = (row0 + gg + k) * DD + d;
            Y2h[off] = h; Y2l[off] = l;
        }
        __syncthreads();
    }
}

// ================== MMA epilogue (256 threads, N-split) ==================
#define E_AH 0
#define E_AL 16384
#define E_W(buf) (32768u + (uint32_t)(buf) * 8192u)
#define E_RED 49152
#define EPI2_SMEM 49664

__global__ __launch_bounds__(256) void epilogue_mma(
    const float* __restrict__ A0,
    const float* __restrict__ Wo, const float* __restrict__ bo,
    const float* __restrict__ Wq, const float* __restrict__ bq,
    const float* __restrict__ mf, const float* __restrict__ zin,
    const float* __restrict__ zbase, float* __restrict__ vacc,
    float* __restrict__ zc, unsigned short* __restrict__ qhh,
    unsigned short* __restrict__ qhl, float* __restrict__ out,
    float sw, float rc, int first, int has_next) {
    extern __shared__ char smc[];
    const uint32_t sbase = smem_u32(smc);
    float* red = (float*)(smc + E_RED);
    const int tid = threadIdx.x;
    const int lane = tid & 31, w = tid >> 5;
    const int wr = w & 3, whalf = w >> 2;
    const int ncol0 = whalf * 64;
    const int g = lane >> 3, r = lane & 7;
    const int wrow = tid >> 4, wc0 = (tid & 15) * 8;
    const long long row0 = (long long)blockIdx.x * 64;
    const int rowL = wr * 16 + (lane >> 2);
    const long long gA = row0 + rowL;
    const long long gB = gA + 8;

    for (int t = tid; t < 1024; t += 256) {
        int row = t >> 4, d0 = (t & 15) * 8;
        const float* src = A0 + (row0 + row) * DD + d0;
        cvt_store8o(smc, E_AH, E_AL, row, d0, *(const float4*)src, *(const float4*)(src + 4));
    }
    {
        const float* src = Wo + (long long)wrow * DD + wc0;
        cvt_store8o(smc, E_W(0), E_W(0) + 4096, wrow, wc0,
                    *(const float4*)src, *(const float4*)(src + 4));
    }
    __syncthreads();

    float C[8][4];
#pragma unroll
    for (int nf = 0; nf < 8; nf++)
#pragma unroll
        for (int e = 0; e < 4; e++) C[nf][e] = 0.f;

    // ---- GEMM1: C = A @ Wo ----
#pragma unroll 1
    for (int kc = 0; kc < 8; kc++) {
        const int cur = kc & 1;
        const uint32_t WH = E_W(cur), WL = WH + 4096;
        const bool pre = (kc < 7);
        float4 wp0, wp1;
        if (pre) {
            const float* src = Wo + (long long)((kc + 1) * 16 + wrow) * DD + wc0;
            wp0 = *(const float4*)src;
            wp1 = *(const float4*)(src + 4);
        }
        uint32_t aoff = sw_off(wr * 16 + ((g & 1) ? 8 : 0) + r, kc * 16 + ((g >> 1) ? 8 : 0));
        uint32_t ah0, ah1, ah2, ah3, al0, al1, al2, al3;
        ldsm4(ah0, ah1, ah2, ah3, sbase + E_AH + aoff);
        ldsm4(al0, al1, al2, al3, sbase + E_AL + aoff);
        uint32_t th[4][4], tl[4][4];
#pragma unroll
        for (int nfp = 0; nfp < 4; nfp++) {
            uint32_t boff = sw_off(((g & 1) ? 8 : 0) + r,
                                   ncol0 + nfp * 16 + ((g >> 1) ? 8 : 0));
            ldsm4t(th[nfp][0], th[nfp][1], th[nfp][2], th[nfp][3], sbase + WH + boff);
            ldsm4t(tl[nfp][0], tl[nfp][1], tl[nfp][2], tl[nfp][3], sbase + WL + boff);
        }
#pragma unroll
        for (int nfp = 0; nfp < 4; nfp++) {
            mma16816(C[2 * nfp],     ah0, ah1, ah2, ah3, th[nfp][0], th[nfp][1]);
            mma16816(C[2 * nfp + 1], ah0, ah1, ah2, ah3, th[nfp][2], th[nfp][3]);
        }
#pragma unroll
        for (int nfp = 0; nfp < 4; nfp++) {
            mma16816(C[2 * nfp],     ah0, ah1, ah2, ah3, tl[nfp][0], tl[nfp][1]);
            mma16816(C[2 * nfp + 1], ah0, ah1, ah2, ah3, tl[nfp][2], tl[nfp][3]);
        }
#pragma unroll
        for (int nfp = 0; nfp < 4; nfp++) {
            mma16816(C[2 * nfp],     al0, al1, al2, al3, th[nfp][0], th[nfp][1]);
            mma16816(C[2 * nfp + 1], al0, al1, al2, al3, th[nfp][2], th[nfp][3]);
        }
        if (pre) {
            const uint32_t NW = E_W(1 - cur);
            cvt_store8o(smc, NW, NW + 4096, wrow, wc0, wp0, wp1);
        }
        __syncthreads();
    }

    // ---- bias + mf, tangent dot ----
    float dotA = 0.f, dotB = 0.f;
#pragma unroll
    for (int nf = 0; nf < 8; nf++) {
        int col = ncol0 + nf * 8 + 2 * (lane & 3);
        float2 bov = *(const float2*)(bo + col);
        float2 mA = *(const float2*)(mf + gA * DD + col);
        float2 mB = *(const float2*)(mf + gB * DD + col);
        C[nf][0] += bov.x + mA.x; C[nf][1] += bov.y + mA.y;
        C[nf][2] += bov.x + mB.x; C[nf][3] += bov.y + mB.y;
        float2 zA = *(const float2*)(zin + gA * DD + col);
        float2 zB = *(const float2*)(zin + gB * DD + col);
        dotA += C[nf][0] * zA.x + C[nf][1] * zA.y;
        dotB += C[nf][2] * zB.x + C[nf][3] * zB.y;
    }
    dotA += __shfl_xor_sync(0xffffffffu, dotA, 1);
    dotA += __shfl_xor_sync(0xffffffffu, dotA, 2);
    dotB += __shfl_xor_sync(0xffffffffu, dotB, 1);
    dotB += __shfl_xor_sync(0xffffffffu, dotB, 2);
    if ((lane & 3) == 0) {
        red[whalf * 64 + rowL] = dotA;
        red[whalf * 64 + rowL + 8] = dotB;
    }
    __syncthreads();
    dotA = red[rowL] + red[64 + rowL];
    dotB = red[rowL + 8] + red[64 + rowL + 8];
    __syncthreads();

    // ---- proj, vacc update, zn sumsq ----
    float ssA = 0.f, ssB = 0.f;
#pragma unroll
    for (int nf = 0; nf < 8; nf++) {
        int col = ncol0 + nf * 8 + 2 * (lane & 3);
        float2 zA = *(const float2*)(zin + gA * DD + col);
        float2 zB = *(const float2*)(zin + gB * DD + col);
        C[nf][0] -= dotA * zA.x; C[nf][1] -= dotA * zA.y;
        C[nf][2] -= dotB * zB.x; C[nf][3] -= dotB * zB.y;
        float2* vA = (float2*)(vacc + gA * DD + col);
        float2* vB = (float2*)(vacc + gB * DD + col);
        float2 vpA = first ? make_float2(0.f, 0.f) : *vA;
        float2 vpB = first ? make_float2(0.f, 0.f) : *vB;
        float2 vnA = make_float2(vpA.x + sw * C[nf][0], vpA.y + sw * C[nf][1]);
        float2 vnB = make_float2(vpB.x + sw * C[nf][2], vpB.y + sw * C[nf][3]);
        *vA = vnA; *vB = vnB;
        float2 zbA = *(const float2*)(zbase + gA * DD + col);
        float2 zbB = *(const float2*)(zbase + gB * DD + col);
        if (has_next) {
            float a0v = zbA.x + rc * C[nf][0], a1v = zbA.y + rc * C[nf][1];
            float b0v = zbB.x + rc * C[nf][2], b1v = zbB.y + rc * C[nf][3];
            ssA += a0v * a0v + a1v * a1v;
            ssB += b0v * b0v + b1v * b1v;
            C[nf][0] = a0v; C[nf][1] = a1v; C[nf][2] = b0v; C[nf][3] = b1v;
        } else {
            float a0v = zbA.x + vnA.x, a1v = zbA.y + vnA.y;
            float b0v = zbB.x + vnB.x, b1v = zbB.y + vnB.y;
            ssA += a0v * a0v + a1v * a1v;
            ssB += b0v * b0v + b1v * b1v;
            C[nf][0] = a0v; C[nf][1] = a1v; C[nf][2] = b0v; C[nf][3] = b1v;
        }
    }
    ssA += __shfl_xor_sync(0xffffffffu, ssA, 1);
    ssA += __shfl_xor_sync(0xffffffffu, ssA, 2);
    ssB += __shfl_xor_sync(0xffffffffu, ssB, 1);
    ssB += __shfl_xor_sync(0xffffffffu, ssB, 2);
    if ((lane & 3) == 0) {
        red[whalf * 64 + rowL] = ssA;
        red[whalf * 64 + rowL + 8] = ssB;
    }
    __syncthreads();
    ssA = red[rowL] + red[64 + rowL];
    ssB = red[rowL + 8] + red[64 + rowL + 8];
    __syncthreads();
    float invA = __fdividef(1.f, fmaxf(sqrtf(ssA), 1e-8f));
    float invB = __fdividef(1.f, fmaxf(sqrtf(ssB), 1e-8f));

    if (!has_next) {
#pragma unroll
        for (int nf = 0; nf < 8; nf++) {
            int col = ncol0 + nf * 8 + 2 * (lane & 3);
            *(float2*)(out + gA * DD + col) = make_float2(C[nf][0] * invA, C[nf][1] * invA);
            *(float2*)(out + gB * DD + col) = make_float2(C[nf][2] * invB, C[nf][3] * invB);
        }
        return;
    }

    // ---- z0 = norm(zbase + rc*proj): store zc + restage into A tile ----
    {
        const float* src = Wq + (long long)wrow * DD + wc0;
        cvt_store8o(smc, E_W(0), E_W(0) + 4096, wrow, wc0,
                    *(const float4*)src, *(const float4*)(src + 4));
    }
#pragma unroll
    for (int nf = 0; nf < 8; nf++) {
        int col = ncol0 + nf * 8 + 2 * (lane & 3);
        float a0v = C[nf][0] * invA, a1v = C[nf][1] * invA;
        float b0v = C[nf][2] * invB, b1v = C[nf][3] * invB;
        *(float2*)(zc + gA * DD + col) = make_float2(a0v, a1v);
        *(float2*)(zc + gB * DD + col) = make_float2(b0v, b1v);
        uint32_t h, l;
        bsplit2(a0v, a1v, h, l);
        *(uint32_t*)(smc + E_AH + sw_off(rowL, col)) = h;
        *(uint32_t*)(smc + E_AL + sw_off(rowL, col)) = l;
        bsplit2(b0v, b1v, h, l);
        *(uint32_t*)(smc + E_AH + sw_off(rowL + 8, col)) = h;
        *(uint32_t*)(smc + E_AL + sw_off(rowL + 8, col)) = l;
    }
    __syncthreads();

    // ---- GEMM2: C = z0 @ Wq ----
#pragma unroll
    for (int nf = 0; nf < 8; nf++)
#pragma unroll
        for (int e = 0; e < 4; e++) C[nf][e] = 0.f;
#pragma unroll 1
    for (int kc = 0; kc < 8; kc++) {
        const int cur = kc & 1;
        const uint32_t WH = E_W(cur), WL = WH + 4096;
        const bool pre = (kc < 7);
        float4 wp0, wp1;
        if (pre) {
            const float* src = Wq + (long long)((kc + 1) * 16 + wrow) * DD + wc0;
            wp0 = *(const float4*)src;
            wp1 = *(const float4*)(src + 4);
        }
        uint32_t aoff = sw_off(wr * 16 + ((g & 1) ? 8 : 0) + r, kc * 16 + ((g >> 1) ? 8 : 0));
        uint32_t ah0, ah1, ah2, ah3, al0, al1, al2, al3;
        ldsm4(ah0, ah1, ah2, ah3, sbase + E_AH + aoff);
        ldsm4(al0, al1, al2, al3, sbase + E_AL + aoff);
        uint32_t th[4][4], tl[4][4];
#pragma unroll
        for (int nfp = 0; nfp < 4; nfp++) {
            uint32_t boff = sw_off(((g & 1) ? 8 : 0) + r,
                                   ncol0 + nfp * 16 + ((g >> 1) ? 8 : 0));
            ldsm4t(th[nfp][0], th[nfp][1], th[nfp][2], th[nfp][3], sbase + WH + boff);
            ldsm4t(tl[nfp][0], tl[nfp][1], tl[nfp][2], tl[nfp][3], sbase + WL + boff);
        }
#pragma unroll
        for (int nfp = 0; nfp < 4; nfp++) {
            mma16816(C[2 * nfp],     ah0, ah1, ah2, ah3, th[nfp][0], th[nfp][1]);
            mma16816(C[2 * nfp + 1], ah0, ah1, ah2, ah3, th[nfp][2], th[nfp][3]);
        }
#pragma unroll
        for (int nfp = 0; nfp < 4; nfp++) {
            mma16816(C[2 * nfp],     ah0, ah1, ah2, ah3, tl[nfp][0], tl[nfp][1]);
            mma16816(C[2 * nfp + 1], ah0, ah1, ah2, ah3, tl[nfp][2], tl[nfp][3]);
        }
#pragma unroll
        for (int nfp = 0; nfp < 4; nfp++) {
            mma16816(C[2 * nfp],     al0, al1, al2, al3, th[nfp][0], th[nfp][1]);
            mma16816(C[2 * nfp + 1], al0, al1, al2, al3, th[nfp][2], th[nfp][3]);
        }
        if (pre) {
            const uint32_t NW = E_W(1 - cur);
            cvt_store8o(smc, NW, NW + 4096, wrow, wc0, wp0, wp1);
        }
        __syncthreads();
    }

    // ---- qh = norm(C + bq) -> prepacked bf16 hi/lo ----
    float qsA = 0.f, qsB = 0.f;
#pragma unroll
    for (int nf = 0; nf < 8; nf++) {
        int col = ncol0 + nf * 8 + 2 * (lane & 3);
        float2 bqv = *(const float2*)(bq + col);
        C[nf][0] += bqv.x; C[nf][1] += bqv.y;
        C[nf][2] += bqv.x; C[nf][3] += bqv.y;
        qsA += C[nf][0] * C[nf][0] + C[nf][1] * C[nf][1];
        qsB += C[nf][2] * C[nf][2] + C[nf][3] * C[nf][3];
    }
    qsA += __shfl_xor_sync(0xffffffffu, qsA, 1);
    qsA += __shfl_xor_sync(0xffffffffu, qsA, 2);
    qsB += __shfl_xor_sync(0xffffffffu, qsB, 1);
    qsB += __shfl_xor_sync(0xffffffffu, qsB, 2);
    if ((lane & 3) == 0) {
        red[whalf * 64 + rowL] = qsA;
        red[whalf * 64 + rowL + 8] = qsB;
    }
    __syncthreads();
    qsA = red[rowL] + red[64 + rowL];
    qsB = red[rowL + 8] + red[64 + rowL + 8];
    float qiA = __fdividef(1.f, fmaxf(sqrtf(qsA), 1e-8f));
    float qiB = __fdividef(1.f, fmaxf(sqrtf(qsB), 1e-8f));
#pragma unroll
    for (int nf = 0; nf < 8; nf++) {
        int col = ncol0 + nf * 8 + 2 * (lane & 3);
        uint32_t h, l;
        bsplit2(C[nf][0] * qiA, C[nf][1] * qiA, h, l);
        *(uint32_t*)(qhh + gA * DD + col) = h;
        *(uint32_t*)(qhl + gA * DD + col) = l;
        bsplit2(C[nf][2] * qiB, C[nf][3] * qiB, h, l);
        *(uint32_t*)(qhh + gB * DD + col) = h;
        *(uint32_t*)(qhl + gB * DD + col) = l;
    }
}

// ---------------- launch ----------------
extern "C" void kernel_launch(void* const* d_in, const int* in_sizes, int n_in,
                              void* d_out, int out_size) {
    const float* z  = (const float*)d_in[0];
    const float* ck = (const float*)d_in[1];
    const float* cb = (const float*)d_in[2];
    const float* Wq = (const float*)d_in[3];
    const float* bq = (const float*)d_in[4];
    const float* Wk = (const float*)d_in[5];
    const float* bk = (const float*)d_in[6];
    const float* Wo = (const float*)d_in[7];
    const float* bo = (const float*)d_in[8];
    float* out = (float*)d_out;

    float *mf, *a0, *zc, *va;
    unsigned short *qhh, *qhl, *khh, *khl;
    cudaGetSymbolAddress((void**)&mf, g_mf);
    cudaGetSymbolAddress((void**)&a0, g_a0);
    cudaGetSymbolAddress((void**)&zc, g_zc);
    cudaGetSymbolAddress((void**)&va, g_va);
    cudaGetSymbolAddress((void**)&qhh, g_qhh);
    cudaGetSymbolAddress((void**)&qhl, g_qhl);
    cudaGetSymbolAddress((void**)&khh, g_khh);
    cudaGetSymbolAddress((void**)&khl, g_khl);

    cudaFuncSetAttribute(dual_gemm_norm, cudaFuncAttributeMaxDynamicSharedMemorySize, DUAL_SMEM);
    cudaFuncSetAttribute(epilogue_mma, cudaFuncAttributeMaxDynamicSharedMemorySize, EPI2_SMEM);
    cudaFuncSetAttribute(attn_kernel, cudaFuncAttributeMaxDynamicSharedMemorySize, ATTN_SMEM);

    conv_kernel<<<dim3(TT / 8, BB), dim3(64, 8)>>>(z, ck, cb, mf);
    dual_gemm_norm<<<BT / 64, 512, DUAL_SMEM>>>(z, Wk, bk, Wq, bq, khh, khl, qhh, qhl);

    const float sws[4] = {1.f / 6.f, 2.f / 6.f, 2.f / 6.f, 1.f / 6.f};
    const float rcs[4] = {0.5f, 0.5f, 1.0f, 0.f};
    const float* zcur = z;
    for (int s = 0; s < 4; s++) {
        cudaMemsetAsync(a0, 0, (size_t)BT * DD * sizeof(float));
        attn_kernel<<<dim3(32, 9), 128, ATTN_SMEM>>>(qhh, qhl, khh, khl, a0);
        epilogue_mma<<<BT / 64, 256, EPI2_SMEM>>>(a0, Wo, bo, Wq, bq,
                                                  mf, zcur, z, va, zc, qhh, qhl, out,
                                                  sws[s], rcs[s], s == 0 ? 1 : 0,
                                                  s < 3 ? 1 : 0);
        zcur = zc;
    }
}

// round 11
// speedup vs baseline: 3.4930x; 1.0115x over previous
#include <cuda_runtime.h>
#include <cstdint>

#define BB 2
#define TT 4096
#define DD 128
#define KK 256
#define BT (BB * TT)

// ---------------- scratch ----------------
__device__ float g_mf[BT * DD];
__device__ float g_a0[BT * DD];
__device__ float g_zc[BT * DD];
__device__ float g_va[BT * DD];
__device__ unsigned short g_qhh[BT * DD];
__device__ unsigned short g_qhl[BT * DD];
__device__ unsigned short g_khh[BT * DD];
__device__ unsigned short g_khl[BT * DD];
// prepacked weights (bf16 hi/lo planes)
__device__ unsigned short g_woh[DD * DD];
__device__ unsigned short g_wol[DD * DD];
__device__ unsigned short g_wqh[DD * DD];
__device__ unsigned short g_wql[DD * DD];

// ================= helpers =================
typedef unsigned long long ull;
__device__ __forceinline__ uint32_t smem_u32(const void* p) {
    uint32_t a;
    asm("{ .reg .u64 t; cvta.to.shared.u64 t, %1; cvt.u32.u64 %0, t; }" : "=r"(a) : "l"(p));
    return a;
}
__device__ __forceinline__ void ldsm4(uint32_t& r0, uint32_t& r1, uint32_t& r2, uint32_t& r3,
                                      uint32_t addr) {
    asm volatile("ldmatrix.sync.aligned.m8n8.x4.shared.b16 {%0,%1,%2,%3}, [%4];"
                 : "=r"(r0), "=r"(r1), "=r"(r2), "=r"(r3) : "r"(addr));
}
__device__ __forceinline__ void ldsm4t(uint32_t& r0, uint32_t& r1, uint32_t& r2, uint32_t& r3,
                                       uint32_t addr) {
    asm volatile("ldmatrix.sync.aligned.m8n8.x4.trans.shared.b16 {%0,%1,%2,%3}, [%4];"
                 : "=r"(r0), "=r"(r1), "=r"(r2), "=r"(r3) : "r"(addr));
}
__device__ __forceinline__ void mma16816(float* c, uint32_t a0, uint32_t a1, uint32_t a2,
                                         uint32_t a3, uint32_t b0, uint32_t b1) {
    asm volatile(
        "mma.sync.aligned.m16n8k16.row.col.f32.bf16.bf16.f32 "
        "{%0,%1,%2,%3}, {%4,%5,%6,%7}, {%8,%9}, {%0,%1,%2,%3};"
        : "+f"(c[0]), "+f"(c[1]), "+f"(c[2]), "+f"(c[3])
        : "r"(a0), "r"(a1), "r"(a2), "r"(a3), "r"(b0), "r"(b1));
}
__device__ __forceinline__ void bsplit2(float x0, float x1, uint32_t& h, uint32_t& l) {
    uint16_t h0, h1, l0, l1;
    asm("cvt.rn.bf16.f32 %0, %1;" : "=h"(h0) : "f"(x0));
    asm("cvt.rn.bf16.f32 %0, %1;" : "=h"(h1) : "f"(x1));
    float f0 = __uint_as_float((uint32_t)h0 << 16);
    float f1 = __uint_as_float((uint32_t)h1 << 16);
    asm("cvt.rn.bf16.f32 %0, %1;" : "=h"(l0) : "f"(x0 - f0));
    asm("cvt.rn.bf16.f32 %0, %1;" : "=h"(l1) : "f"(x1 - f1));
    h = (uint32_t)h0 | ((uint32_t)h1 << 16);
    l = (uint32_t)l0 | ((uint32_t)l1 << 16);
}
__device__ __forceinline__ uint32_t sw_off(int row, int d) {
    return (uint32_t)(row * 256 + ((((d >> 3) ^ (row & 7)) & 15) << 4) + (d & 7) * 2);
}
__device__ __forceinline__ float sinpoly(float x) {
    float x2 = x * x;
    float pp = fmaf(x2, 2.7557319e-06f, -1.9841270e-04f);
    pp = fmaf(x2, pp, 8.3333333e-03f);
    pp = fmaf(x2, pp, -1.6666667e-01f);
    return fmaf(x * x2, pp, x);
}
__device__ __forceinline__ ull dup2(float x) {
    ull r; asm("mov.b64 %0, {%1, %1};" : "=l"(r) : "f"(x)); return r;
}
__device__ __forceinline__ ull pack2(float x, float y) {
    ull r; asm("mov.b64 %0, {%1, %2};" : "=l"(r) : "f"(x), "f"(y)); return r;
}
__device__ __forceinline__ void fma2(ull& d, ull a, ull b) {
    asm("fma.rn.f32x2 %0, %1, %2, %0;" : "+l"(d) : "l"(a), "l"(b));
}
__device__ __forceinline__ float2 unpk(ull v) {
    float2 r; asm("mov.b64 {%0, %1}, %2;" : "=f"(r.x), "=f"(r.y) : "l"(v)); return r;
}

__device__ __forceinline__ void cvt_store8o(char* smcp, uint32_t hoff, uint32_t loff,
                                            int row, int col, float4 a, float4 b) {
    uint32_t hw[4], lw[4];
    bsplit2(a.x, a.y, hw[0], lw[0]);
    bsplit2(a.z, a.w, hw[1], lw[1]);
    bsplit2(b.x, b.y, hw[2], lw[2]);
    bsplit2(b.z, b.w, hw[3], lw[3]);
    uint32_t off = sw_off(row, col);
    *(uint4*)(smcp + hoff + off) = make_uint4(hw[0], hw[1], hw[2], hw[3]);
    *(uint4*)(smcp + loff + off) = make_uint4(lw[0], lw[1], lw[2], lw[3]);
}

// ---------------- one-time W prepack ----------------
__global__ __launch_bounds__(256) void prep_w(const float* __restrict__ Wo,
                                              const float* __restrict__ Wq,
                                              unsigned short* __restrict__ Woh,
                                              unsigned short* __restrict__ Wol,
                                              unsigned short* __restrict__ Wqh,
                                              unsigned short* __restrict__ Wql) {
    int i = blockIdx.x * 256 + threadIdx.x;  // 8192 threads, 2 elems each
    float2 a = *(const float2*)(Wo + 2 * i);
    uint32_t h, l;
    bsplit2(a.x, a.y, h, l);
    *(uint32_t*)(Woh + 2 * i) = h;
    *(uint32_t*)(Wol + 2 * i) = l;
    float2 b = *(const float2*)(Wq + 2 * i);
    bsplit2(b.x, b.y, h, l);
    *(uint32_t*)(Wqh + 2 * i) = h;
    *(uint32_t*)(Wql + 2 * i) = l;
}

// attn smem: Qhi 16K | Qlo 16K | K double-buffered (hi 16K + lo 16K) x2 = 96KB
#define QH_OFF 0
#define QL_OFF 16384
#define KBASE_OFF 32768
#define ATTN_SMEM 98304

// ---------------- causal sin-attention: prepacked bf16, M=64, 2 CTAs/SM ----------------
__global__ __launch_bounds__(128, 2) void attn_kernel(const unsigned short* __restrict__ Qhh,
                                                      const unsigned short* __restrict__ Qhl,
                                                      const unsigned short* __restrict__ Khh,
                                                      const unsigned short* __restrict__ Khl,
                                                      float* __restrict__ O) {
    extern __shared__ char smc[];
    const uint32_t sbase = smem_u32(smc);
    const int tid = threadIdx.x;
    const int lane = tid & 31, w = tid >> 5;
    const int P = blockIdx.x, split = blockIdx.y;
    const int g = lane >> 3, r = lane & 7;
    const int krow = tid >> 1, kc0 = (tid & 1) * 64;
    const int lo = (130 * split) / 9, hi = (130 * (split + 1)) / 9;

    int c = 0;
    for (int sp = 0; sp < 4; sp++) {
        const int b = sp >> 1;
        const int R = (sp & 1) ? (63 - P) : P;
        const int n = R + 1;
        int s_lo = lo - c; if (s_lo < 0) s_lo = 0;
        int s_hi = hi - c; if (s_hi > n) s_hi = n;
        c += n;
        if (s_lo >= s_hi) continue;

        const unsigned short* Qhb = Qhh + (long long)b * TT * DD;
        const unsigned short* Qlb = Qhl + (long long)b * TT * DD;
        const unsigned short* Khb = Khh + (long long)b * TT * DD;
        const unsigned short* Klb = Khl + (long long)b * TT * DD;

        __syncthreads();
        for (int t = tid; t < 1024; t += 128) {
            int row = t >> 4, d0 = (t & 15) * 8;
            long long src = ((long long)R * 64 + row) * DD + d0;
            uint32_t off = sw_off(row, d0);
            *(uint4*)(smc + QH_OFF + off) = *(const uint4*)(Qhb + src);
            *(uint4*)(smc + QL_OFF + off) = *(const uint4*)(Qlb + src);
        }
        {
            long long src = ((long long)s_lo * 64 + krow) * DD + kc0;
#pragma unroll
            for (int q = 0; q < 8; q++) {
                uint32_t off = sw_off(krow, kc0 + 8 * q);
                *(uint4*)(smc + KBASE_OFF + off) = *(const uint4*)(Khb + src + 8 * q);
                *(uint4*)(smc + KBASE_OFF + 16384 + off) = *(const uint4*)(Klb + src + 8 * q);
            }
        }
        float Oc[16][4];
#pragma unroll
        for (int nf = 0; nf < 16; nf++)
#pragma unroll
            for (int e = 0; e < 4; e++) Oc[nf][e] = 0.f;
        __syncthreads();

        uint32_t qah[8][4], qal[8][4];
#pragma unroll
        for (int kc = 0; kc < 8; kc++) {
            uint32_t aoff = sw_off(w * 16 + ((g & 1) ? 8 : 0) + r, kc * 16 + ((g >> 1) ? 8 : 0));
            ldsm4(qah[kc][0], qah[kc][1], qah[kc][2], qah[kc][3], sbase + QH_OFF + aoff);
            ldsm4(qal[kc][0], qal[kc][1], qal[kc][2], qal[kc][3], sbase + QL_OFF + aoff);
        }

        for (int sb = s_lo; sb < s_hi; sb++) {
            const int cur = (sb - s_lo) & 1;
            const uint32_t KH = KBASE_OFF + (uint32_t)cur * 32768;
            const uint32_t KL = KH + 16384;
            const bool pre = (sb + 1 < s_hi);
            const uint32_t NH = KBASE_OFF + (uint32_t)(1 - cur) * 32768;
            long long psrc = ((long long)(sb + 1) * 64 + krow) * DD + kc0;

            float C[8][4];
#pragma unroll
            for (int nf = 0; nf < 8; nf++)
#pragma unroll
                for (int e = 0; e < 4; e++) C[nf][e] = 0.f;
#pragma unroll
            for (int kc = 0; kc < 8; kc++) {
                int d0 = kc * 16;
                uint32_t bh[4][4], bl[4][4];
#pragma unroll
                for (int nfp = 0; nfp < 4; nfp++) {
                    uint32_t boff = sw_off(nfp * 16 + ((g >> 1) ? 8 : 0) + r,
                                           d0 + ((g & 1) ? 8 : 0));
                    ldsm4(bh[nfp][0], bh[nfp][1], bh[nfp][2], bh[nfp][3], sbase + KH + boff);
                    ldsm4(bl[nfp][0], bl[nfp][1], bl[nfp][2], bl[nfp][3], sbase + KL + boff);
                }
#pragma unroll
                for (int nfp = 0; nfp < 4; nfp++) {
                    mma16816(C[2 * nfp],     qah[kc][0], qah[kc][1], qah[kc][2], qah[kc][3], bh[nfp][0], bh[nfp][1]);
                    mma16816(C[2 * nfp + 1], qah[kc][0], qah[kc][1], qah[kc][2], qah[kc][3], bh[nfp][2], bh[nfp][3]);
                }
#pragma unroll
                for (int nfp = 0; nfp < 4; nfp++) {
                    mma16816(C[2 * nfp],     qah[kc][0], qah[kc][1], qah[kc][2], qah[kc][3], bl[nfp][0], bl[nfp][1]);
                    mma16816(C[2 * nfp + 1], qah[kc][0], qah[kc][1], qah[kc][2], qah[kc][3], bl[nfp][2], bl[nfp][3]);
                }
#pragma unroll
                for (int nfp = 0; nfp < 4; nfp++) {
                    mma16816(C[2 * nfp],     qal[kc][0], qal[kc][1], qal[kc][2], qal[kc][3], bh[nfp][0], bh[nfp][1]);
                    mma16816(C[2 * nfp + 1], qal[kc][0], qal[kc][1], qal[kc][2], qal[kc][3], bh[nfp][2], bh[nfp][3]);
                }
            }
            if (pre) {
#pragma unroll
                for (int q = 0; q < 8; q++)
                    *(uint4*)(smc + NH + sw_off(krow, kc0 + 8 * q)) =
                        *(const uint4*)(Khb + psrc + 8 * q);
            }

            uint32_t a2h[4][4], a2l[4][4];
            const int ig = R * 64 + w * 16 + (lane >> 2);
#pragma unroll
            for (int nf = 0; nf < 8; nf++) {
                int jb = sb * 64 + nf * 8 + 2 * (lane & 3);
                float s0 = sinpoly(C[nf][0]); if (jb > ig) s0 = 0.f;
                float s1 = sinpoly(C[nf][1]); if (jb + 1 > ig) s1 = 0.f;
                float s2 = sinpoly(C[nf][2]); if (jb > ig + 8) s2 = 0.f;
                float s3 = sinpoly(C[nf][3]); if (jb + 1 > ig + 8) s3 = 0.f;
                int kc2 = nf >> 1, hk = (nf & 1) ? 2 : 0;
                bsplit2(s0, s1, a2h[kc2][hk], a2l[kc2][hk]);
                bsplit2(s2, s3, a2h[kc2][hk + 1], a2l[kc2][hk + 1]);
            }

#pragma unroll
            for (int kc2 = 0; kc2 < 4; kc2++) {
                int j0 = kc2 * 16;
#pragma unroll
                for (int hh = 0; hh < 2; hh++) {
                    uint32_t th[4][4], tl[4][4];
#pragma unroll
                    for (int q = 0; q < 4; q++) {
                        int nfp = hh * 4 + q;
                        uint32_t boff = sw_off(j0 + ((g & 1) ? 8 : 0) + r,
                                               nfp * 16 + ((g >> 1) ? 8 : 0));
                        ldsm4t(th[q][0], th[q][1], th[q][2], th[q][3], sbase + KH + boff);
                        ldsm4t(tl[q][0], tl[q][1], tl[q][2], tl[q][3], sbase + KL + boff);
                    }
#pragma unroll
                    for (int q = 0; q < 4; q++) {
                        int nfp = hh * 4 + q;
                        mma16816(Oc[2 * nfp],     a2h[kc2][0], a2h[kc2][1], a2h[kc2][2], a2h[kc2][3], th[q][0], th[q][1]);
                        mma16816(Oc[2 * nfp + 1], a2h[kc2][0], a2h[kc2][1], a2h[kc2][2], a2h[kc2][3], th[q][2], th[q][3]);
                    }
#pragma unroll
                    for (int q = 0; q < 4; q++) {
                        int nfp = hh * 4 + q;
                        mma16816(Oc[2 * nfp],     a2h[kc2][0], a2h[kc2][1], a2h[kc2][2], a2h[kc2][3], tl[q][0], tl[q][1]);
                        mma16816(Oc[2 * nfp + 1], a2h[kc2][0], a2h[kc2][1], a2h[kc2][2], a2h[kc2][3], tl[q][2], tl[q][3]);
                    }
#pragma unroll
                    for (int q = 0; q < 4; q++) {
                        int nfp = hh * 4 + q;
                        mma16816(Oc[2 * nfp],     a2l[kc2][0], a2l[kc2][1], a2l[kc2][2], a2l[kc2][3], th[q][0], th[q][1]);
                        mma16816(Oc[2 * nfp + 1], a2l[kc2][0], a2l[kc2][1], a2l[kc2][2], a2l[kc2][3], th[q][2], th[q][3]);
                    }
                }
            }
            if (pre) {
#pragma unroll
                for (int q = 0; q < 8; q++)
                    *(uint4*)(smc + NH + 16384 + sw_off(krow, kc0 + 8 * q)) =
                        *(const uint4*)(Klb + psrc + 8 * q);
            }
            __syncthreads();
        }

        {
            long long rbase = (long long)b * TT + (long long)R * 64 + w * 16 + (lane >> 2);
#pragma unroll
            for (int nf = 0; nf < 16; nf++) {
                int d = nf * 8 + 2 * (lane & 3);
                atomicAdd(O + rbase * DD + d,       Oc[nf][0]);
                atomicAdd(O + rbase * DD + d + 1,   Oc[nf][1]);
                atomicAdd(O + (rbase + 8) * DD + d,     Oc[nf][2]);
                atomicAdd(O + (rbase + 8) * DD + d + 1, Oc[nf][3]);
            }
        }
    }
}

// ---------------- depthwise causal conv (FFMA2, d-pairs) ----------------
__global__ __launch_bounds__(512) void conv_kernel(const float* __restrict__ z,
                                                   const float* __restrict__ w,
                                                   const float* __restrict__ bias,
                                                   float* __restrict__ mf) {
    int d0 = threadIdx.x * 2;
    int t = blockIdx.x * 8 + threadIdx.y;
    int b = blockIdx.y;
    float2 bv = *(const float2*)(bias + d0);
    ull acc = pack2(bv.x, bv.y);
    int kstart = (KK - 1) - t;
    if (kstart < 0) kstart = 0;
    const float* zp = z + ((long long)b * TT + t - (KK - 1)) * DD + d0;
    const float* wp = w + d0;
#pragma unroll 4
    for (int k = kstart; k < KK; k++)
        fma2(acc, *(const ull*)(zp + (long long)k * DD), *(const ull*)(wp + (long long)k * DD));
    float2 res = unpk(acc);
    *(float2*)(mf + ((long long)b * TT + t) * DD + d0) = res;
}

// ---------------- group reduce (dual_gemm_norm) ----------------
__device__ __forceinline__ void group_reduce8(float v[8], float* red, int grp, int wig, int lane) {
#pragma unroll
    for (int k = 0; k < 8; k++) {
        float x = v[k];
#pragma unroll
        for (int o = 16; o; o >>= 1) x += __shfl_xor_sync(0xffffffffu, x, o);
        if (lane == 0) red[grp * 32 + wig * 8 + k] = x;
    }
    __syncthreads();
#pragma unroll
    for (int k = 0; k < 8; k++)
        v[k] = red[grp * 32 + k] + red[grp * 32 + 8 + k] + red[grp * 32 + 16 + k] +
               red[grp * 32 + 24 + k];
    __syncthreads();
}

__device__ __forceinline__ void matvec8(const float* Ws, const float* xg, int d, float bias,
                                        float tot[8]) {
    ull acc0 = dup2(bias), acc1 = dup2(bias), acc2 = dup2(bias), acc3 = dup2(bias);
#pragma unroll 4
    for (int j = 0; j < 128; j++) {
        ull w2 = dup2(Ws[j * 128 + d]);
        ulonglong2 x01 = *(const ulonglong2*)(xg + j * 8);
        ulonglong2 x23 = *(const ulonglong2*)(xg + j * 8 + 4);
        fma2(acc0, x01.x, w2);
        fma2(acc1, x01.y, w2);
        fma2(acc2, x23.x, w2);
        fma2(acc3, x23.y, w2);
    }
    float2 a0 = unpk(acc0), a1 = unpk(acc1), a2 = unpk(acc2), a3 = unpk(acc3);
    tot[0] = a0.x; tot[1] = a0.y; tot[2] = a1.x; tot[3] = a1.y;
    tot[4] = a2.x; tot[5] = a2.y; tot[6] = a3.x; tot[7] = a3.y;
}

#define DUAL_SMEM ((16384 + 16384 + 4096 + 128) * 4)

__global__ __launch_bounds__(512) void dual_gemm_norm(const float* __restrict__ X,
                                                      const float* __restrict__ W1,
                                                      const float* __restrict__ b1,
                                                      const float* __restrict__ W2,
                                                      const float* __restrict__ b2,
                                                      unsigned short* __restrict__ Y1h,
                                                      unsigned short* __restrict__ Y1l,
                                                      unsigned short* __restrict__ Y2h,
                                                      unsigned short* __restrict__ Y2l) {
    extern __shared__ float sm[];
    float* W1s = sm;
    float* W2s = sm + 16384;
    float* xp  = sm + 32768;
    float* red = sm + 36864;
    int tid = threadIdx.x, grp = tid >> 7, d = tid & 127, wig = (tid >> 5) & 3, lane = tid & 31;
    for (int i = tid; i < 16384; i += 512) { W1s[i] = W1[i]; W2s[i] = W2[i]; }
    float b1v = b1[d], b2v = b2[d];
    __syncthreads();
    long long row0 = (long long)blockIdx.x * 64 + grp * 16;
    float* xg = xp + grp * 1024;
    for (int gg = 0; gg < 16; gg += 8) {
#pragma unroll
        for (int k = 0; k < 8; k++)
            xg[d * 8 + k] = X[(row0 + gg + k) * DD + d];
        __syncthreads();
        float tot[8], v[8];
        matvec8(W1s, xg, d, b1v, tot);
#pragma unroll
        for (int k = 0; k < 8; k++) v[k] = tot[k] * tot[k];
        group_reduce8(v, red, grp, wig, lane);
#pragma unroll
        for (int k = 0; k < 8; k++) {
            float y = __fdividef(tot[k], fmaxf(sqrtf(v[k]), 1e-8f));
            uint16_t h;
            asm("cvt.rn.bf16.f32 %0, %1;" : "=h"(h) : "f"(y));
            float fh = __uint_as_float((uint32_t)h << 16);
            uint16_t l;
            asm("cvt.rn.bf16.f32 %0, %1;" : "=h"(l) : "f"(y - fh));
            long long off = (row0 + gg + k) * DD + d;
            Y1h[off] = h; Y1l[off] = l;
        }
        matvec8(W2s, xg, d, b2v, tot);
#pragma unroll
        for (int k = 0; k < 8; k++) v[k] = tot[k] * tot[k];
        group_reduce8(v, red, grp, wig, lane);
#pragma unroll
        for (int k = 0; k < 8; k++) {
            float y = __fdividef(tot[k], fmaxf(sqrtf(v[k]), 1e-8f));
            uint16_t h;
            asm("cvt.rn.bf16.f32 %0, %1;" : "=h"(h) : "f"(y));
            float fh = __uint_as_float((uint32_t)h << 16);
            uint16_t l;
            asm("cvt.rn.bf16.f32 %0, %1;" : "=h"(l) : "f"(y - fh));
            long long off = (row0 + gg + k) * DD + d;
            Y2h[off] = h; Y2l[off] = l;
        }
        __syncthreads();
    }
}

// ================== MMA epilogue: full W resident, sync-free GEMMs ==================
// smem: A hi 16K | A lo 16K | W hi 32K | W lo 32K | red 512B = 96.5KB
#define E_AH 0
#define E_AL 16384
#define E_WH 32768
#define E_WL 65536
#define E_RED 98304
#define EPI3_SMEM 98816

__global__ __launch_bounds__(256, 2) void epilogue_mma(
    const float* __restrict__ A0,
    const unsigned short* __restrict__ Woh, const unsigned short* __restrict__ Wol,
    const float* __restrict__ bo,
    const unsigned short* __restrict__ Wqh, const unsigned short* __restrict__ Wql,
    const float* __restrict__ bq,
    const float* __restrict__ mf, const float* __restrict__ zin,
    const float* __restrict__ zbase, float* __restrict__ vacc,
    float* __restrict__ zc, unsigned short* __restrict__ qhh,
    unsigned short* __restrict__ qhl, float* __restrict__ out,
    float sw, float rc, int first, int has_next) {
    extern __shared__ char smc[];
    const uint32_t sbase = smem_u32(smc);
    float* red = (float*)(smc + E_RED);
    const int tid = threadIdx.x;
    const int lane = tid & 31, w = tid >> 5;
    const int wr = w & 3, whalf = w >> 2;
    const int ncol0 = whalf * 64;
    const int g = lane >> 3, r = lane & 7;
    const long long row0 = (long long)blockIdx.x * 64;
    const int rowL = wr * 16 + (lane >> 2);
    const long long gA = row0 + rowL;
    const long long gB = gA + 8;

    // stage A (64x128, fp32 -> bf16 hi/lo) and FULL Wo (128x128 bf16 planes, pure copy)
    for (int t = tid; t < 1024; t += 256) {
        int row = t >> 4, d0 = (t & 15) * 8;
        const float* src = A0 + (row0 + row) * DD + d0;
        cvt_store8o(smc, E_AH, E_AL, row, d0, *(const float4*)src, *(const float4*)(src + 4));
    }
    for (int t = tid; t < 2048; t += 256) {
        int row = t >> 4, d0 = (t & 15) * 8;
        uint32_t off = sw_off(row, d0);
        *(uint4*)(smc + E_WH + off) = *(const uint4*)(Woh + row * DD + d0);
        *(uint4*)(smc + E_WL + off) = *(const uint4*)(Wol + row * DD + d0);
    }
    __syncthreads();

    float C[8][4];
#pragma unroll
    for (int nf = 0; nf < 8; nf++)
#pragma unroll
        for (int e = 0; e < 4; e++) C[nf][e] = 0.f;

    // ---- GEMM1: C = A @ Wo (sync-free, W resident) ----
#pragma unroll
    for (int kc = 0; kc < 8; kc++) {
        uint32_t aoff = sw_off(wr * 16 + ((g & 1) ? 8 : 0) + r, kc * 16 + ((g >> 1) ? 8 : 0));
        uint32_t ah0, ah1, ah2, ah3, al0, al1, al2, al3;
        ldsm4(ah0, ah1, ah2, ah3, sbase + E_AH + aoff);
        ldsm4(al0, al1, al2, al3, sbase + E_AL + aoff);
        uint32_t th[4][4], tl[4][4];
#pragma unroll
        for (int nfp = 0; nfp < 4; nfp++) {
            uint32_t boff = sw_off(kc * 16 + ((g & 1) ? 8 : 0) + r,
                                   ncol0 + nfp * 16 + ((g >> 1) ? 8 : 0));
            ldsm4t(th[nfp][0], th[nfp][1], th[nfp][2], th[nfp][3], sbase + E_WH + boff);
            ldsm4t(tl[nfp][0], tl[nfp][1], tl[nfp][2], tl[nfp][3], sbase + E_WL + boff);
        }
#pragma unroll
        for (int nfp = 0; nfp < 4; nfp++) {
            mma16816(C[2 * nfp],     ah0, ah1, ah2, ah3, th[nfp][0], th[nfp][1]);
            mma16816(C[2 * nfp + 1], ah0, ah1, ah2, ah3, th[nfp][2], th[nfp][3]);
        }
#pragma unroll
        for (int nfp = 0; nfp < 4; nfp++) {
            mma16816(C[2 * nfp],     ah0, ah1, ah2, ah3, tl[nfp][0], tl[nfp][1]);
            mma16816(C[2 * nfp + 1], ah0, ah1, ah2, ah3, tl[nfp][2], tl[nfp][3]);
        }
#pragma unroll
        for (int nfp = 0; nfp < 4; nfp++) {
            mma16816(C[2 * nfp],     al0, al1, al2, al3, th[nfp][0], th[nfp][1]);
            mma16816(C[2 * nfp + 1], al0, al1, al2, al3, th[nfp][2], th[nfp][3]);
        }
    }

    // ---- bias + mf, tangent dot ----
    float dotA = 0.f, dotB = 0.f;
#pragma unroll
    for (int nf = 0; nf < 8; nf++) {
        int col = ncol0 + nf * 8 + 2 * (lane & 3);
        float2 bov = *(const float2*)(bo + col);
        float2 mA = *(const float2*)(mf + gA * DD + col);
        float2 mB = *(const float2*)(mf + gB * DD + col);
        C[nf][0] += bov.x + mA.x; C[nf][1] += bov.y + mA.y;
        C[nf][2] += bov.x + mB.x; C[nf][3] += bov.y + mB.y;
        float2 zA = *(const float2*)(zin + gA * DD + col);
        float2 zB = *(const float2*)(zin + gB * DD + col);
        dotA += C[nf][0] * zA.x + C[nf][1] * zA.y;
        dotB += C[nf][2] * zB.x + C[nf][3] * zB.y;
    }
    dotA += __shfl_xor_sync(0xffffffffu, dotA, 1);
    dotA += __shfl_xor_sync(0xffffffffu, dotA, 2);
    dotB += __shfl_xor_sync(0xffffffffu, dotB, 1);
    dotB += __shfl_xor_sync(0xffffffffu, dotB, 2);
    if ((lane & 3) == 0) {
        red[whalf * 64 + rowL] = dotA;
        red[whalf * 64 + rowL + 8] = dotB;
    }
    __syncthreads();
    dotA = red[rowL] + red[64 + rowL];
    dotB = red[rowL + 8] + red[64 + rowL + 8];
    __syncthreads();

    // ---- proj, vacc update, zn sumsq; load Wq into W buffer (all warps past GEMM1) ----
    for (int t = tid; t < 2048; t += 256) {
        int row = t >> 4, d0 = (t & 15) * 8;
        uint32_t off = sw_off(row, d0);
        *(uint4*)(smc + E_WH + off) = *(const uint4*)(Wqh + row * DD + d0);
        *(uint4*)(smc + E_WL + off) = *(const uint4*)(Wql + row * DD + d0);
    }
    float ssA = 0.f, ssB = 0.f;
#pragma unroll
    for (int nf = 0; nf < 8; nf++) {
        int col = ncol0 + nf * 8 + 2 * (lane & 3);
        float2 zA = *(const float2*)(zin + gA * DD + col);
        float2 zB = *(const float2*)(zin + gB * DD + col);
        C[nf][0] -= dotA * zA.x; C[nf][1] -= dotA * zA.y;
        C[nf][2] -= dotB * zB.x; C[nf][3] -= dotB * zB.y;
        float2* vA = (float2*)(vacc + gA * DD + col);
        float2* vB = (float2*)(vacc + gB * DD + col);
        float2 vpA = first ? make_float2(0.f, 0.f) : *vA;
        float2 vpB = first ? make_float2(0.f, 0.f) : *vB;
        float2 vnA = make_float2(vpA.x + sw * C[nf][0], vpA.y + sw * C[nf][1]);
        float2 vnB = make_float2(vpB.x + sw * C[nf][2], vpB.y + sw * C[nf][3]);
        *vA = vnA; *vB = vnB;
        float2 zbA = *(const float2*)(zbase + gA * DD + col);
        float2 zbB = *(const float2*)(zbase + gB * DD + col);
        if (has_next) {
            float a0v = zbA.x + rc * C[nf][0], a1v = zbA.y + rc * C[nf][1];
            float b0v = zbB.x + rc * C[nf][2], b1v = zbB.y + rc * C[nf][3];
            ssA += a0v * a0v + a1v * a1v;
            ssB += b0v * b0v + b1v * b1v;
            C[nf][0] = a0v; C[nf][1] = a1v; C[nf][2] = b0v; C[nf][3] = b1v;
        } else {
            float a0v = zbA.x + vnA.x, a1v = zbA.y + vnA.y;
            float b0v = zbB.x + vnB.x, b1v = zbB.y + vnB.y;
            ssA += a0v * a0v + a1v * a1v;
            ssB += b0v * b0v + b1v * b1v;
            C[nf][0] = a0v; C[nf][1] = a1v; C[nf][2] = b0v; C[nf][3] = b1v;
        }
    }
    ssA += __shfl_xor_sync(0xffffffffu, ssA, 1);
    ssA += __shfl_xor_sync(0xffffffffu, ssA, 2);
    ssB += __shfl_xor_sync(0xffffffffu, ssB, 1);
    ssB += __shfl_xor_sync(0xffffffffu, ssB, 2);
    if ((lane & 3) == 0) {
        red[whalf * 64 + rowL] = ssA;
        red[whalf * 64 + rowL + 8] = ssB;
    }
    __syncthreads();
    ssA = red[rowL] + red[64 + rowL];
    ssB = red[rowL + 8] + red[64 + rowL + 8];
    __syncthreads();
    float invA = __fdividef(1.f, fmaxf(sqrtf(ssA), 1e-8f));
    float invB = __fdividef(1.f, fmaxf(sqrtf(ssB), 1e-8f));

    if (!has_next) {
#pragma unroll
        for (int nf = 0; nf < 8; nf++) {
            int col = ncol0 + nf * 8 + 2 * (lane & 3);
            *(float2*)(out + gA * DD + col) = make_float2(C[nf][0] * invA, C[nf][1] * invA);
            *(float2*)(out + gB * DD + col) = make_float2(C[nf][2] * invB, C[nf][3] * invB);
        }
        return;
    }

    // ---- z0 = norm(zbase + rc*proj): store zc + restage into A tile ----
#pragma unroll
    for (int nf = 0; nf < 8; nf++) {
        int col = ncol0 + nf * 8 + 2 * (lane & 3);
        float a0v = C[nf][0] * invA, a1v = C[nf][1] * invA;
        float b0v = C[nf][2] * invB, b1v = C[nf][3] * invB;
        *(float2*)(zc + gA * DD + col) = make_float2(a0v, a1v);
        *(float2*)(zc + gB * DD + col) = make_float2(b0v, b1v);
        uint32_t h, l;
        bsplit2(a0v, a1v, h, l);
        *(uint32_t*)(smc + E_AH + sw_off(rowL, col)) = h;
        *(uint32_t*)(smc + E_AL + sw_off(rowL, col)) = l;
        bsplit2(b0v, b1v, h, l);
        *(uint32_t*)(smc + E_AH + sw_off(rowL + 8, col)) = h;
        *(uint32_t*)(smc + E_AL + sw_off(rowL + 8, col)) = l;
    }
    __syncthreads();

    // ---- GEMM2: C = z0 @ Wq (sync-free, W resident) ----
#pragma unroll
    for (int nf = 0; nf < 8; nf++)
#pragma unroll
        for (int e = 0; e < 4; e++) C[nf][e] = 0.f;
#pragma unroll
    for (int kc = 0; kc < 8; kc++) {
        uint32_t aoff = sw_off(wr * 16 + ((g & 1) ? 8 : 0) + r, kc * 16 + ((g >> 1) ? 8 : 0));
        uint32_t ah0, ah1, ah2, ah3, al0, al1, al2, al3;
        ldsm4(ah0, ah1, ah2, ah3, sbase + E_AH + aoff);
        ldsm4(al0, al1, al2, al3, sbase + E_AL + aoff);
        uint32_t th[4][4], tl[4][4];
#pragma unroll
        for (int nfp = 0; nfp < 4; nfp++) {
            uint32_t boff = sw_off(kc * 16 + ((g & 1) ? 8 : 0) + r,
                                   ncol0 + nfp * 16 + ((g >> 1) ? 8 : 0));
            ldsm4t(th[nfp][0], th[nfp][1], th[nfp][2], th[nfp][3], sbase + E_WH + boff);
            ldsm4t(tl[nfp][0], tl[nfp][1], tl[nfp][2], tl[nfp][3], sbase + E_WL + boff);
        }
#pragma unroll
        for (int nfp = 0; nfp < 4; nfp++) {
            mma16816(C[2 * nfp],     ah0, ah1, ah2, ah3, th[nfp][0], th[nfp][1]);
            mma16816(C[2 * nfp + 1], ah0, ah1, ah2, ah3, th[nfp][2], th[nfp][3]);
        }
#pragma unroll
        for (int nfp = 0; nfp < 4; nfp++) {
            mma16816(C[2 * nfp],     ah0, ah1, ah2, ah3, tl[nfp][0], tl[nfp][1]);
            mma16816(C[2 * nfp + 1], ah0, ah1, ah2, ah3, tl[nfp][2], tl[nfp][3]);
        }
#pragma unroll
        for (int nfp = 0; nfp < 4; nfp++) {
            mma16816(C[2 * nfp],     al0, al1, al2, al3, th[nfp][0], th[nfp][1]);
            mma16816(C[2 * nfp + 1], al0, al1, al2, al3, th[nfp][2], th[nfp][3]);
        }
    }

    // ---- qh = norm(C + bq) -> prepacked bf16 hi/lo ----
    float qsA = 0.f, qsB = 0.f;
#pragma unroll
    for (int nf = 0; nf < 8; nf++) {
        int col = ncol0 + nf * 8 + 2 * (lane & 3);
        float2 bqv = *(const float2*)(bq + col);
        C[nf][0] += bqv.x; C[nf][1] += bqv.y;
        C[nf][2] += bqv.x; C[nf][3] += bqv.y;
        qsA += C[nf][0] * C[nf][0] + C[nf][1] * C[nf][1];
        qsB += C[nf][2] * C[nf][2] + C[nf][3] * C[nf][3];
    }
    qsA += __shfl_xor_sync(0xffffffffu, qsA, 1);
    qsA += __shfl_xor_sync(0xffffffffu, qsA, 2);
    qsB += __shfl_xor_sync(0xffffffffu, qsB, 1);
    qsB += __shfl_xor_sync(0xffffffffu, qsB, 2);
    if ((lane & 3) == 0) {
        red[whalf * 64 + rowL] = qsA;
        red[whalf * 64 + rowL + 8] = qsB;
    }
    __syncthreads();
    qsA = red[rowL] + red[64 + rowL];
    qsB = red[rowL + 8] + red[64 + rowL + 8];
    float qiA = __fdividef(1.f, fmaxf(sqrtf(qsA), 1e-8f));
    float qiB = __fdividef(1.f, fmaxf(sqrtf(qsB), 1e-8f));
#pragma unroll
    for (int nf = 0; nf < 8; nf++) {
        int col = ncol0 + nf * 8 + 2 * (lane & 3);
        uint32_t h, l;
        bsplit2(C[nf][0] * qiA, C[nf][1] * qiA, h, l);
        *(uint32_t*)(qhh + gA * DD + col) = h;
        *(uint32_t*)(qhl + gA * DD + col) = l;
        bsplit2(C[nf][2] * qiB, C[nf][3] * qiB, h, l);
        *(uint32_t*)(qhh + gB * DD + col) = h;
        *(uint32_t*)(qhl + gB * DD + col) = l;
    }
}

// ---------------- launch ----------------
extern "C" void kernel_launch(void* const* d_in, const int* in_sizes, int n_in,
                              void* d_out, int out_size) {
    const float* z  = (const float*)d_in[0];
    const float* ck = (const float*)d_in[1];
    const float* cb = (const float*)d_in[2];
    const float* Wq = (const float*)d_in[3];
    const float* bq = (const float*)d_in[4];
    const float* Wk = (const float*)d_in[5];
    const float* bk = (const float*)d_in[6];
    const float* Wo = (const float*)d_in[7];
    const float* bo = (const float*)d_in[8];
    float* out = (float*)d_out;

    float *mf, *a0, *zc, *va;
    unsigned short *qhh, *qhl, *khh, *khl, *woh, *wol, *wqh, *wql;
    cudaGetSymbolAddress((void**)&mf, g_mf);
    cudaGetSymbolAddress((void**)&a0, g_a0);
    cudaGetSymbolAddress((void**)&zc, g_zc);
    cudaGetSymbolAddress((void**)&va, g_va);
    cudaGetSymbolAddress((void**)&qhh, g_qhh);
    cudaGetSymbolAddress((void**)&qhl, g_qhl);
    cudaGetSymbolAddress((void**)&khh, g_khh);
    cudaGetSymbolAddress((void**)&khl, g_khl);
    cudaGetSymbolAddress((void**)&woh, g_woh);
    cudaGetSymbolAddress((void**)&wol, g_wol);
    cudaGetSymbolAddress((void**)&wqh, g_wqh);
    cudaGetSymbolAddress((void**)&wql, g_wql);

    cudaFuncSetAttribute(dual_gemm_norm, cudaFuncAttributeMaxDynamicSharedMemorySize, DUAL_SMEM);
    cudaFuncSetAttribute(epilogue_mma, cudaFuncAttributeMaxDynamicSharedMemorySize, EPI3_SMEM);
    cudaFuncSetAttribute(attn_kernel, cudaFuncAttributeMaxDynamicSharedMemorySize, ATTN_SMEM);

    prep_w<<<32, 256>>>(Wo, Wq, woh, wol, wqh, wql);
    conv_kernel<<<dim3(TT / 8, BB), dim3(64, 8)>>>(z, ck, cb, mf);
    dual_gemm_norm<<<BT / 64, 512, DUAL_SMEM>>>(z, Wk, bk, Wq, bq, khh, khl, qhh, qhl);

    const float sws[4] = {1.f / 6.f, 2.f / 6.f, 2.f / 6.f, 1.f / 6.f};
    const float rcs[4] = {0.5f, 0.5f, 1.0f, 0.f};
    const float* zcur = z;
    for (int s = 0; s < 4; s++) {
        cudaMemsetAsync(a0, 0, (size_t)BT * DD * sizeof(float));
        attn_kernel<<<dim3(32, 9), 128, ATTN_SMEM>>>(qhh, qhl, khh, khl, a0);
        epilogue_mma<<<BT / 64, 256, EPI3_SMEM>>>(a0, woh, wol, bo, wqh, wql, bq,
                                                  mf, zcur, z, va, zc, qhh, qhl, out,
                                                  sws[s], rcs[s], s == 0 ? 1 : 0,
                                                  s < 3 ? 1 : 0);
        zcur = zc;
    }
}